// round 5
// baseline (speedup 1.0000x reference)
#include <cuda_runtime.h>

// ---------------------------------------------------------------------------
// Problem constants
// ---------------------------------------------------------------------------
#define BB     16
#define CIN    1024
#define HW     1024      // 32*32
#define CK     256
#define CV     512
#define MTOT   768       // stacked key(256) + value(512) output channels
#define KTOT   9216      // CIN * 9

// ---------------------------------------------------------------------------
// Scratch (device globals; no allocation allowed)
// ---------------------------------------------------------------------------
__device__ float g_wT_t[KTOT * MTOT];          // temp-branch weights, [k][co]
__device__ float g_wT_s[KTOT * MTOT];          // search-branch weights
__device__ float g_mk[BB * CK * HW];           // m_key   [b][c][pix]
__device__ float g_qk[BB * CK * HW];           // q_key
__device__ float g_mv[BB * CV * HW];           // m_value
__device__ float g_S [BB * HW * HW];           // scores -> exp(scores)
__device__ float g_rsum[BB * HW];              // 1 / column sum

// ---------------------------------------------------------------------------
// Weight reshuffle: wT[(r*1024+ci)*768 + co] = w[co][ci][r]
// ---------------------------------------------------------------------------
__global__ void transpose_w(const float* __restrict__ wk,
                            const float* __restrict__ wv,
                            int which)
{
    int idx = blockIdx.x * blockDim.x + threadIdx.x;
    if (idx >= KTOT * MTOT) return;
    int k  = idx / MTOT;
    int co = idx - k * MTOT;
    int ci = k & 1023;
    int r  = k >> 10;
    float v = (co < CK) ? wk[co * KTOT + ci * 9 + r]
                        : wv[(co - CK) * KTOT + ci * 9 + r];
    (which ? g_wT_s : g_wT_t)[idx] = v;
}

// ---------------------------------------------------------------------------
// Implicit-GEMM conv: C[768, 16384] = wT^T-style GEMM with on-the-fly im2col.
// BM=BN=128, BK=32, 256 threads, 8x8 micro-tile (4+64 split quads).
// which==0: temp   -> key=g_mk, val=g_mv
// which==1: search -> key=g_qk, val=d_out (+512 chan offset)
// ---------------------------------------------------------------------------
__global__ __launch_bounds__(256, 2)
void conv_gemm(const float* __restrict__ src,
               const float* __restrict__ bias_k,
               const float* __restrict__ bias_v,
               float* __restrict__ out,     // only used for which==1 value path
               int which)
{
    __shared__ float As[32][128];
    __shared__ float Bs[32][128];

    const float* __restrict__ wT = which ? g_wT_s : g_wT_t;

    int tid = threadIdx.x;
    int tx  = tid & 15;          // n direction (16)
    int ty  = tid >> 4;          // m direction (16)
    int n0  = blockIdx.x * 128;  // pixel index over B*HW
    int co0 = blockIdx.y * 128;  // output channel
    int b   = n0 >> 10;
    int pix0 = n0 & 1023;
    const float* srcb = src + (size_t)b * (CIN * HW);

    int lrow = tid >> 5;          // 0..7
    int lcol = (tid & 31) * 4;    // 0..124

    // hoist pixel coords for B loads (independent of kt)
    int py[4], px[4];
#pragma unroll
    for (int t = 0; t < 4; ++t) {
        int pix = pix0 + lcol + t;
        py[t] = pix >> 5;
        px[t] = pix & 31;
    }

    float acc[8][8];
#pragma unroll
    for (int i = 0; i < 8; ++i)
#pragma unroll
        for (int j = 0; j < 8; ++j) acc[i][j] = 0.f;

    for (int kt = 0; kt < 288; ++kt) {
        int r   = kt >> 5;            // filter tap 0..8
        int ci0 = (kt & 31) << 5;     // input-channel base
        int dy  = r / 3 - 1;
        int dx  = r % 3 - 1;

        // --- load A tile (coalesced float4) ---
        const float* wrow = wT + (size_t)(kt * 32) * MTOT + co0;
#pragma unroll
        for (int p = 0; p < 4; ++p) {
            int kk = p * 8 + lrow;
            float4 v = *reinterpret_cast<const float4*>(&wrow[(size_t)kk * MTOT + lcol]);
            *reinterpret_cast<float4*>(&As[kk][lcol]) = v;
        }
        // --- load B tile (im2col gather) ---
#pragma unroll
        for (int p = 0; p < 4; ++p) {
            int kk = p * 8 + lrow;
            const float* srcc = srcb + (size_t)(ci0 + kk) * HW;
            float4 v;
            float tmp[4];
#pragma unroll
            for (int t = 0; t < 4; ++t) {
                int iy = py[t] + dy;
                int ix = px[t] + dx;
                float vv = 0.f;
                if ((unsigned)iy < 32u && (unsigned)ix < 32u)
                    vv = srcc[iy * 32 + ix];
                tmp[t] = vv;
            }
            v.x = tmp[0]; v.y = tmp[1]; v.z = tmp[2]; v.w = tmp[3];
            *reinterpret_cast<float4*>(&Bs[kk][lcol]) = v;
        }
        __syncthreads();

#pragma unroll 8
        for (int kk = 0; kk < 32; ++kk) {
            float4 a0 = *reinterpret_cast<const float4*>(&As[kk][ty * 4]);
            float4 a1 = *reinterpret_cast<const float4*>(&As[kk][ty * 4 + 64]);
            float4 b0 = *reinterpret_cast<const float4*>(&Bs[kk][tx * 4]);
            float4 b1 = *reinterpret_cast<const float4*>(&Bs[kk][tx * 4 + 64]);
            float a[8] = {a0.x, a0.y, a0.z, a0.w, a1.x, a1.y, a1.z, a1.w};
            float bv[8] = {b0.x, b0.y, b0.z, b0.w, b1.x, b1.y, b1.z, b1.w};
#pragma unroll
            for (int i = 0; i < 8; ++i)
#pragma unroll
                for (int j = 0; j < 8; ++j)
                    acc[i][j] += a[i] * bv[j];
        }
        __syncthreads();
    }

    // --- epilogue ---
    bool is_key = (co0 < CK);   // 128-row tiles never straddle the 256 boundary
#pragma unroll
    for (int i = 0; i < 8; ++i) {
        int row = ty * 4 + (i & 3) + ((i >> 2) << 6);
        int co  = co0 + row;
        float bias;
        float* dst;
        if (is_key) {
            bias = bias_k[co];
            dst  = (which ? g_qk : g_mk) + (size_t)b * (CK * HW) + (size_t)co * HW + pix0;
        } else {
            int cv = co - CK;
            bias = bias_v[cv];
            if (which) // q_value straight into output (channels 512..1023)
                dst = out + (size_t)b * (2 * CV * HW) + (size_t)(CV + cv) * HW + pix0;
            else
                dst = g_mv + (size_t)b * (CV * HW) + (size_t)cv * HW + pix0;
        }
#pragma unroll
        for (int jq = 0; jq < 2; ++jq) {
            int col = tx * 4 + jq * 64;
            float4 o;
            o.x = acc[i][jq * 4 + 0] + bias;
            o.y = acc[i][jq * 4 + 1] + bias;
            o.z = acc[i][jq * 4 + 2] + bias;
            o.w = acc[i][jq * 4 + 3] + bias;
            *reinterpret_cast<float4*>(&dst[col]) = o;
        }
    }
}

// ---------------------------------------------------------------------------
// Scores: S[b][m][q] = (1/16) * sum_c mk[b][c][m] * qk[b][c][q]
// ---------------------------------------------------------------------------
__global__ __launch_bounds__(256, 2)
void scores_gemm()
{
    __shared__ float As[32][128];
    __shared__ float Bs[32][128];
    int tid = threadIdx.x, tx = tid & 15, ty = tid >> 4;
    int b  = blockIdx.z;
    int m0 = blockIdx.y * 128;
    int q0 = blockIdx.x * 128;
    const float* mk = g_mk + (size_t)b * (CK * HW);
    const float* qk = g_qk + (size_t)b * (CK * HW);

    int lrow = tid >> 5;
    int lcol = (tid & 31) * 4;

    float acc[8][8];
#pragma unroll
    for (int i = 0; i < 8; ++i)
#pragma unroll
        for (int j = 0; j < 8; ++j) acc[i][j] = 0.f;

    for (int k0 = 0; k0 < CK; k0 += 32) {
#pragma unroll
        for (int p = 0; p < 4; ++p) {
            int kk = p * 8 + lrow;
            *reinterpret_cast<float4*>(&As[kk][lcol]) =
                *reinterpret_cast<const float4*>(&mk[(size_t)(k0 + kk) * HW + m0 + lcol]);
            *reinterpret_cast<float4*>(&Bs[kk][lcol]) =
                *reinterpret_cast<const float4*>(&qk[(size_t)(k0 + kk) * HW + q0 + lcol]);
        }
        __syncthreads();
#pragma unroll 8
        for (int kk = 0; kk < 32; ++kk) {
            float4 a0 = *reinterpret_cast<const float4*>(&As[kk][ty * 4]);
            float4 a1 = *reinterpret_cast<const float4*>(&As[kk][ty * 4 + 64]);
            float4 b0 = *reinterpret_cast<const float4*>(&Bs[kk][tx * 4]);
            float4 b1 = *reinterpret_cast<const float4*>(&Bs[kk][tx * 4 + 64]);
            float a[8] = {a0.x, a0.y, a0.z, a0.w, a1.x, a1.y, a1.z, a1.w};
            float bv[8] = {b0.x, b0.y, b0.z, b0.w, b1.x, b1.y, b1.z, b1.w};
#pragma unroll
            for (int i = 0; i < 8; ++i)
#pragma unroll
                for (int j = 0; j < 8; ++j)
                    acc[i][j] += a[i] * bv[j];
        }
        __syncthreads();
    }

    const float scale = 0.0625f;  // 1/sqrt(256)
#pragma unroll
    for (int i = 0; i < 8; ++i) {
        int m = m0 + ty * 4 + (i & 3) + ((i >> 2) << 6);
        float* srow = g_S + (size_t)b * (HW * HW) + (size_t)m * HW + q0;
#pragma unroll
        for (int jq = 0; jq < 2; ++jq) {
            int col = tx * 4 + jq * 64;
            float4 o;
            o.x = acc[i][jq * 4 + 0] * scale;
            o.y = acc[i][jq * 4 + 1] * scale;
            o.z = acc[i][jq * 4 + 2] * scale;
            o.w = acc[i][jq * 4 + 3] * scale;
            *reinterpret_cast<float4*>(&srow[col]) = o;
        }
    }
}

// ---------------------------------------------------------------------------
// Column softmax over m (axis=1): S <- exp(S - colmax); g_rsum = 1/colsum
// block (32,8): 32 q-columns per block, 8-row strip-mined reduction.
// ---------------------------------------------------------------------------
__global__ void softmax_col()
{
    __shared__ float red[8][32];
    int tx = threadIdx.x, ty = threadIdx.y;
    int b = blockIdx.y;
    int q = blockIdx.x * 32 + tx;
    float* col = g_S + (size_t)b * (HW * HW) + q;

    float mx = -3.402823e38f;
    for (int m = ty; m < HW; m += 8)
        mx = fmaxf(mx, col[(size_t)m * HW]);
    red[ty][tx] = mx;
    __syncthreads();
    if (ty == 0) {
        float v = red[0][tx];
#pragma unroll
        for (int r = 1; r < 8; ++r) v = fmaxf(v, red[r][tx]);
        red[0][tx] = v;
    }
    __syncthreads();
    mx = red[0][tx];
    __syncthreads();

    float s = 0.f;
    for (int m = ty; m < HW; m += 8) {
        float e = __expf(col[(size_t)m * HW] - mx);
        col[(size_t)m * HW] = e;
        s += e;
    }
    red[ty][tx] = s;
    __syncthreads();
    if (ty == 0) {
        float v = red[0][tx];
#pragma unroll
        for (int r = 1; r < 8; ++r) v += red[r][tx];
        g_rsum[b * HW + q] = 1.0f / v;
    }
}

// ---------------------------------------------------------------------------
// Output: out[b][c][q] = (sum_m mv[b][c][m] * E[b][m][q]) * rsum[b][q]
// A is row-major [c][m] -> transposed smem load with +1 pad (scalar a-reads).
// ---------------------------------------------------------------------------
__global__ __launch_bounds__(256, 2)
void out_gemm(float* __restrict__ out)
{
    __shared__ float As[32][129];
    __shared__ float Bs[32][128];
    int tid = threadIdx.x, tx = tid & 15, ty = tid >> 4;
    int b  = blockIdx.z;
    int c0 = blockIdx.y * 128;
    int q0 = blockIdx.x * 128;
    const float* mv = g_mv + (size_t)b * (CV * HW);
    const float* E  = g_S  + (size_t)b * (HW * HW);

    float acc[8][8];
#pragma unroll
    for (int i = 0; i < 8; ++i)
#pragma unroll
        for (int j = 0; j < 8; ++j) acc[i][j] = 0.f;

    for (int k0 = 0; k0 < HW; k0 += 32) {
        // transposed A load: As[kk][mm] = mv[c0+mm][k0+kk]
#pragma unroll
        for (int p = 0; p < 4; ++p) {
            int mm = p * 32 + (tid >> 3);
            int k4 = (tid & 7) * 4;
            float4 v = *reinterpret_cast<const float4*>(&mv[(size_t)(c0 + mm) * HW + k0 + k4]);
            As[k4 + 0][mm] = v.x;
            As[k4 + 1][mm] = v.y;
            As[k4 + 2][mm] = v.z;
            As[k4 + 3][mm] = v.w;
        }
#pragma unroll
        for (int p = 0; p < 4; ++p) {
            int kk = p * 8 + (tid >> 5);
            int nn = (tid & 31) * 4;
            *reinterpret_cast<float4*>(&Bs[kk][nn]) =
                *reinterpret_cast<const float4*>(&E[(size_t)(k0 + kk) * HW + q0 + nn]);
        }
        __syncthreads();
#pragma unroll 8
        for (int kk = 0; kk < 32; ++kk) {
            float a[8];
#pragma unroll
            for (int i = 0; i < 8; ++i)
                a[i] = As[kk][ty * 4 + (i & 3) + ((i >> 2) << 6)];
            float4 b0 = *reinterpret_cast<const float4*>(&Bs[kk][tx * 4]);
            float4 b1 = *reinterpret_cast<const float4*>(&Bs[kk][tx * 4 + 64]);
            float bv[8] = {b0.x, b0.y, b0.z, b0.w, b1.x, b1.y, b1.z, b1.w};
#pragma unroll
            for (int i = 0; i < 8; ++i)
#pragma unroll
                for (int j = 0; j < 8; ++j)
                    acc[i][j] += a[i] * bv[j];
        }
        __syncthreads();
    }

    const float* rs = g_rsum + b * HW + q0;
    float4 r0 = *reinterpret_cast<const float4*>(&rs[tx * 4]);
    float4 r1 = *reinterpret_cast<const float4*>(&rs[tx * 4 + 64]);
    float rv[8] = {r0.x, r0.y, r0.z, r0.w, r1.x, r1.y, r1.z, r1.w};
#pragma unroll
    for (int i = 0; i < 8; ++i) {
        int c = c0 + ty * 4 + (i & 3) + ((i >> 2) << 6);
        float* drow = out + (size_t)b * (2 * CV * HW) + (size_t)c * HW + q0;
#pragma unroll
        for (int jq = 0; jq < 2; ++jq) {
            int col = tx * 4 + jq * 64;
            float4 o;
            o.x = acc[i][jq * 4 + 0] * rv[jq * 4 + 0];
            o.y = acc[i][jq * 4 + 1] * rv[jq * 4 + 1];
            o.z = acc[i][jq * 4 + 2] * rv[jq * 4 + 2];
            o.w = acc[i][jq * 4 + 3] * rv[jq * 4 + 3];
            *reinterpret_cast<float4*>(&drow[col]) = o;
        }
    }
}

// ---------------------------------------------------------------------------
// Launch
// ---------------------------------------------------------------------------
extern "C" void kernel_launch(void* const* d_in, const int* in_sizes, int n_in,
                              void* d_out, int out_size)
{
    const float* src_t = (const float*)d_in[0];
    const float* src_s = (const float*)d_in[1];
    const float* wk_m  = (const float*)d_in[2];
    const float* bk_m  = (const float*)d_in[3];
    const float* wv_m  = (const float*)d_in[4];
    const float* bv_m  = (const float*)d_in[5];
    const float* wk_q  = (const float*)d_in[6];
    const float* bk_q  = (const float*)d_in[7];
    const float* wv_q  = (const float*)d_in[8];
    const float* bv_q  = (const float*)d_in[9];
    float* out = (float*)d_out;

    // 1. weight reshuffle (both branches)
    {
        int n = KTOT * MTOT;
        int blk = (n + 255) / 256;
        transpose_w<<<blk, 256>>>(wk_m, wv_m, 0);
        transpose_w<<<blk, 256>>>(wk_q, wv_q, 1);
    }
    // 2. convs (implicit GEMM). grid: 16384/128 pixel-tiles x 768/128 chan-tiles
    {
        dim3 grid(128, 6);
        conv_gemm<<<grid, 256>>>(src_t, bk_m, bv_m, out, 0);
        conv_gemm<<<grid, 256>>>(src_s, bk_q, bv_q, out, 1);
    }
    // 3. attention scores
    {
        dim3 grid(8, 8, BB);
        scores_gemm<<<grid, 256>>>();
    }
    // 4. column softmax (over memory axis)
    {
        dim3 grid(32, BB);
        dim3 blk(32, 8);
        softmax_col<<<grid, blk>>>();
    }
    // 5. weighted memory readout -> out channels [0, 512)
    {
        dim3 grid(8, 4, BB);
        out_gemm<<<grid, 256>>>(out);
    }
}

// round 6
// speedup vs baseline: 2.1890x; 2.1890x over previous
#include <cuda_runtime.h>
#include <cstdint>

// ---------------------------------------------------------------------------
// Problem constants
// ---------------------------------------------------------------------------
#define BB     16
#define CIN    1024
#define HW     1024      // 32*32
#define CK     256
#define CV     512
#define MTOT   768       // stacked key(256) + value(512) output channels
#define KTOT   9216      // CIN * 9

// conv tensor-core GEMM tiling
#define BM     128
#define BN     256
#define BKC    32
#define KITERS 288       // 9216 / 32
#define LD     36        // BK + 4 pad -> conflict-free fragment LDS
#define STAGE_FLOATS (BM*LD + BN*LD)   // 4608 + 9216 = 13824
#define NSTAGE 3

// ---------------------------------------------------------------------------
// Scratch (device globals; no allocation allowed)
// ---------------------------------------------------------------------------
__device__ float g_wT_t[MTOT * KTOT];        // temp  weights [co][k], tf32-rounded
__device__ float g_wT_s[MTOT * KTOT];        // search weights
__device__ float g_src0[BB * CIN * HW];      // tf32-rounded src_temp
__device__ float g_src1[BB * CIN * HW];      // tf32-rounded src_search
__device__ float g_mk[BB * CK * HW];
__device__ float g_qk[BB * CK * HW];
__device__ float g_mv[BB * CV * HW];
__device__ float g_S [BB * HW * HW];
__device__ float g_rsum[BB * HW];

__device__ __forceinline__ float rna_tf32(float x) {
    float y; asm("cvt.rna.tf32.f32 %0, %1;" : "=f"(y) : "f"(x)); return y;
}

// ---------------------------------------------------------------------------
// Round sources to tf32 (RNA) once
// ---------------------------------------------------------------------------
__global__ void round_src_k(const float* __restrict__ a, int which)
{
    int i = blockIdx.x * blockDim.x + threadIdx.x;   // float4 index
    float4 v = reinterpret_cast<const float4*>(a)[i];
    v.x = rna_tf32(v.x); v.y = rna_tf32(v.y);
    v.z = rna_tf32(v.z); v.w = rna_tf32(v.w);
    float* dst = which ? g_src1 : g_src0;
    reinterpret_cast<float4*>(dst)[i] = v;
}

// ---------------------------------------------------------------------------
// Weight reshuffle: wT[co][k = r*1024 + ci] = rna_tf32( w[co][ci][r] )
// ---------------------------------------------------------------------------
__global__ void transpose_w(const float* __restrict__ wk,
                            const float* __restrict__ wv,
                            int which)
{
    int idx = blockIdx.x * blockDim.x + threadIdx.x;
    if (idx >= MTOT * KTOT) return;
    int co = idx / KTOT;
    int k  = idx - co * KTOT;
    int ci = k & 1023;
    int r  = k >> 10;
    float v = (co < CK) ? wk[co * KTOT + ci * 9 + r]
                        : wv[(co - CK) * KTOT + ci * 9 + r];
    (which ? g_wT_s : g_wT_t)[idx] = rna_tf32(v);
}

// ---------------------------------------------------------------------------
// cp.async helpers
// ---------------------------------------------------------------------------
__device__ __forceinline__ void cp_async16(uint32_t s, const void* g) {
    asm volatile("cp.async.cg.shared.global [%0], [%1], 16;" :: "r"(s), "l"(g));
}
__device__ __forceinline__ void cp_async4(uint32_t s, const void* g, int sz) {
    asm volatile("cp.async.ca.shared.global [%0], [%1], 4, %2;"
                 :: "r"(s), "l"(g), "r"(sz));
}
__device__ __forceinline__ void cp_commit() {
    asm volatile("cp.async.commit_group;");
}
__device__ __forceinline__ void cp_wait1() {
    asm volatile("cp.async.wait_group 1;");
}

// ---------------------------------------------------------------------------
// TF32 tensor-core implicit-GEMM conv.
// C[768, 16384] ; A = wT [co][k] (tf32), B = im2col(src) on the fly (tf32).
// BM=128, BN=256, BK=32, 256 thr, 8 warps of 64x64 (4x8 m16n8k8 tiles).
// 3-stage cp.async pipeline; LD=36 pad -> conflict-free fragment LDS.
// which==0: temp -> g_mk / g_mv ; which==1: search -> g_qk / d_out[512..]
// ---------------------------------------------------------------------------
__global__ __launch_bounds__(256, 1)
void conv_mma(const float* __restrict__ bias_k,
              const float* __restrict__ bias_v,
              float* __restrict__ out,
              int which)
{
    extern __shared__ float sm[];
    const float* __restrict__ wT  = which ? g_wT_s : g_wT_t;
    const float* __restrict__ src = which ? g_src1 : g_src0;

    const int tid  = threadIdx.x;
    const int warp = tid >> 5, lane = tid & 31;
    const int grp  = lane >> 2, tig = lane & 3;
    const int wm   = (warp >> 2) * 64;      // 0 / 64
    const int wn   = (warp & 3) * 64;       // 0..192

    const int npix0 = blockIdx.x * BN;      // over B*HW (256-pixel tiles, never straddle batch)
    const int co0   = blockIdx.y * BM;
    const int b     = npix0 >> 10;
    const int pix0  = npix0 & 1023;
    const float* srcb = src + (size_t)b * (CIN * HW);

    const uint32_t smem_u = (uint32_t)__cvta_generic_to_shared(sm);

    // staging maps
    const int ac = tid & 7;       // A: float4 k-index
    const int am = tid >> 3;      // A: row base 0..31
    const int bpix = pix0 + tid;  // B: this thread's pixel (n = tid)
    const int bpy = bpix >> 5, bpx = bpix & 31;

    float acc[4][8][4];
#pragma unroll
    for (int mt = 0; mt < 4; ++mt)
#pragma unroll
        for (int nt = 0; nt < 8; ++nt)
#pragma unroll
            for (int c = 0; c < 4; ++c) acc[mt][nt][c] = 0.f;

    // ---- stage loader -----------------------------------------------------
    auto issue = [&](int kt, int buf) {
        const int r   = kt >> 5;            // filter tap 0..8
        const int ci0 = (kt & 31) << 5;     // input-channel base
        const uint32_t sA = smem_u + (uint32_t)buf * (STAGE_FLOATS * 4);
        // A tile: 128 rows x 32 k, fully in-bounds, cp.async.16
        const float* arow = wT + (size_t)co0 * KTOT + (size_t)r * 1024 + ci0;
#pragma unroll
        for (int p = 0; p < 4; ++p) {
            int mm = am + p * 32;
            cp_async16(sA + (uint32_t)(mm * LD + ac * 4) * 4,
                       arow + (size_t)mm * KTOT + ac * 4);
        }
        // B tile: 256 n x 32 k, per-element cp.async.4 with zero-fill halo
        const int dy = r / 3 - 1, dx = r % 3 - 1;
        const int iy = bpy + dy, ix = bpx + dx;
        const bool ok = ((unsigned)iy < 32u) && ((unsigned)ix < 32u);
        const float* g = srcb + (size_t)ci0 * HW + (ok ? (iy * 32 + ix) : 0);
        const int sz = ok ? 4 : 0;
        const uint32_t sB = sA + BM * LD * 4 + (uint32_t)tid * (LD * 4);
#pragma unroll
        for (int j = 0; j < 32; ++j)
            cp_async4(sB + j * 4, g + (size_t)j * HW, sz);
    };

    issue(0, 0); cp_commit();
    issue(1, 1); cp_commit();

    int buf = 0;
    for (int kt = 0; kt < KITERS; ++kt) {
        cp_wait1();                 // current stage resident
        __syncthreads();
        if (kt + 2 < KITERS) issue(kt + 2, (buf + 2) % 3);
        cp_commit();

        const float* As = sm + buf * STAGE_FLOATS;
        const float* Bs = As + BM * LD;

#pragma unroll
        for (int s = 0; s < 4; ++s) {
            const int k8 = s * 8;
            uint32_t a[4][4], bf[8][2];
#pragma unroll
            for (int mt = 0; mt < 4; ++mt) {
                int row = wm + mt * 16 + grp;
                a[mt][0] = __float_as_uint(As[row * LD + k8 + tig]);
                a[mt][1] = __float_as_uint(As[(row + 8) * LD + k8 + tig]);
                a[mt][2] = __float_as_uint(As[row * LD + k8 + tig + 4]);
                a[mt][3] = __float_as_uint(As[(row + 8) * LD + k8 + tig + 4]);
            }
#pragma unroll
            for (int nt = 0; nt < 8; ++nt) {
                int col = wn + nt * 8 + grp;
                bf[nt][0] = __float_as_uint(Bs[col * LD + k8 + tig]);
                bf[nt][1] = __float_as_uint(Bs[col * LD + k8 + tig + 4]);
            }
#pragma unroll
            for (int mt = 0; mt < 4; ++mt)
#pragma unroll
                for (int nt = 0; nt < 8; ++nt)
                    asm volatile(
                        "mma.sync.aligned.m16n8k8.row.col.f32.tf32.tf32.f32 "
                        "{%0,%1,%2,%3}, {%4,%5,%6,%7}, {%8,%9}, {%0,%1,%2,%3};"
                        : "+f"(acc[mt][nt][0]), "+f"(acc[mt][nt][1]),
                          "+f"(acc[mt][nt][2]), "+f"(acc[mt][nt][3])
                        : "r"(a[mt][0]), "r"(a[mt][1]), "r"(a[mt][2]), "r"(a[mt][3]),
                          "r"(bf[nt][0]), "r"(bf[nt][1]));
        }
        buf = (buf + 1) % 3;
    }

    // ---- epilogue: c0,c1 -> (row0, 2tig..2tig+1) ; c2,c3 -> (row0+8, ...) --
    const bool is_key = (co0 < CK);
#pragma unroll
    for (int mt = 0; mt < 4; ++mt) {
        int r0 = co0 + wm + mt * 16 + grp;
        int r1 = r0 + 8;
        float bia0, bia1;
        float *d0, *d1;
        if (is_key) {
            float* base = (which ? g_qk : g_mk) + (size_t)b * (CK * HW);
            bia0 = bias_k[r0]; bia1 = bias_k[r1];
            d0 = base + (size_t)r0 * HW;
            d1 = base + (size_t)r1 * HW;
        } else {
            int c0v = r0 - CK, c1v = r1 - CK;
            bia0 = bias_v[c0v]; bia1 = bias_v[c1v];
            if (which) {
                float* base = out + (size_t)b * (2 * CV * HW) + (size_t)CV * HW;
                d0 = base + (size_t)c0v * HW;
                d1 = base + (size_t)c1v * HW;
            } else {
                float* base = g_mv + (size_t)b * (CV * HW);
                d0 = base + (size_t)c0v * HW;
                d1 = base + (size_t)c1v * HW;
            }
        }
#pragma unroll
        for (int nt = 0; nt < 8; ++nt) {
            int col = pix0 + wn + nt * 8 + 2 * tig;
            float2 v0 = make_float2(acc[mt][nt][0] + bia0, acc[mt][nt][1] + bia0);
            float2 v1 = make_float2(acc[mt][nt][2] + bia1, acc[mt][nt][3] + bia1);
            *reinterpret_cast<float2*>(&d0[col]) = v0;
            *reinterpret_cast<float2*>(&d1[col]) = v1;
        }
    }
}

// ---------------------------------------------------------------------------
// Scores: S[b][m][q] = (1/16) * sum_c mk[b][c][m] * qk[b][c][q]   (unchanged)
// ---------------------------------------------------------------------------
__global__ __launch_bounds__(256, 2)
void scores_gemm()
{
    __shared__ float As[32][128];
    __shared__ float Bs[32][128];
    int tid = threadIdx.x, tx = tid & 15, ty = tid >> 4;
    int b  = blockIdx.z;
    int m0 = blockIdx.y * 128;
    int q0 = blockIdx.x * 128;
    const float* mk = g_mk + (size_t)b * (CK * HW);
    const float* qk = g_qk + (size_t)b * (CK * HW);

    int lrow = tid >> 5;
    int lcol = (tid & 31) * 4;

    float acc[8][8];
#pragma unroll
    for (int i = 0; i < 8; ++i)
#pragma unroll
        for (int j = 0; j < 8; ++j) acc[i][j] = 0.f;

    for (int k0 = 0; k0 < CK; k0 += 32) {
#pragma unroll
        for (int p = 0; p < 4; ++p) {
            int kk = p * 8 + lrow;
            *reinterpret_cast<float4*>(&As[kk][lcol]) =
                *reinterpret_cast<const float4*>(&mk[(size_t)(k0 + kk) * HW + m0 + lcol]);
            *reinterpret_cast<float4*>(&Bs[kk][lcol]) =
                *reinterpret_cast<const float4*>(&qk[(size_t)(k0 + kk) * HW + q0 + lcol]);
        }
        __syncthreads();
#pragma unroll 8
        for (int kk = 0; kk < 32; ++kk) {
            float4 a0 = *reinterpret_cast<const float4*>(&As[kk][ty * 4]);
            float4 a1 = *reinterpret_cast<const float4*>(&As[kk][ty * 4 + 64]);
            float4 b0 = *reinterpret_cast<const float4*>(&Bs[kk][tx * 4]);
            float4 b1 = *reinterpret_cast<const float4*>(&Bs[kk][tx * 4 + 64]);
            float a[8] = {a0.x, a0.y, a0.z, a0.w, a1.x, a1.y, a1.z, a1.w};
            float bv[8] = {b0.x, b0.y, b0.z, b0.w, b1.x, b1.y, b1.z, b1.w};
#pragma unroll
            for (int i = 0; i < 8; ++i)
#pragma unroll
                for (int j = 0; j < 8; ++j)
                    acc[i][j] += a[i] * bv[j];
        }
        __syncthreads();
    }

    const float scale = 0.0625f;
#pragma unroll
    for (int i = 0; i < 8; ++i) {
        int m = m0 + ty * 4 + (i & 3) + ((i >> 2) << 6);
        float* srow = g_S + (size_t)b * (HW * HW) + (size_t)m * HW + q0;
#pragma unroll
        for (int jq = 0; jq < 2; ++jq) {
            int col = tx * 4 + jq * 64;
            float4 o;
            o.x = acc[i][jq * 4 + 0] * scale;
            o.y = acc[i][jq * 4 + 1] * scale;
            o.z = acc[i][jq * 4 + 2] * scale;
            o.w = acc[i][jq * 4 + 3] * scale;
            *reinterpret_cast<float4*>(&srow[col]) = o;
        }
    }
}

// ---------------------------------------------------------------------------
// Column softmax over m (axis=1)  (unchanged)
// ---------------------------------------------------------------------------
__global__ void softmax_col()
{
    __shared__ float red[8][32];
    int tx = threadIdx.x, ty = threadIdx.y;
    int b = blockIdx.y;
    int q = blockIdx.x * 32 + tx;
    float* col = g_S + (size_t)b * (HW * HW) + q;

    float mx = -3.402823e38f;
    for (int m = ty; m < HW; m += 8)
        mx = fmaxf(mx, col[(size_t)m * HW]);
    red[ty][tx] = mx;
    __syncthreads();
    if (ty == 0) {
        float v = red[0][tx];
#pragma unroll
        for (int r = 1; r < 8; ++r) v = fmaxf(v, red[r][tx]);
        red[0][tx] = v;
    }
    __syncthreads();
    mx = red[0][tx];
    __syncthreads();

    float s = 0.f;
    for (int m = ty; m < HW; m += 8) {
        float e = __expf(col[(size_t)m * HW] - mx);
        col[(size_t)m * HW] = e;
        s += e;
    }
    red[ty][tx] = s;
    __syncthreads();
    if (ty == 0) {
        float v = red[0][tx];
#pragma unroll
        for (int r = 1; r < 8; ++r) v += red[r][tx];
        g_rsum[b * HW + q] = 1.0f / v;
    }
}

// ---------------------------------------------------------------------------
// Output: out[b][c][q] = (sum_m mv[b][c][m] * E[b][m][q]) * rsum[b][q]  (unchanged)
// ---------------------------------------------------------------------------
__global__ __launch_bounds__(256, 2)
void out_gemm(float* __restrict__ out)
{
    __shared__ float As[32][129];
    __shared__ float Bs[32][128];
    int tid = threadIdx.x, tx = tid & 15, ty = tid >> 4;
    int b  = blockIdx.z;
    int c0 = blockIdx.y * 128;
    int q0 = blockIdx.x * 128;
    const float* mv = g_mv + (size_t)b * (CV * HW);
    const float* E  = g_S  + (size_t)b * (HW * HW);

    float acc[8][8];
#pragma unroll
    for (int i = 0; i < 8; ++i)
#pragma unroll
        for (int j = 0; j < 8; ++j) acc[i][j] = 0.f;

    for (int k0 = 0; k0 < HW; k0 += 32) {
#pragma unroll
        for (int p = 0; p < 4; ++p) {
            int mm = p * 32 + (tid >> 3);
            int k4 = (tid & 7) * 4;
            float4 v = *reinterpret_cast<const float4*>(&mv[(size_t)(c0 + mm) * HW + k0 + k4]);
            As[k4 + 0][mm] = v.x;
            As[k4 + 1][mm] = v.y;
            As[k4 + 2][mm] = v.z;
            As[k4 + 3][mm] = v.w;
        }
#pragma unroll
        for (int p = 0; p < 4; ++p) {
            int kk = p * 8 + (tid >> 5);
            int nn = (tid & 31) * 4;
            *reinterpret_cast<float4*>(&Bs[kk][nn]) =
                *reinterpret_cast<const float4*>(&E[(size_t)(k0 + kk) * HW + q0 + nn]);
        }
        __syncthreads();
#pragma unroll 8
        for (int kk = 0; kk < 32; ++kk) {
            float a[8];
#pragma unroll
            for (int i = 0; i < 8; ++i)
                a[i] = As[kk][ty * 4 + (i & 3) + ((i >> 2) << 6)];
            float4 b0 = *reinterpret_cast<const float4*>(&Bs[kk][tx * 4]);
            float4 b1 = *reinterpret_cast<const float4*>(&Bs[kk][tx * 4 + 64]);
            float bv[8] = {b0.x, b0.y, b0.z, b0.w, b1.x, b1.y, b1.z, b1.w};
#pragma unroll
            for (int i = 0; i < 8; ++i)
#pragma unroll
                for (int j = 0; j < 8; ++j)
                    acc[i][j] += a[i] * bv[j];
        }
        __syncthreads();
    }

    const float* rs = g_rsum + b * HW + q0;
    float4 r0 = *reinterpret_cast<const float4*>(&rs[tx * 4]);
    float4 r1 = *reinterpret_cast<const float4*>(&rs[tx * 4 + 64]);
    float rv[8] = {r0.x, r0.y, r0.z, r0.w, r1.x, r1.y, r1.z, r1.w};
#pragma unroll
    for (int i = 0; i < 8; ++i) {
        int c = c0 + ty * 4 + (i & 3) + ((i >> 2) << 6);
        float* drow = out + (size_t)b * (2 * CV * HW) + (size_t)c * HW + q0;
#pragma unroll
        for (int jq = 0; jq < 2; ++jq) {
            int col = tx * 4 + jq * 64;
            float4 o;
            o.x = acc[i][jq * 4 + 0] * rv[jq * 4 + 0];
            o.y = acc[i][jq * 4 + 1] * rv[jq * 4 + 1];
            o.z = acc[i][jq * 4 + 2] * rv[jq * 4 + 2];
            o.w = acc[i][jq * 4 + 3] * rv[jq * 4 + 3];
            *reinterpret_cast<float4*>(&drow[col]) = o;
        }
    }
}

// ---------------------------------------------------------------------------
// Launch
// ---------------------------------------------------------------------------
extern "C" void kernel_launch(void* const* d_in, const int* in_sizes, int n_in,
                              void* d_out, int out_size)
{
    const float* src_t = (const float*)d_in[0];
    const float* src_s = (const float*)d_in[1];
    const float* wk_m  = (const float*)d_in[2];
    const float* bk_m  = (const float*)d_in[3];
    const float* wv_m  = (const float*)d_in[4];
    const float* bv_m  = (const float*)d_in[5];
    const float* wk_q  = (const float*)d_in[6];
    const float* bk_q  = (const float*)d_in[7];
    const float* wv_q  = (const float*)d_in[8];
    const float* bv_q  = (const float*)d_in[9];
    float* out = (float*)d_out;

    const size_t shm = (size_t)NSTAGE * STAGE_FLOATS * sizeof(float); // 165,888 B
    cudaFuncSetAttribute(conv_mma, cudaFuncAttributeMaxDynamicSharedMemorySize, (int)shm);

    // 0. tf32 round sources (RNA) into device-global copies
    {
        int n4 = (BB * CIN * HW) / 4;          // 4,194,304
        round_src_k<<<n4 / 256, 256>>>(src_t, 0);
        round_src_k<<<n4 / 256, 256>>>(src_s, 1);
    }
    // 1. weight reshuffle + tf32 round
    {
        int n = MTOT * KTOT;
        transpose_w<<<(n + 255) / 256, 256>>>(wk_m, wv_m, 0);
        transpose_w<<<(n + 255) / 256, 256>>>(wk_q, wv_q, 1);
    }
    // 2. tensor-core convs: grid 64 pixel-tiles x 6 channel-tiles
    {
        dim3 grid(64, 6);
        conv_mma<<<grid, 256, shm>>>(bk_m, bv_m, out, 0);
        conv_mma<<<grid, 256, shm>>>(bk_q, bv_q, out, 1);
    }
    // 3. attention scores
    {
        dim3 grid(8, 8, BB);
        scores_gemm<<<grid, 256>>>();
    }
    // 4. column softmax
    {
        dim3 grid(32, BB);
        dim3 blk(32, 8);
        softmax_col<<<grid, blk>>>();
    }
    // 5. weighted memory readout -> out channels [0, 512)
    {
        dim3 grid(8, 4, BB);
        out_gemm<<<grid, 256>>>(out);
    }
}

// round 8
// speedup vs baseline: 3.6246x; 1.6558x over previous
#include <cuda_runtime.h>
#include <cuda_fp16.h>
#include <cstdint>

// ---------------------------------------------------------------------------
// Problem constants
// ---------------------------------------------------------------------------
#define BB     16
#define CIN    1024
#define HW     1024      // 32*32
#define CK     256
#define CV     512
#define MTOT   768       // stacked key(256) + value(512) output channels
#define KTOT   9216      // CIN * 9

// conv f16 tensor-core GEMM tiling
#define BM     128
#define BN     256
#define BKC    32
#define KITERS 288       // 9216 / 32
#define LDH    40        // smem pitch in halfs (80 B) -> conflict-free frags
#define A_BYTES (BM * LDH * 2)          // 10240
#define B_BYTES (BN * LDH * 2)          // 20480
#define STAGE_BYTES (A_BYTES + B_BYTES) // 30720
#define NSTAGE 3
#define SMEM_TOTAL (NSTAGE * STAGE_BYTES)   // 92160

// ---------------------------------------------------------------------------
// Scratch (device globals; no allocation allowed)
// ---------------------------------------------------------------------------
__device__ __half g_wT_t[MTOT * KTOT];     // temp  weights [co][k], f16
__device__ __half g_wT_s[MTOT * KTOT];     // search weights
__device__ __half g_srcT0[BB * HW * CIN];  // transposed f16 src_temp  [b][pix][ci]
__device__ __half g_srcT1[BB * HW * CIN];  // transposed f16 src_search
__device__ float g_mk[BB * CK * HW];
__device__ float g_qk[BB * CK * HW];
__device__ float g_mv[BB * CV * HW];
__device__ float g_S [BB * HW * HW];
__device__ float g_rsum[BB * HW];

// ---------------------------------------------------------------------------
// cp.async helpers
// ---------------------------------------------------------------------------
__device__ __forceinline__ void cp_async16z(uint32_t s, const void* g, int sz) {
    asm volatile("cp.async.cg.shared.global [%0], [%1], 16, %2;"
                 :: "r"(s), "l"(g), "r"(sz));
}
__device__ __forceinline__ void cp_commit() { asm volatile("cp.async.commit_group;"); }
__device__ __forceinline__ void cp_wait1()  { asm volatile("cp.async.wait_group 1;"); }

// ---------------------------------------------------------------------------
// Pre-pass 1: transpose + f16 src: [b][ci][pix] -> [b][pix][ci]
// grid (32 pixTiles, 32 ciTiles, B), block (32,8)
// ---------------------------------------------------------------------------
__global__ void transpose_src(const float* __restrict__ src, int which)
{
    __shared__ float t[32][33];
    int b = blockIdx.z;
    int pix0 = blockIdx.x * 32, ci0 = blockIdx.y * 32;
    const float* s = src + ((size_t)b * CIN + ci0) * HW + pix0;
    for (int i = threadIdx.y; i < 32; i += 8)
        t[i][threadIdx.x] = s[(size_t)i * HW + threadIdx.x];   // t[ci][pix]
    __syncthreads();
    __half* d = (which ? g_srcT1 : g_srcT0) + ((size_t)b * HW + pix0) * CIN + ci0;
    for (int i = threadIdx.y; i < 32; i += 8)
        d[(size_t)i * CIN + threadIdx.x] = __float2half_rn(t[threadIdx.x][i]);
}

// ---------------------------------------------------------------------------
// Pre-pass 2: weight reshuffle wT[co][k = r*1024+ci] = f16(w[co][ci][r])
// ---------------------------------------------------------------------------
__global__ void transpose_w(const float* __restrict__ wk,
                            const float* __restrict__ wv, int which)
{
    int idx = blockIdx.x * blockDim.x + threadIdx.x;
    if (idx >= MTOT * KTOT) return;
    int co = idx / KTOT;
    int k  = idx - co * KTOT;
    int ci = k & 1023;
    int r  = k >> 10;
    float v = (co < CK) ? wk[co * KTOT + ci * 9 + r]
                        : wv[(co - CK) * KTOT + ci * 9 + r];
    (which ? g_wT_s : g_wT_t)[idx] = __float2half_rn(v);
}

// ---------------------------------------------------------------------------
// FP16 tensor-core implicit-GEMM conv (mma.sync.m16n8k16.f32.f16.f16.f32).
// C[768, B*HW]; A = wT[co][k] f16, B = im2col(srcT) f16, fp32 accumulate.
// BM=128, BN=256, BK=32 (2 x k16), 256 thr, 8 warps of 64x64.
// 3-stage cp.async pipeline; pitch-40-half smem, conflict-free fragment LDS.
// which==0: temp -> g_mk / g_mv ; which==1: search -> g_qk / d_out[512..]
// ---------------------------------------------------------------------------
__global__ __launch_bounds__(256, 1)
void conv_mma(const float* __restrict__ bias_k,
              const float* __restrict__ bias_v,
              float* __restrict__ out,
              int which)
{
    extern __shared__ char sm[];
    const __half* __restrict__ wT   = which ? g_wT_s : g_wT_t;
    const __half* __restrict__ srcT = which ? g_srcT1 : g_srcT0;

    const int tid  = threadIdx.x;
    const int warp = tid >> 5, lane = tid & 31;
    const int grp  = lane >> 2, tig = lane & 3;
    const int wm   = (warp >> 2) * 64;      // 0 / 64
    const int wn   = (warp & 3) * 64;       // 0..192

    const int npix0 = blockIdx.x * BN;      // 256-pixel tiles, never straddle batch
    const int co0   = blockIdx.y * BM;
    const int b     = npix0 >> 10;
    const int pix0  = npix0 & 1023;
    const __half* srcTb = srcT + (size_t)b * (HW * CIN);

    const uint32_t smem_u = (uint32_t)__cvta_generic_to_shared(sm);

    // B-load per-thread pixel (row n = tid)
    const int bp = pix0 + tid;
    const int by = bp >> 5, bx = bp & 31;

    float acc[4][8][4];
#pragma unroll
    for (int mt = 0; mt < 4; ++mt)
#pragma unroll
        for (int nt = 0; nt < 8; ++nt)
#pragma unroll
            for (int c = 0; c < 4; ++c) acc[mt][nt][c] = 0.f;

    // ---- stage loader: 6 cp.async.16 per thread -----------------------------
    auto issue = [&](int kt, int buf) {
        const int r   = kt >> 5;            // filter tap 0..8
        const int ci0 = (kt & 31) << 5;     // input-channel base
        const uint32_t sA = smem_u + (uint32_t)buf * STAGE_BYTES;
        const uint32_t sB = sA + A_BYTES;
        // A: 128 rows x 64B (32 halfs); 512 16B-chunks, 2 per thread
        const __half* abase = wT + (size_t)co0 * KTOT + kt * 32;
#pragma unroll
        for (int j = 0; j < 2; ++j) {
            int c = tid * 2 + j;            // 0..511
            int m = c >> 2;                 // 0..127
            int q = c & 3;                  // 16B chunk in row
            cp_async16z(sA + (uint32_t)(m * (LDH * 2) + q * 16),
                        abase + (size_t)m * KTOT + q * 8, 16);
        }
        // B: 256 rows x 64B; row n = tid, 4 chunks, contiguous in srcT
        const int dy = r / 3 - 1, dx = r % 3 - 1;
        const int iy = by + dy, ix = bx + dx;
        const bool ok = ((unsigned)iy < 32u) && ((unsigned)ix < 32u);
        const __half* g = srcTb + (size_t)(ok ? (iy * 32 + ix) : 0) * CIN + ci0;
        const int sz = ok ? 16 : 0;
        const uint32_t rb = (uint32_t)tid * (LDH * 2);
#pragma unroll
        for (int j = 0; j < 4; ++j)
            cp_async16z(sB + rb + j * 16, g + j * 8, sz);
    };

    issue(0, 0); cp_commit();
    issue(1, 1); cp_commit();

    int buf = 0;
    for (int kt = 0; kt < KITERS; ++kt) {
        cp_wait1();                 // current stage resident
        __syncthreads();
        if (kt + 2 < KITERS) issue(kt + 2, (buf + 2) % 3);
        cp_commit();

        const __half* As = reinterpret_cast<const __half*>(sm + buf * STAGE_BYTES);
        const __half* Bs = reinterpret_cast<const __half*>(sm + buf * STAGE_BYTES + A_BYTES);

#pragma unroll
        for (int s = 0; s < 2; ++s) {
            const int k16 = s * 16;
            uint32_t a[4][4], bf[8][2];
#pragma unroll
            for (int mt = 0; mt < 4; ++mt) {
                int row = wm + mt * 16 + grp;
                a[mt][0] = *reinterpret_cast<const uint32_t*>(&As[row * LDH + k16 + 2 * tig]);
                a[mt][1] = *reinterpret_cast<const uint32_t*>(&As[(row + 8) * LDH + k16 + 2 * tig]);
                a[mt][2] = *reinterpret_cast<const uint32_t*>(&As[row * LDH + k16 + 2 * tig + 8]);
                a[mt][3] = *reinterpret_cast<const uint32_t*>(&As[(row + 8) * LDH + k16 + 2 * tig + 8]);
            }
#pragma unroll
            for (int nt = 0; nt < 8; ++nt) {
                int col = wn + nt * 8 + grp;
                bf[nt][0] = *reinterpret_cast<const uint32_t*>(&Bs[col * LDH + k16 + 2 * tig]);
                bf[nt][1] = *reinterpret_cast<const uint32_t*>(&Bs[col * LDH + k16 + 2 * tig + 8]);
            }
#pragma unroll
            for (int mt = 0; mt < 4; ++mt)
#pragma unroll
                for (int nt = 0; nt < 8; ++nt)
                    asm volatile(
                        "mma.sync.aligned.m16n8k16.row.col.f32.f16.f16.f32 "
                        "{%0,%1,%2,%3}, {%4,%5,%6,%7}, {%8,%9}, {%0,%1,%2,%3};"
                        : "+f"(acc[mt][nt][0]), "+f"(acc[mt][nt][1]),
                          "+f"(acc[mt][nt][2]), "+f"(acc[mt][nt][3])
                        : "r"(a[mt][0]), "r"(a[mt][1]), "r"(a[mt][2]), "r"(a[mt][3]),
                          "r"(bf[nt][0]), "r"(bf[nt][1]));
        }
        buf = (buf + 1) % 3;
    }

    // ---- epilogue: c0,c1 -> (row0, 2tig..2tig+1) ; c2,c3 -> (row0+8, ...) --
    const bool is_key = (co0 < CK);
#pragma unroll
    for (int mt = 0; mt < 4; ++mt) {
        int r0 = co0 + wm + mt * 16 + grp;
        int r1 = r0 + 8;
        float bia0, bia1;
        float *d0, *d1;
        if (is_key) {
            float* base = (which ? g_qk : g_mk) + (size_t)b * (CK * HW);
            bia0 = bias_k[r0]; bia1 = bias_k[r1];
            d0 = base + (size_t)r0 * HW;
            d1 = base + (size_t)r1 * HW;
        } else {
            int c0v = r0 - CK, c1v = r1 - CK;
            bia0 = bias_v[c0v]; bia1 = bias_v[c1v];
            if (which) {
                float* base = out + (size_t)b * (2 * CV * HW) + (size_t)CV * HW;
                d0 = base + (size_t)c0v * HW;
                d1 = base + (size_t)c1v * HW;
            } else {
                float* base = g_mv + (size_t)b * (CV * HW);
                d0 = base + (size_t)c0v * HW;
                d1 = base + (size_t)c1v * HW;
            }
        }
#pragma unroll
        for (int nt = 0; nt < 8; ++nt) {
            int col = pix0 + wn + nt * 8 + 2 * tig;
            float2 v0 = make_float2(acc[mt][nt][0] + bia0, acc[mt][nt][1] + bia0);
            float2 v1 = make_float2(acc[mt][nt][2] + bia1, acc[mt][nt][3] + bia1);
            *reinterpret_cast<float2*>(&d0[col]) = v0;
            *reinterpret_cast<float2*>(&d1[col]) = v1;
        }
    }
}

// ---------------------------------------------------------------------------
// Scores: S[b][m][q] = (1/16) * sum_c mk[b][c][m] * qk[b][c][q]   (unchanged)
// ---------------------------------------------------------------------------
__global__ __launch_bounds__(256, 2)
void scores_gemm()
{
    __shared__ float As[32][128];
    __shared__ float Bs[32][128];
    int tid = threadIdx.x, tx = tid & 15, ty = tid >> 4;
    int b  = blockIdx.z;
    int m0 = blockIdx.y * 128;
    int q0 = blockIdx.x * 128;
    const float* mk = g_mk + (size_t)b * (CK * HW);
    const float* qk = g_qk + (size_t)b * (CK * HW);

    int lrow = tid >> 5;
    int lcol = (tid & 31) * 4;

    float acc[8][8];
#pragma unroll
    for (int i = 0; i < 8; ++i)
#pragma unroll
        for (int j = 0; j < 8; ++j) acc[i][j] = 0.f;

    for (int k0 = 0; k0 < CK; k0 += 32) {
#pragma unroll
        for (int p = 0; p < 4; ++p) {
            int kk = p * 8 + lrow;
            *reinterpret_cast<float4*>(&As[kk][lcol]) =
                *reinterpret_cast<const float4*>(&mk[(size_t)(k0 + kk) * HW + m0 + lcol]);
            *reinterpret_cast<float4*>(&Bs[kk][lcol]) =
                *reinterpret_cast<const float4*>(&qk[(size_t)(k0 + kk) * HW + q0 + lcol]);
        }
        __syncthreads();
#pragma unroll 8
        for (int kk = 0; kk < 32; ++kk) {
            float4 a0 = *reinterpret_cast<const float4*>(&As[kk][ty * 4]);
            float4 a1 = *reinterpret_cast<const float4*>(&As[kk][ty * 4 + 64]);
            float4 b0 = *reinterpret_cast<const float4*>(&Bs[kk][tx * 4]);
            float4 b1 = *reinterpret_cast<const float4*>(&Bs[kk][tx * 4 + 64]);
            float a[8] = {a0.x, a0.y, a0.z, a0.w, a1.x, a1.y, a1.z, a1.w};
            float bv[8] = {b0.x, b0.y, b0.z, b0.w, b1.x, b1.y, b1.z, b1.w};
#pragma unroll
            for (int i = 0; i < 8; ++i)
#pragma unroll
                for (int j = 0; j < 8; ++j)
                    acc[i][j] += a[i] * bv[j];
        }
        __syncthreads();
    }

    const float scale = 0.0625f;
#pragma unroll
    for (int i = 0; i < 8; ++i) {
        int m = m0 + ty * 4 + (i & 3) + ((i >> 2) << 6);
        float* srow = g_S + (size_t)b * (HW * HW) + (size_t)m * HW + q0;
#pragma unroll
        for (int jq = 0; jq < 2; ++jq) {
            int col = tx * 4 + jq * 64;
            float4 o;
            o.x = acc[i][jq * 4 + 0] * scale;
            o.y = acc[i][jq * 4 + 1] * scale;
            o.z = acc[i][jq * 4 + 2] * scale;
            o.w = acc[i][jq * 4 + 3] * scale;
            *reinterpret_cast<float4*>(&srow[col]) = o;
        }
    }
}

// ---------------------------------------------------------------------------
// Column softmax over m (axis=1)  (unchanged)
// ---------------------------------------------------------------------------
__global__ void softmax_col()
{
    __shared__ float red[8][32];
    int tx = threadIdx.x, ty = threadIdx.y;
    int b = blockIdx.y;
    int q = blockIdx.x * 32 + tx;
    float* col = g_S + (size_t)b * (HW * HW) + q;

    float mx = -3.402823e38f;
    for (int m = ty; m < HW; m += 8)
        mx = fmaxf(mx, col[(size_t)m * HW]);
    red[ty][tx] = mx;
    __syncthreads();
    if (ty == 0) {
        float v = red[0][tx];
#pragma unroll
        for (int r = 1; r < 8; ++r) v = fmaxf(v, red[r][tx]);
        red[0][tx] = v;
    }
    __syncthreads();
    mx = red[0][tx];
    __syncthreads();

    float s = 0.f;
    for (int m = ty; m < HW; m += 8) {
        float e = __expf(col[(size_t)m * HW] - mx);
        col[(size_t)m * HW] = e;
        s += e;
    }
    red[ty][tx] = s;
    __syncthreads();
    if (ty == 0) {
        float v = red[0][tx];
#pragma unroll
        for (int r = 1; r < 8; ++r) v += red[r][tx];
        g_rsum[b * HW + q] = 1.0f / v;
    }
}

// ---------------------------------------------------------------------------
// Output: out[b][c][q] = (sum_m mv[b][c][m] * E[b][m][q]) * rsum[b][q]  (unchanged)
// ---------------------------------------------------------------------------
__global__ __launch_bounds__(256, 2)
void out_gemm(float* __restrict__ out)
{
    __shared__ float As[32][129];
    __shared__ float Bs[32][128];
    int tid = threadIdx.x, tx = tid & 15, ty = tid >> 4;
    int b  = blockIdx.z;
    int c0 = blockIdx.y * 128;
    int q0 = blockIdx.x * 128;
    const float* mv = g_mv + (size_t)b * (CV * HW);
    const float* E  = g_S  + (size_t)b * (HW * HW);

    float acc[8][8];
#pragma unroll
    for (int i = 0; i < 8; ++i)
#pragma unroll
        for (int j = 0; j < 8; ++j) acc[i][j] = 0.f;

    for (int k0 = 0; k0 < HW; k0 += 32) {
#pragma unroll
        for (int p = 0; p < 4; ++p) {
            int mm = p * 32 + (tid >> 3);
            int k4 = (tid & 7) * 4;
            float4 v = *reinterpret_cast<const float4*>(&mv[(size_t)(c0 + mm) * HW + k0 + k4]);
            As[k4 + 0][mm] = v.x;
            As[k4 + 1][mm] = v.y;
            As[k4 + 2][mm] = v.z;
            As[k4 + 3][mm] = v.w;
        }
#pragma unroll
        for (int p = 0; p < 4; ++p) {
            int kk = p * 8 + (tid >> 5);
            int nn = (tid & 31) * 4;
            *reinterpret_cast<float4*>(&Bs[kk][nn]) =
                *reinterpret_cast<const float4*>(&E[(size_t)(k0 + kk) * HW + q0 + nn]);
        }
        __syncthreads();
#pragma unroll 8
        for (int kk = 0; kk < 32; ++kk) {
            float a[8];
#pragma unroll
            for (int i = 0; i < 8; ++i)
                a[i] = As[kk][ty * 4 + (i & 3) + ((i >> 2) << 6)];
            float4 b0 = *reinterpret_cast<const float4*>(&Bs[kk][tx * 4]);
            float4 b1 = *reinterpret_cast<const float4*>(&Bs[kk][tx * 4 + 64]);
            float bv[8] = {b0.x, b0.y, b0.z, b0.w, b1.x, b1.y, b1.z, b1.w};
#pragma unroll
            for (int i = 0; i < 8; ++i)
#pragma unroll
                for (int j = 0; j < 8; ++j)
                    acc[i][j] += a[i] * bv[j];
        }
        __syncthreads();
    }

    const float* rs = g_rsum + b * HW + q0;
    float4 r0 = *reinterpret_cast<const float4*>(&rs[tx * 4]);
    float4 r1 = *reinterpret_cast<const float4*>(&rs[tx * 4 + 64]);
    float rv[8] = {r0.x, r0.y, r0.z, r0.w, r1.x, r1.y, r1.z, r1.w};
#pragma unroll
    for (int i = 0; i < 8; ++i) {
        int c = c0 + ty * 4 + (i & 3) + ((i >> 2) << 6);
        float* drow = out + (size_t)b * (2 * CV * HW) + (size_t)c * HW + q0;
#pragma unroll
        for (int jq = 0; jq < 2; ++jq) {
            int col = tx * 4 + jq * 64;
            float4 o;
            o.x = acc[i][jq * 4 + 0] * rv[jq * 4 + 0];
            o.y = acc[i][jq * 4 + 1] * rv[jq * 4 + 1];
            o.z = acc[i][jq * 4 + 2] * rv[jq * 4 + 2];
            o.w = acc[i][jq * 4 + 3] * rv[jq * 4 + 3];
            *reinterpret_cast<float4*>(&drow[col]) = o;
        }
    }
}

// ---------------------------------------------------------------------------
// Launch
// ---------------------------------------------------------------------------
extern "C" void kernel_launch(void* const* d_in, const int* in_sizes, int n_in,
                              void* d_out, int out_size)
{
    const float* src_t = (const float*)d_in[0];
    const float* src_s = (const float*)d_in[1];
    const float* wk_m  = (const float*)d_in[2];
    const float* bk_m  = (const float*)d_in[3];
    const float* wv_m  = (const float*)d_in[4];
    const float* bv_m  = (const float*)d_in[5];
    const float* wk_q  = (const float*)d_in[6];
    const float* bk_q  = (const float*)d_in[7];
    const float* wv_q  = (const float*)d_in[8];
    const float* bv_q  = (const float*)d_in[9];
    float* out = (float*)d_out;

    cudaFuncSetAttribute(conv_mma, cudaFuncAttributeMaxDynamicSharedMemorySize,
                         SMEM_TOTAL);

    // 0. transpose + f16 sources: [b][ci][pix] -> [b][pix][ci]
    {
        dim3 grid(32, 32, BB);
        dim3 blk(32, 8);
        transpose_src<<<grid, blk>>>(src_t, 0);
        transpose_src<<<grid, blk>>>(src_s, 1);
    }
    // 1. weight reshuffle + f16 round
    {
        int n = MTOT * KTOT;
        transpose_w<<<(n + 255) / 256, 256>>>(wk_m, wv_m, 0);
        transpose_w<<<(n + 255) / 256, 256>>>(wk_q, wv_q, 1);
    }
    // 2. f16 tensor-core convs: 64 pixel-tiles x 6 channel-tiles
    {
        dim3 grid(64, 6);
        conv_mma<<<grid, 256, SMEM_TOTAL>>>(bk_m, bv_m, out, 0);
        conv_mma<<<grid, 256, SMEM_TOTAL>>>(bk_q, bv_q, out, 1);
    }
    // 3. attention scores
    {
        dim3 grid(8, 8, BB);
        scores_gemm<<<grid, 256>>>();
    }
    // 4. column softmax
    {
        dim3 grid(32, BB);
        dim3 blk(32, 8);
        softmax_col<<<grid, blk>>>();
    }
    // 5. weighted memory readout -> out channels [0, 512)
    {
        dim3 grid(8, 4, BB);
        out_gemm<<<grid, 256>>>(out);
    }
}

// round 9
// speedup vs baseline: 4.1698x; 1.1504x over previous
#include <cuda_runtime.h>
#include <cuda_fp16.h>
#include <cstdint>

// ---------------------------------------------------------------------------
// Problem constants
// ---------------------------------------------------------------------------
#define BB     16
#define CIN    1024
#define HW     1024      // 32*32
#define CK     256
#define CV     512
#define MTOT   768       // stacked key(256) + value(512) output channels
#define KTOT   9216      // CIN * 9

// shared f16 mma tiling (all three GEMMs)
#define BM     128
#define BN     256
#define LDH    40        // smem pitch in halfs (80 B) -> conflict-free frags
#define A_BYTES (BM * LDH * 2)          // 10240
#define B_BYTES (BN * LDH * 2)          // 20480
#define STAGE_BYTES (A_BYTES + B_BYTES) // 30720
#define NSTAGE 3
#define SMEM_TOTAL (NSTAGE * STAGE_BYTES)   // 92160

#define KITERS_CONV 288   // 9216 / 32
#define KITERS_SC   8     // 256 / 32
#define KITERS_OUT  32    // 1024 / 32

// ---------------------------------------------------------------------------
// Scratch (device globals; no allocation allowed)
// ---------------------------------------------------------------------------
__device__ __half g_wT_t[MTOT * KTOT];     // temp  weights [co][k], f16
__device__ __half g_wT_s[MTOT * KTOT];     // search weights
__device__ __half g_srcT0[BB * HW * CIN];  // transposed f16 src_temp  [b][pix][ci]
__device__ __half g_srcT1[BB * HW * CIN];  // transposed f16 src_search
__device__ __half g_mkh[BB * CK * HW];     // m_key   [b][c][pix] f16
__device__ __half g_qkh[BB * CK * HW];     // q_key   [b][c][pix] f16
__device__ __half g_mkT[BB * HW * CK];     // m_key   [b][m][c]   f16
__device__ __half g_qkT[BB * HW * CK];     // q_key   [b][q][c]   f16
__device__ __half g_mvh[BB * CV * HW];     // m_value [b][c][m]   f16
__device__ float  g_S  [BB * HW * HW];     // scores  [b][q][m]   f32
__device__ __half g_E  [BB * HW * HW];     // exp     [b][q][m]   f16
__device__ float  g_rsum[BB * HW];         // 1 / row sum

// ---------------------------------------------------------------------------
// cp.async helpers
// ---------------------------------------------------------------------------
__device__ __forceinline__ void cp_async16z(uint32_t s, const void* g, int sz) {
    asm volatile("cp.async.cg.shared.global [%0], [%1], 16, %2;"
                 :: "r"(s), "l"(g), "r"(sz));
}
__device__ __forceinline__ void cp_commit() { asm volatile("cp.async.commit_group;"); }
__device__ __forceinline__ void cp_wait1()  { asm volatile("cp.async.wait_group 1;"); }

#define MMA_F16(acc, a, bf)                                                   \
    asm volatile(                                                             \
        "mma.sync.aligned.m16n8k16.row.col.f32.f16.f16.f32 "                  \
        "{%0,%1,%2,%3}, {%4,%5,%6,%7}, {%8,%9}, {%0,%1,%2,%3};"               \
        : "+f"((acc)[0]), "+f"((acc)[1]), "+f"((acc)[2]), "+f"((acc)[3])      \
        : "r"((a)[0]), "r"((a)[1]), "r"((a)[2]), "r"((a)[3]),                 \
          "r"((bf)[0]), "r"((bf)[1]))

// ---------------------------------------------------------------------------
// Pre-pass 1: transpose + f16 src: [b][ci][pix] -> [b][pix][ci]
// ---------------------------------------------------------------------------
__global__ void transpose_src(const float* __restrict__ src, int which)
{
    __shared__ float t[32][33];
    int b = blockIdx.z;
    int pix0 = blockIdx.x * 32, ci0 = blockIdx.y * 32;
    const float* s = src + ((size_t)b * CIN + ci0) * HW + pix0;
    for (int i = threadIdx.y; i < 32; i += 8)
        t[i][threadIdx.x] = s[(size_t)i * HW + threadIdx.x];   // t[ci][pix]
    __syncthreads();
    __half* d = (which ? g_srcT1 : g_srcT0) + ((size_t)b * HW + pix0) * CIN + ci0;
    for (int i = threadIdx.y; i < 32; i += 8)
        d[(size_t)i * CIN + threadIdx.x] = __float2half_rn(t[threadIdx.x][i]);
}

// ---------------------------------------------------------------------------
// Pre-pass 2: weight reshuffle wT[co][k = r*1024+ci] = f16(w[co][ci][r])
// ---------------------------------------------------------------------------
__global__ void transpose_w(const float* __restrict__ wk,
                            const float* __restrict__ wv, int which)
{
    int idx = blockIdx.x * blockDim.x + threadIdx.x;
    if (idx >= MTOT * KTOT) return;
    int co = idx / KTOT;
    int k  = idx - co * KTOT;
    int ci = k & 1023;
    int r  = k >> 10;
    float v = (co < CK) ? wk[co * KTOT + ci * 9 + r]
                        : wv[(co - CK) * KTOT + ci * 9 + r];
    (which ? g_wT_s : g_wT_t)[idx] = __float2half_rn(v);
}

// ---------------------------------------------------------------------------
// Key transpose f16: [b][c][pix] -> [b][pix][c]
// ---------------------------------------------------------------------------
__global__ void transpose_kh(int which)
{
    __shared__ __half t[32][34];
    const __half* in = which ? g_qkh : g_mkh;
    __half* outp     = which ? g_qkT : g_mkT;
    int b = blockIdx.z;
    int pix0 = blockIdx.x * 32, c0 = blockIdx.y * 32;
    const __half* s = in + ((size_t)b * CK + c0) * HW + pix0;
    for (int i = threadIdx.y; i < 32; i += 8)
        t[i][threadIdx.x] = s[(size_t)i * HW + threadIdx.x];   // t[c][pix]
    __syncthreads();
    __half* d = outp + ((size_t)b * HW + pix0) * CK + c0;
    for (int i = threadIdx.y; i < 32; i += 8)
        d[(size_t)i * CK + threadIdx.x] = t[threadIdx.x][i];
}

// ---------------------------------------------------------------------------
// FP16 tensor-core implicit-GEMM conv (both branches in one launch).
// grid (64, 12): y<6 -> temp branch, y>=6 -> search branch; co0 = (y%6)*128.
// keys -> g_mkh/g_qkh (f16), m_value -> g_mvh (f16), q_value -> d_out (f32).
// ---------------------------------------------------------------------------
__global__ __launch_bounds__(256, 1)
void conv_mma(const float* __restrict__ bk_m, const float* __restrict__ bv_m,
              const float* __restrict__ bk_q, const float* __restrict__ bv_q,
              float* __restrict__ out)
{
    extern __shared__ char sm[];
    const int which = (blockIdx.y >= 6);
    const __half* __restrict__ wT   = which ? g_wT_s : g_wT_t;
    const __half* __restrict__ srcT = which ? g_srcT1 : g_srcT0;
    const float* __restrict__ bias_k = which ? bk_q : bk_m;
    const float* __restrict__ bias_v = which ? bv_q : bv_m;

    const int tid  = threadIdx.x;
    const int warp = tid >> 5, lane = tid & 31;
    const int grp  = lane >> 2, tig = lane & 3;
    const int wm   = (warp >> 2) * 64;
    const int wn   = (warp & 3) * 64;

    const int npix0 = blockIdx.x * BN;
    const int co0   = (blockIdx.y % 6) * BM;
    const int b     = npix0 >> 10;
    const int pix0  = npix0 & 1023;
    const __half* srcTb = srcT + (size_t)b * (HW * CIN);

    const uint32_t smem_u = (uint32_t)__cvta_generic_to_shared(sm);
    const int bp = pix0 + tid;
    const int by = bp >> 5, bx = bp & 31;

    float acc[4][8][4];
#pragma unroll
    for (int mt = 0; mt < 4; ++mt)
#pragma unroll
        for (int nt = 0; nt < 8; ++nt)
#pragma unroll
            for (int c = 0; c < 4; ++c) acc[mt][nt][c] = 0.f;

    auto issue = [&](int kt, int buf) {
        const int r   = kt >> 5;
        const int ci0 = (kt & 31) << 5;
        const uint32_t sA = smem_u + (uint32_t)buf * STAGE_BYTES;
        const uint32_t sB = sA + A_BYTES;
        const __half* abase = wT + (size_t)co0 * KTOT + kt * 32;
#pragma unroll
        for (int j = 0; j < 2; ++j) {
            int c = tid * 2 + j;
            int m = c >> 2, q = c & 3;
            cp_async16z(sA + (uint32_t)(m * (LDH * 2) + q * 16),
                        abase + (size_t)m * KTOT + q * 8, 16);
        }
        const int dy = r / 3 - 1, dx = r % 3 - 1;
        const int iy = by + dy, ix = bx + dx;
        const bool ok = ((unsigned)iy < 32u) && ((unsigned)ix < 32u);
        const __half* g = srcTb + (size_t)(ok ? (iy * 32 + ix) : 0) * CIN + ci0;
        const int sz = ok ? 16 : 0;
        const uint32_t rb = (uint32_t)tid * (LDH * 2);
#pragma unroll
        for (int j = 0; j < 4; ++j)
            cp_async16z(sB + rb + j * 16, g + j * 8, sz);
    };

    issue(0, 0); cp_commit();
    issue(1, 1); cp_commit();

    int buf = 0;
    for (int kt = 0; kt < KITERS_CONV; ++kt) {
        cp_wait1();
        __syncthreads();
        if (kt + 2 < KITERS_CONV) issue(kt + 2, (buf + 2) % 3);
        cp_commit();

        const __half* As = reinterpret_cast<const __half*>(sm + buf * STAGE_BYTES);
        const __half* Bs = reinterpret_cast<const __half*>(sm + buf * STAGE_BYTES + A_BYTES);

#pragma unroll
        for (int s = 0; s < 2; ++s) {
            const int k16 = s * 16;
            uint32_t a[4][4], bf[8][2];
#pragma unroll
            for (int mt = 0; mt < 4; ++mt) {
                int row = wm + mt * 16 + grp;
                a[mt][0] = *reinterpret_cast<const uint32_t*>(&As[row * LDH + k16 + 2 * tig]);
                a[mt][1] = *reinterpret_cast<const uint32_t*>(&As[(row + 8) * LDH + k16 + 2 * tig]);
                a[mt][2] = *reinterpret_cast<const uint32_t*>(&As[row * LDH + k16 + 2 * tig + 8]);
                a[mt][3] = *reinterpret_cast<const uint32_t*>(&As[(row + 8) * LDH + k16 + 2 * tig + 8]);
            }
#pragma unroll
            for (int nt = 0; nt < 8; ++nt) {
                int col = wn + nt * 8 + grp;
                bf[nt][0] = *reinterpret_cast<const uint32_t*>(&Bs[col * LDH + k16 + 2 * tig]);
                bf[nt][1] = *reinterpret_cast<const uint32_t*>(&Bs[col * LDH + k16 + 2 * tig + 8]);
            }
#pragma unroll
            for (int mt = 0; mt < 4; ++mt)
#pragma unroll
                for (int nt = 0; nt < 8; ++nt)
                    MMA_F16(acc[mt][nt], a[mt], bf[nt]);
        }
        buf = (buf + 1) % 3;
    }

    // ---- epilogue ---------------------------------------------------------
    const bool is_key = (co0 < CK);
#pragma unroll
    for (int mt = 0; mt < 4; ++mt) {
        int r0 = co0 + wm + mt * 16 + grp;
        int r1 = r0 + 8;
        if (is_key) {
            float bia0 = bias_k[r0], bia1 = bias_k[r1];
            __half* base = (which ? g_qkh : g_mkh) + (size_t)b * (CK * HW);
            __half* d0 = base + (size_t)r0 * HW;
            __half* d1 = base + (size_t)r1 * HW;
#pragma unroll
            for (int nt = 0; nt < 8; ++nt) {
                int col = pix0 + wn + nt * 8 + 2 * tig;
                *reinterpret_cast<__half2*>(&d0[col]) =
                    __floats2half2_rn(acc[mt][nt][0] + bia0, acc[mt][nt][1] + bia0);
                *reinterpret_cast<__half2*>(&d1[col]) =
                    __floats2half2_rn(acc[mt][nt][2] + bia1, acc[mt][nt][3] + bia1);
            }
        } else {
            int c0v = r0 - CK, c1v = r1 - CK;
            float bia0 = bias_v[c0v], bia1 = bias_v[c1v];
            if (which) {   // q_value -> d_out channels [512,1024), f32
                float* base = out + (size_t)b * (2 * CV * HW) + (size_t)CV * HW;
                float* d0 = base + (size_t)c0v * HW;
                float* d1 = base + (size_t)c1v * HW;
#pragma unroll
                for (int nt = 0; nt < 8; ++nt) {
                    int col = pix0 + wn + nt * 8 + 2 * tig;
                    *reinterpret_cast<float2*>(&d0[col]) =
                        make_float2(acc[mt][nt][0] + bia0, acc[mt][nt][1] + bia0);
                    *reinterpret_cast<float2*>(&d1[col]) =
                        make_float2(acc[mt][nt][2] + bia1, acc[mt][nt][3] + bia1);
                }
            } else {       // m_value -> g_mvh f16
                __half* base = g_mvh + (size_t)b * (CV * HW);
                __half* d0 = base + (size_t)c0v * HW;
                __half* d1 = base + (size_t)c1v * HW;
#pragma unroll
                for (int nt = 0; nt < 8; ++nt) {
                    int col = pix0 + wn + nt * 8 + 2 * tig;
                    *reinterpret_cast<__half2*>(&d0[col]) =
                        __floats2half2_rn(acc[mt][nt][0] + bia0, acc[mt][nt][1] + bia0);
                    *reinterpret_cast<__half2*>(&d1[col]) =
                        __floats2half2_rn(acc[mt][nt][2] + bia1, acc[mt][nt][3] + bia1);
                }
            }
        }
    }
}

// ---------------------------------------------------------------------------
// Scores (f16 mma): S[b][q][m] = (1/16) * sum_c qkT[b][q][c] * mkT[b][m][c]
// grid (64, 8): x -> (b, m0 = (x&3)*256), y -> q0 = y*128. K = 256.
// ---------------------------------------------------------------------------
__global__ __launch_bounds__(256, 1)
void scores_tc()
{
    extern __shared__ char sm[];
    const int tid  = threadIdx.x;
    const int warp = tid >> 5, lane = tid & 31;
    const int grp  = lane >> 2, tig = lane & 3;
    const int wm   = (warp >> 2) * 64;
    const int wn   = (warp & 3) * 64;

    const int b  = blockIdx.x >> 2;
    const int m0 = (blockIdx.x & 3) * BN;
    const int q0 = blockIdx.y * BM;
    const __half* qkT = g_qkT + (size_t)b * (HW * CK);
    const __half* mkT = g_mkT + (size_t)b * (HW * CK);

    const uint32_t smem_u = (uint32_t)__cvta_generic_to_shared(sm);

    float acc[4][8][4];
#pragma unroll
    for (int mt = 0; mt < 4; ++mt)
#pragma unroll
        for (int nt = 0; nt < 8; ++nt)
#pragma unroll
            for (int c = 0; c < 4; ++c) acc[mt][nt][c] = 0.f;

    auto issue = [&](int kt, int buf) {
        const uint32_t sA = smem_u + (uint32_t)buf * STAGE_BYTES;
        const uint32_t sB = sA + A_BYTES;
        const __half* abase = qkT + (size_t)q0 * CK + kt * 32;
#pragma unroll
        for (int j = 0; j < 2; ++j) {
            int c = tid * 2 + j;
            int m = c >> 2, q = c & 3;
            cp_async16z(sA + (uint32_t)(m * (LDH * 2) + q * 16),
                        abase + (size_t)m * CK + q * 8, 16);
        }
        const __half* bbase = mkT + (size_t)(m0 + tid) * CK + kt * 32;
        const uint32_t rb = (uint32_t)tid * (LDH * 2);
#pragma unroll
        for (int j = 0; j < 4; ++j)
            cp_async16z(sB + rb + j * 16, bbase + j * 8, 16);
    };

    issue(0, 0); cp_commit();
    issue(1, 1); cp_commit();

    int buf = 0;
    for (int kt = 0; kt < KITERS_SC; ++kt) {
        cp_wait1();
        __syncthreads();
        if (kt + 2 < KITERS_SC) issue(kt + 2, (buf + 2) % 3);
        cp_commit();

        const __half* As = reinterpret_cast<const __half*>(sm + buf * STAGE_BYTES);
        const __half* Bs = reinterpret_cast<const __half*>(sm + buf * STAGE_BYTES + A_BYTES);
#pragma unroll
        for (int s = 0; s < 2; ++s) {
            const int k16 = s * 16;
            uint32_t a[4][4], bf[8][2];
#pragma unroll
            for (int mt = 0; mt < 4; ++mt) {
                int row = wm + mt * 16 + grp;
                a[mt][0] = *reinterpret_cast<const uint32_t*>(&As[row * LDH + k16 + 2 * tig]);
                a[mt][1] = *reinterpret_cast<const uint32_t*>(&As[(row + 8) * LDH + k16 + 2 * tig]);
                a[mt][2] = *reinterpret_cast<const uint32_t*>(&As[row * LDH + k16 + 2 * tig + 8]);
                a[mt][3] = *reinterpret_cast<const uint32_t*>(&As[(row + 8) * LDH + k16 + 2 * tig + 8]);
            }
#pragma unroll
            for (int nt = 0; nt < 8; ++nt) {
                int col = wn + nt * 8 + grp;
                bf[nt][0] = *reinterpret_cast<const uint32_t*>(&Bs[col * LDH + k16 + 2 * tig]);
                bf[nt][1] = *reinterpret_cast<const uint32_t*>(&Bs[col * LDH + k16 + 2 * tig + 8]);
            }
#pragma unroll
            for (int mt = 0; mt < 4; ++mt)
#pragma unroll
                for (int nt = 0; nt < 8; ++nt)
                    MMA_F16(acc[mt][nt], a[mt], bf[nt]);
        }
        buf = (buf + 1) % 3;
    }

    const float scale = 0.0625f;   // 1/sqrt(256)
#pragma unroll
    for (int mt = 0; mt < 4; ++mt) {
        int r0 = q0 + wm + mt * 16 + grp;
        int r1 = r0 + 8;
        float* s0 = g_S + (size_t)b * (HW * HW) + (size_t)r0 * HW + m0;
        float* s1 = g_S + (size_t)b * (HW * HW) + (size_t)r1 * HW + m0;
#pragma unroll
        for (int nt = 0; nt < 8; ++nt) {
            int col = wn + nt * 8 + 2 * tig;
            *reinterpret_cast<float2*>(&s0[col]) =
                make_float2(acc[mt][nt][0] * scale, acc[mt][nt][1] * scale);
            *reinterpret_cast<float2*>(&s1[col]) =
                make_float2(acc[mt][nt][2] * scale, acc[mt][nt][3] * scale);
        }
    }
}

// ---------------------------------------------------------------------------
// Row softmax over m: E[b][q][:] = exp(S - rowmax) (f16), rsum = 1/rowsum.
// One warp per row; 8 rows per 256-thread block. grid = BB*HW/8 = 2048.
// ---------------------------------------------------------------------------
__global__ __launch_bounds__(256)
void softmax_row()
{
    const int warp = threadIdx.x >> 5, lane = threadIdx.x & 31;
    const int gid = blockIdx.x * 8 + warp;       // row over BB*HW
    const float4* s4 = reinterpret_cast<const float4*>(g_S + (size_t)gid * HW);

    float4 v[8];
    float mx = -3.402823e38f;
#pragma unroll
    for (int j = 0; j < 8; ++j) {
        v[j] = s4[j * 32 + lane];
        mx = fmaxf(mx, fmaxf(fmaxf(v[j].x, v[j].y), fmaxf(v[j].z, v[j].w)));
    }
#pragma unroll
    for (int o = 16; o > 0; o >>= 1)
        mx = fmaxf(mx, __shfl_xor_sync(0xFFFFFFFFu, mx, o));

    uint2* e2 = reinterpret_cast<uint2*>(g_E + (size_t)gid * HW);
    float sum = 0.f;
#pragma unroll
    for (int j = 0; j < 8; ++j) {
        float e0 = __expf(v[j].x - mx);
        float e1 = __expf(v[j].y - mx);
        float e2f = __expf(v[j].z - mx);
        float e3 = __expf(v[j].w - mx);
        sum += (e0 + e1) + (e2f + e3);
        __half2 h01 = __floats2half2_rn(e0, e1);
        __half2 h23 = __floats2half2_rn(e2f, e3);
        uint2 u;
        u.x = *reinterpret_cast<uint32_t*>(&h01);
        u.y = *reinterpret_cast<uint32_t*>(&h23);
        e2[j * 32 + lane] = u;
    }
#pragma unroll
    for (int o = 16; o > 0; o >>= 1)
        sum += __shfl_xor_sync(0xFFFFFFFFu, sum, o);
    if (lane == 0) g_rsum[gid] = 1.0f / sum;
}

// ---------------------------------------------------------------------------
// Readout (f16 mma): out[b][c][q] = (sum_m mvh[b][c][m] * E[b][q][m]) * rsum
// grid (64, 4): x -> (b, q0 = (x&3)*256), y -> c0 = y*128. K = 1024.
// ---------------------------------------------------------------------------
__global__ __launch_bounds__(256, 1)
void out_tc(float* __restrict__ out)
{
    extern __shared__ char sm[];
    const int tid  = threadIdx.x;
    const int warp = tid >> 5, lane = tid & 31;
    const int grp  = lane >> 2, tig = lane & 3;
    const int wm   = (warp >> 2) * 64;
    const int wn   = (warp & 3) * 64;

    const int b  = blockIdx.x >> 2;
    const int q0 = (blockIdx.x & 3) * BN;
    const int c0 = blockIdx.y * BM;
    const __half* mvh = g_mvh + (size_t)b * (CV * HW);
    const __half* E   = g_E   + (size_t)b * (HW * HW);

    const uint32_t smem_u = (uint32_t)__cvta_generic_to_shared(sm);

    float acc[4][8][4];
#pragma unroll
    for (int mt = 0; mt < 4; ++mt)
#pragma unroll
        for (int nt = 0; nt < 8; ++nt)
#pragma unroll
            for (int c = 0; c < 4; ++c) acc[mt][nt][c] = 0.f;

    auto issue = [&](int kt, int buf) {
        const uint32_t sA = smem_u + (uint32_t)buf * STAGE_BYTES;
        const uint32_t sB = sA + A_BYTES;
        const __half* abase = mvh + (size_t)c0 * HW + kt * 32;
#pragma unroll
        for (int j = 0; j < 2; ++j) {
            int c = tid * 2 + j;
            int m = c >> 2, q = c & 3;
            cp_async16z(sA + (uint32_t)(m * (LDH * 2) + q * 16),
                        abase + (size_t)m * HW + q * 8, 16);
        }
        const __half* bbase = E + (size_t)(q0 + tid) * HW + kt * 32;
        const uint32_t rb = (uint32_t)tid * (LDH * 2);
#pragma unroll
        for (int j = 0; j < 4; ++j)
            cp_async16z(sB + rb + j * 16, bbase + j * 8, 16);
    };

    issue(0, 0); cp_commit();
    issue(1, 1); cp_commit();

    int buf = 0;
    for (int kt = 0; kt < KITERS_OUT; ++kt) {
        cp_wait1();
        __syncthreads();
        if (kt + 2 < KITERS_OUT) issue(kt + 2, (buf + 2) % 3);
        cp_commit();

        const __half* As = reinterpret_cast<const __half*>(sm + buf * STAGE_BYTES);
        const __half* Bs = reinterpret_cast<const __half*>(sm + buf * STAGE_BYTES + A_BYTES);
#pragma unroll
        for (int s = 0; s < 2; ++s) {
            const int k16 = s * 16;
            uint32_t a[4][4], bf[8][2];
#pragma unroll
            for (int mt = 0; mt < 4; ++mt) {
                int row = wm + mt * 16 + grp;
                a[mt][0] = *reinterpret_cast<const uint32_t*>(&As[row * LDH + k16 + 2 * tig]);
                a[mt][1] = *reinterpret_cast<const uint32_t*>(&As[(row + 8) * LDH + k16 + 2 * tig]);
                a[mt][2] = *reinterpret_cast<const uint32_t*>(&As[row * LDH + k16 + 2 * tig + 8]);
                a[mt][3] = *reinterpret_cast<const uint32_t*>(&As[(row + 8) * LDH + k16 + 2 * tig + 8]);
            }
#pragma unroll
            for (int nt = 0; nt < 8; ++nt) {
                int col = wn + nt * 8 + grp;
                bf[nt][0] = *reinterpret_cast<const uint32_t*>(&Bs[col * LDH + k16 + 2 * tig]);
                bf[nt][1] = *reinterpret_cast<const uint32_t*>(&Bs[col * LDH + k16 + 2 * tig + 8]);
            }
#pragma unroll
            for (int mt = 0; mt < 4; ++mt)
#pragma unroll
                for (int nt = 0; nt < 8; ++nt)
                    MMA_F16(acc[mt][nt], a[mt], bf[nt]);
        }
        buf = (buf + 1) % 3;
    }

    const float* rs = g_rsum + (size_t)b * HW;
#pragma unroll
    for (int mt = 0; mt < 4; ++mt) {
        int r0 = c0 + wm + mt * 16 + grp;
        int r1 = r0 + 8;
        float* d0 = out + (size_t)b * (2 * CV * HW) + (size_t)r0 * HW;
        float* d1 = out + (size_t)b * (2 * CV * HW) + (size_t)r1 * HW;
#pragma unroll
        for (int nt = 0; nt < 8; ++nt) {
            int col = q0 + wn + nt * 8 + 2 * tig;
            float2 r2 = *reinterpret_cast<const float2*>(&rs[col]);
            *reinterpret_cast<float2*>(&d0[col]) =
                make_float2(acc[mt][nt][0] * r2.x, acc[mt][nt][1] * r2.y);
            *reinterpret_cast<float2*>(&d1[col]) =
                make_float2(acc[mt][nt][2] * r2.x, acc[mt][nt][3] * r2.y);
        }
    }
}

// ---------------------------------------------------------------------------
// Launch
// ---------------------------------------------------------------------------
extern "C" void kernel_launch(void* const* d_in, const int* in_sizes, int n_in,
                              void* d_out, int out_size)
{
    const float* src_t = (const float*)d_in[0];
    const float* src_s = (const float*)d_in[1];
    const float* wk_m  = (const float*)d_in[2];
    const float* bk_m  = (const float*)d_in[3];
    const float* wv_m  = (const float*)d_in[4];
    const float* bv_m  = (const float*)d_in[5];
    const float* wk_q  = (const float*)d_in[6];
    const float* bk_q  = (const float*)d_in[7];
    const float* wv_q  = (const float*)d_in[8];
    const float* bv_q  = (const float*)d_in[9];
    float* out = (float*)d_out;

    cudaFuncSetAttribute(conv_mma, cudaFuncAttributeMaxDynamicSharedMemorySize, SMEM_TOTAL);
    cudaFuncSetAttribute(scores_tc, cudaFuncAttributeMaxDynamicSharedMemorySize, SMEM_TOTAL);
    cudaFuncSetAttribute(out_tc, cudaFuncAttributeMaxDynamicSharedMemorySize, SMEM_TOTAL);

    // 0. transpose + f16 sources
    {
        dim3 grid(32, 32, BB);
        dim3 blk(32, 8);
        transpose_src<<<grid, blk>>>(src_t, 0);
        transpose_src<<<grid, blk>>>(src_s, 1);
    }
    // 1. weight reshuffle + f16 round
    {
        int n = MTOT * KTOT;
        transpose_w<<<(n + 255) / 256, 256>>>(wk_m, wv_m, 0);
        transpose_w<<<(n + 255) / 256, 256>>>(wk_q, wv_q, 1);
    }
    // 2. both convs in one launch
    {
        dim3 grid(64, 12);
        conv_mma<<<grid, 256, SMEM_TOTAL>>>(bk_m, bv_m, bk_q, bv_q, out);
    }
    // 3. key transposes -> [b][pix][c]
    {
        dim3 grid(32, 8, BB);
        dim3 blk(32, 8);
        transpose_kh<<<grid, blk>>>(0);
        transpose_kh<<<grid, blk>>>(1);
    }
    // 4. attention scores (tensor cores), S[b][q][m]
    {
        dim3 grid(64, 8);
        scores_tc<<<grid, 256, SMEM_TOTAL>>>();
    }
    // 5. row softmax -> E f16 + rsum
    {
        softmax_row<<<BB * HW / 8, 256>>>();
    }
    // 6. readout (tensor cores) -> out channels [0, 512)
    {
        dim3 grid(64, 4);
        out_tc<<<grid, 256, SMEM_TOTAL>>>(out);
    }
}

// round 11
// speedup vs baseline: 7.5407x; 1.8084x over previous
#include <cuda_runtime.h>
#include <cuda_fp16.h>
#include <cstdint>

// ---------------------------------------------------------------------------
// Problem constants
// ---------------------------------------------------------------------------
#define BB     16
#define CIN    1024
#define HW     1024      // 32*32
#define CK     256
#define CV     512
#define MTOT   768       // stacked key(256) + value(512) output channels
#define NTILE  4096      // BB * 256 winograd tiles

// shared f16 mma tiling
#define BM     128
#define BN     256
#define LDH    40        // smem pitch in halfs (80 B) -> conflict-free frags
#define A_BYTES (BM * LDH * 2)          // 10240
#define B_BYTES (BN * LDH * 2)          // 20480
#define STAGE_BYTES (A_BYTES + B_BYTES) // 30720
#define NSTAGE 3
#define SMEM_TOTAL (NSTAGE * STAGE_BYTES)   // 92160

#define KITERS_WG   32    // 1024 / 32
#define KITERS_SC   8     // 256 / 32
#define KITERS_OUT  32    // 1024 / 32

// ---------------------------------------------------------------------------
// Scratch (device globals; no allocation allowed). All accessed ONLY from
// device code (host passes `which` flags, never symbol addresses).
// ---------------------------------------------------------------------------
__device__ __half g_srcT0[BB * HW * CIN];    // f16 src_temp  [b][pix][ci]
__device__ __half g_srcT1[BB * HW * CIN];    // f16 src_search
__device__ __half g_U_t[16 * MTOT * CIN];    // winograd weights temp   [t][co][ci]
__device__ __half g_U_s[16 * MTOT * CIN];    // winograd weights search
__device__ __half g_V  [16 * NTILE * CIN];   // winograd input  [t][b*256+tile][ci]
__device__ float  g_M  [16 * MTOT * NTILE];  // gemm out [t][co][bt]
__device__ __half g_mkh[BB * CK * HW];       // m_key   [b][c][pix] f16
__device__ __half g_qkh[BB * CK * HW];       // q_key   [b][c][pix] f16
__device__ __half g_mkT[BB * HW * CK];       // m_key   [b][m][c]   f16
__device__ __half g_qkT[BB * HW * CK];       // q_key   [b][q][c]   f16
__device__ __half g_mvh[BB * CV * HW];       // m_value [b][c][m]   f16
__device__ float  g_S  [BB * HW * HW];       // scores  [b][q][m]   f32
__device__ __half g_E  [BB * HW * HW];       // exp     [b][q][m]   f16
__device__ float  g_rsum[BB * HW];           // 1 / row sum

// ---------------------------------------------------------------------------
// cp.async helpers
// ---------------------------------------------------------------------------
__device__ __forceinline__ void cp_async16z(uint32_t s, const void* g, int sz) {
    asm volatile("cp.async.cg.shared.global [%0], [%1], 16, %2;"
                 :: "r"(s), "l"(g), "r"(sz));
}
__device__ __forceinline__ void cp_commit() { asm volatile("cp.async.commit_group;"); }
__device__ __forceinline__ void cp_wait1()  { asm volatile("cp.async.wait_group 1;"); }

#define MMA_F16(acc, a, bf)                                                   \
    asm volatile(                                                             \
        "mma.sync.aligned.m16n8k16.row.col.f32.f16.f16.f32 "                  \
        "{%0,%1,%2,%3}, {%4,%5,%6,%7}, {%8,%9}, {%0,%1,%2,%3};"               \
        : "+f"((acc)[0]), "+f"((acc)[1]), "+f"((acc)[2]), "+f"((acc)[3])      \
        : "r"((a)[0]), "r"((a)[1]), "r"((a)[2]), "r"((a)[3]),                 \
          "r"((bf)[0]), "r"((bf)[1]))

// ---------------------------------------------------------------------------
// Pre-pass: transpose + f16 src: [b][ci][pix] -> [b][pix][ci]
// ---------------------------------------------------------------------------
__global__ void transpose_src(const float* __restrict__ src, int which)
{
    __shared__ float t[32][33];
    int b = blockIdx.z;
    int pix0 = blockIdx.x * 32, ci0 = blockIdx.y * 32;
    const float* s = src + ((size_t)b * CIN + ci0) * HW + pix0;
    for (int i = threadIdx.y; i < 32; i += 8)
        t[i][threadIdx.x] = s[(size_t)i * HW + threadIdx.x];   // t[ci][pix]
    __syncthreads();
    __half* d = (which ? g_srcT1 : g_srcT0) + ((size_t)b * HW + pix0) * CIN + ci0;
    for (int i = threadIdx.y; i < 32; i += 8)
        d[(size_t)i * CIN + threadIdx.x] = __float2half_rn(t[threadIdx.x][i]);
}

// ---------------------------------------------------------------------------
// Winograd weight transform: U = G g G^T per (co, ci).
// wk: [CK][CIN][9], wv: [CV][CIN][9] (co-stacked). Out: U[t][co][ci] f16.
// Destination selected INSIDE the kernel via `which`.
// ---------------------------------------------------------------------------
__global__ void wg_w(const float* __restrict__ wk,
                     const float* __restrict__ wv,
                     int which)
{
    __half* __restrict__ U = which ? g_U_s : g_U_t;
    int idx = blockIdx.x * blockDim.x + threadIdx.x;
    if (idx >= MTOT * CIN) return;
    int co = idx / CIN;
    int ci = idx - co * CIN;
    const float* g = (co < CK) ? (wk + ((size_t)co * CIN + ci) * 9)
                               : (wv + ((size_t)(co - CK) * CIN + ci) * 9);
    float gr[3][3];
#pragma unroll
    for (int r = 0; r < 9; ++r) gr[r / 3][r % 3] = g[r];
    float t[4][3];
#pragma unroll
    for (int j = 0; j < 3; ++j) {
        t[0][j] = gr[0][j];
        t[1][j] = 0.5f * (gr[0][j] + gr[1][j] + gr[2][j]);
        t[2][j] = 0.5f * (gr[0][j] - gr[1][j] + gr[2][j]);
        t[3][j] = gr[2][j];
    }
#pragma unroll
    for (int i = 0; i < 4; ++i) {
        float u0 = t[i][0];
        float u1 = 0.5f * (t[i][0] + t[i][1] + t[i][2]);
        float u2 = 0.5f * (t[i][0] - t[i][1] + t[i][2]);
        float u3 = t[i][2];
        U[((size_t)(i * 4 + 0) * MTOT + co) * CIN + ci] = __float2half_rn(u0);
        U[((size_t)(i * 4 + 1) * MTOT + co) * CIN + ci] = __float2half_rn(u1);
        U[((size_t)(i * 4 + 2) * MTOT + co) * CIN + ci] = __float2half_rn(u2);
        U[((size_t)(i * 4 + 3) * MTOT + co) * CIN + ci] = __float2half_rn(u3);
    }
}

// ---------------------------------------------------------------------------
// Winograd input transform: V = B^T d B per (b, tile, ci).
// Source selected INSIDE the kernel via `which`. Zero-pad halo.
// grid (256 tiles, BB), block 256; each thread handles 2 ci x 2 passes.
// ---------------------------------------------------------------------------
__global__ __launch_bounds__(256)
void wg_d(int which)
{
    const __half* __restrict__ srcT = which ? g_srcT1 : g_srcT0;
    const int tile = blockIdx.x;
    const int b    = blockIdx.y;
    const int ty = tile >> 4, tx = tile & 15;
    const int oy = 2 * ty, ox = 2 * tx;
    const int bt = b * 256 + tile;
    const __half* sb = srcT + (size_t)b * (HW * CIN);

#pragma unroll
    for (int pass = 0; pass < 2; ++pass) {
        int ci = (threadIdx.x + pass * 256) * 2;
        float2 d[4][4];
#pragma unroll
        for (int i = 0; i < 4; ++i) {
            int iy = oy - 1 + i;
#pragma unroll
            for (int j = 0; j < 4; ++j) {
                int ix = ox - 1 + j;
                if ((unsigned)iy < 32u && (unsigned)ix < 32u) {
                    __half2 h = *reinterpret_cast<const __half2*>(
                        &sb[(size_t)(iy * 32 + ix) * CIN + ci]);
                    d[i][j] = __half22float2(h);
                } else {
                    d[i][j] = make_float2(0.f, 0.f);
                }
            }
        }
        float2 r[4][4];
#pragma unroll
        for (int j = 0; j < 4; ++j) {
            r[0][j] = make_float2(d[0][j].x - d[2][j].x, d[0][j].y - d[2][j].y);
            r[1][j] = make_float2(d[1][j].x + d[2][j].x, d[1][j].y + d[2][j].y);
            r[2][j] = make_float2(d[2][j].x - d[1][j].x, d[2][j].y - d[1][j].y);
            r[3][j] = make_float2(d[1][j].x - d[3][j].x, d[1][j].y - d[3][j].y);
        }
#pragma unroll
        for (int i = 0; i < 4; ++i) {
            float2 v[4];
            v[0] = make_float2(r[i][0].x - r[i][2].x, r[i][0].y - r[i][2].y);
            v[1] = make_float2(r[i][1].x + r[i][2].x, r[i][1].y + r[i][2].y);
            v[2] = make_float2(r[i][2].x - r[i][1].x, r[i][2].y - r[i][1].y);
            v[3] = make_float2(r[i][1].x - r[i][3].x, r[i][1].y - r[i][3].y);
#pragma unroll
            for (int j = 0; j < 4; ++j) {
                *reinterpret_cast<__half2*>(
                    &g_V[((size_t)(i * 4 + j) * NTILE + bt) * CIN + ci]) =
                    __floats2half2_rn(v[j].x, v[j].y);
            }
        }
    }
}

// ---------------------------------------------------------------------------
// Winograd GEMM: M[t][co][n] = sum_ci U[t][co][ci] * V[t][n][ci], f16 mma.
// grid (16 n-tiles, 6 co-tiles, 16 t). K = 1024. U selected via `which`.
// ---------------------------------------------------------------------------
__global__ __launch_bounds__(256, 1)
void wg_gemm(int which)
{
    extern __shared__ char sm[];
    const __half* __restrict__ U = which ? g_U_s : g_U_t;
    const int tid  = threadIdx.x;
    const int warp = tid >> 5, lane = tid & 31;
    const int grp  = lane >> 2, tig = lane & 3;
    const int wm   = (warp >> 2) * 64;
    const int wn   = (warp & 3) * 64;

    const int n0  = blockIdx.x * BN;
    const int co0 = blockIdx.y * BM;
    const int t   = blockIdx.z;
    const __half* Ut = U   + (size_t)t * MTOT * CIN;
    const __half* Vt = g_V + (size_t)t * NTILE * CIN;

    const uint32_t smem_u = (uint32_t)__cvta_generic_to_shared(sm);

    float acc[4][8][4];
#pragma unroll
    for (int mt = 0; mt < 4; ++mt)
#pragma unroll
        for (int nt = 0; nt < 8; ++nt)
#pragma unroll
            for (int c = 0; c < 4; ++c) acc[mt][nt][c] = 0.f;

    auto issue = [&](int kt, int buf) {
        const uint32_t sA = smem_u + (uint32_t)buf * STAGE_BYTES;
        const uint32_t sB = sA + A_BYTES;
        const __half* abase = Ut + (size_t)co0 * CIN + kt * 32;
#pragma unroll
        for (int j = 0; j < 2; ++j) {
            int c = tid * 2 + j;
            int m = c >> 2, q = c & 3;
            cp_async16z(sA + (uint32_t)(m * (LDH * 2) + q * 16),
                        abase + (size_t)m * CIN + q * 8, 16);
        }
        const __half* bbase = Vt + (size_t)(n0 + tid) * CIN + kt * 32;
        const uint32_t rb = (uint32_t)tid * (LDH * 2);
#pragma unroll
        for (int j = 0; j < 4; ++j)
            cp_async16z(sB + rb + j * 16, bbase + j * 8, 16);
    };

    issue(0, 0); cp_commit();
    issue(1, 1); cp_commit();

    int buf = 0;
    for (int kt = 0; kt < KITERS_WG; ++kt) {
        cp_wait1();
        __syncthreads();
        if (kt + 2 < KITERS_WG) issue(kt + 2, (buf + 2) % 3);
        cp_commit();

        const __half* As = reinterpret_cast<const __half*>(sm + buf * STAGE_BYTES);
        const __half* Bs = reinterpret_cast<const __half*>(sm + buf * STAGE_BYTES + A_BYTES);
#pragma unroll
        for (int s = 0; s < 2; ++s) {
            const int k16 = s * 16;
            uint32_t a[4][4], bf[8][2];
#pragma unroll
            for (int mt = 0; mt < 4; ++mt) {
                int row = wm + mt * 16 + grp;
                a[mt][0] = *reinterpret_cast<const uint32_t*>(&As[row * LDH + k16 + 2 * tig]);
                a[mt][1] = *reinterpret_cast<const uint32_t*>(&As[(row + 8) * LDH + k16 + 2 * tig]);
                a[mt][2] = *reinterpret_cast<const uint32_t*>(&As[row * LDH + k16 + 2 * tig + 8]);
                a[mt][3] = *reinterpret_cast<const uint32_t*>(&As[(row + 8) * LDH + k16 + 2 * tig + 8]);
            }
#pragma unroll
            for (int nt = 0; nt < 8; ++nt) {
                int col = wn + nt * 8 + grp;
                bf[nt][0] = *reinterpret_cast<const uint32_t*>(&Bs[col * LDH + k16 + 2 * tig]);
                bf[nt][1] = *reinterpret_cast<const uint32_t*>(&Bs[col * LDH + k16 + 2 * tig + 8]);
            }
#pragma unroll
            for (int mt = 0; mt < 4; ++mt)
#pragma unroll
                for (int nt = 0; nt < 8; ++nt)
                    MMA_F16(acc[mt][nt], a[mt], bf[nt]);
        }
        buf = (buf + 1) % 3;
    }

#pragma unroll
    for (int mt = 0; mt < 4; ++mt) {
        int r0 = co0 + wm + mt * 16 + grp;
        int r1 = r0 + 8;
        float* d0 = g_M + ((size_t)t * MTOT + r0) * NTILE + n0;
        float* d1 = g_M + ((size_t)t * MTOT + r1) * NTILE + n0;
#pragma unroll
        for (int nt = 0; nt < 8; ++nt) {
            int col = wn + nt * 8 + 2 * tig;
            *reinterpret_cast<float2*>(&d0[col]) =
                make_float2(acc[mt][nt][0], acc[mt][nt][1]);
            *reinterpret_cast<float2*>(&d1[col]) =
                make_float2(acc[mt][nt][2], acc[mt][nt][3]);
        }
    }
}

// ---------------------------------------------------------------------------
// Winograd output transform: Y = A^T m A (+bias), scatter to destinations.
// grid (16, 768), block 256: bt = bx*256+tid, co = by.
// which==0: keys->g_mkh, values->g_mvh (f16).
// which==1: keys->g_qkh (f16), values->d_out[512..] (f32).
// ---------------------------------------------------------------------------
__global__ __launch_bounds__(256)
void wg_out(const float* __restrict__ bias_k,
            const float* __restrict__ bias_v,
            float* __restrict__ out, int which)
{
    const int bt = blockIdx.x * 256 + threadIdx.x;
    const int co = blockIdx.y;
    const int b    = bt >> 8;
    const int tile = bt & 255;
    const int ty = tile >> 4, tx = tile & 15;
    const int pix = (2 * ty) * 32 + 2 * tx;

    float m[4][4];
#pragma unroll
    for (int i = 0; i < 4; ++i)
#pragma unroll
        for (int j = 0; j < 4; ++j)
            m[i][j] = g_M[((size_t)(i * 4 + j) * MTOT + co) * NTILE + bt];

    float s0[4], s1[4];
#pragma unroll
    for (int j = 0; j < 4; ++j) {
        s0[j] = m[0][j] + m[1][j] + m[2][j];
        s1[j] = m[1][j] - m[2][j] - m[3][j];
    }
    float y00 = s0[0] + s0[1] + s0[2];
    float y01 = s0[1] - s0[2] - s0[3];
    float y10 = s1[0] + s1[1] + s1[2];
    float y11 = s1[1] - s1[2] - s1[3];

    if (co < CK) {
        float bia = bias_k[co];
        __half* d = (which ? g_qkh : g_mkh) + ((size_t)b * CK + co) * HW;
        *reinterpret_cast<__half2*>(&d[pix])      = __floats2half2_rn(y00 + bia, y01 + bia);
        *reinterpret_cast<__half2*>(&d[pix + 32]) = __floats2half2_rn(y10 + bia, y11 + bia);
    } else {
        int cv = co - CK;
        float bia = bias_v[cv];
        if (which) {
            float* d = out + (size_t)b * (2 * CV * HW) + (size_t)(CV + cv) * HW;
            *reinterpret_cast<float2*>(&d[pix])      = make_float2(y00 + bia, y01 + bia);
            *reinterpret_cast<float2*>(&d[pix + 32]) = make_float2(y10 + bia, y11 + bia);
        } else {
            __half* d = g_mvh + ((size_t)b * CV + cv) * HW;
            *reinterpret_cast<__half2*>(&d[pix])      = __floats2half2_rn(y00 + bia, y01 + bia);
            *reinterpret_cast<__half2*>(&d[pix + 32]) = __floats2half2_rn(y10 + bia, y11 + bia);
        }
    }
}

// ---------------------------------------------------------------------------
// Key transpose f16: [b][c][pix] -> [b][pix][c]
// ---------------------------------------------------------------------------
__global__ void transpose_kh(int which)
{
    __shared__ __half t[32][34];
    const __half* in = which ? g_qkh : g_mkh;
    __half* outp     = which ? g_qkT : g_mkT;
    int b = blockIdx.z;
    int pix0 = blockIdx.x * 32, c0 = blockIdx.y * 32;
    const __half* s = in + ((size_t)b * CK + c0) * HW + pix0;
    for (int i = threadIdx.y; i < 32; i += 8)
        t[i][threadIdx.x] = s[(size_t)i * HW + threadIdx.x];   // t[c][pix]
    __syncthreads();
    __half* d = outp + ((size_t)b * HW + pix0) * CK + c0;
    for (int i = threadIdx.y; i < 32; i += 8)
        d[(size_t)i * CK + threadIdx.x] = t[threadIdx.x][i];
}

// ---------------------------------------------------------------------------
// Scores (f16 mma): S[b][q][m] = (1/16) * sum_c qkT[b][q][c] * mkT[b][m][c]
// ---------------------------------------------------------------------------
__global__ __launch_bounds__(256, 1)
void scores_tc()
{
    extern __shared__ char sm[];
    const int tid  = threadIdx.x;
    const int warp = tid >> 5, lane = tid & 31;
    const int grp  = lane >> 2, tig = lane & 3;
    const int wm   = (warp >> 2) * 64;
    const int wn   = (warp & 3) * 64;

    const int b  = blockIdx.x >> 2;
    const int m0 = (blockIdx.x & 3) * BN;
    const int q0 = blockIdx.y * BM;
    const __half* qkT = g_qkT + (size_t)b * (HW * CK);
    const __half* mkT = g_mkT + (size_t)b * (HW * CK);

    const uint32_t smem_u = (uint32_t)__cvta_generic_to_shared(sm);

    float acc[4][8][4];
#pragma unroll
    for (int mt = 0; mt < 4; ++mt)
#pragma unroll
        for (int nt = 0; nt < 8; ++nt)
#pragma unroll
            for (int c = 0; c < 4; ++c) acc[mt][nt][c] = 0.f;

    auto issue = [&](int kt, int buf) {
        const uint32_t sA = smem_u + (uint32_t)buf * STAGE_BYTES;
        const uint32_t sB = sA + A_BYTES;
        const __half* abase = qkT + (size_t)q0 * CK + kt * 32;
#pragma unroll
        for (int j = 0; j < 2; ++j) {
            int c = tid * 2 + j;
            int m = c >> 2, q = c & 3;
            cp_async16z(sA + (uint32_t)(m * (LDH * 2) + q * 16),
                        abase + (size_t)m * CK + q * 8, 16);
        }
        const __half* bbase = mkT + (size_t)(m0 + tid) * CK + kt * 32;
        const uint32_t rb = (uint32_t)tid * (LDH * 2);
#pragma unroll
        for (int j = 0; j < 4; ++j)
            cp_async16z(sB + rb + j * 16, bbase + j * 8, 16);
    };

    issue(0, 0); cp_commit();
    issue(1, 1); cp_commit();

    int buf = 0;
    for (int kt = 0; kt < KITERS_SC; ++kt) {
        cp_wait1();
        __syncthreads();
        if (kt + 2 < KITERS_SC) issue(kt + 2, (buf + 2) % 3);
        cp_commit();

        const __half* As = reinterpret_cast<const __half*>(sm + buf * STAGE_BYTES);
        const __half* Bs = reinterpret_cast<const __half*>(sm + buf * STAGE_BYTES + A_BYTES);
#pragma unroll
        for (int s = 0; s < 2; ++s) {
            const int k16 = s * 16;
            uint32_t a[4][4], bf[8][2];
#pragma unroll
            for (int mt = 0; mt < 4; ++mt) {
                int row = wm + mt * 16 + grp;
                a[mt][0] = *reinterpret_cast<const uint32_t*>(&As[row * LDH + k16 + 2 * tig]);
                a[mt][1] = *reinterpret_cast<const uint32_t*>(&As[(row + 8) * LDH + k16 + 2 * tig]);
                a[mt][2] = *reinterpret_cast<const uint32_t*>(&As[row * LDH + k16 + 2 * tig + 8]);
                a[mt][3] = *reinterpret_cast<const uint32_t*>(&As[(row + 8) * LDH + k16 + 2 * tig + 8]);
            }
#pragma unroll
            for (int nt = 0; nt < 8; ++nt) {
                int col = wn + nt * 8 + grp;
                bf[nt][0] = *reinterpret_cast<const uint32_t*>(&Bs[col * LDH + k16 + 2 * tig]);
                bf[nt][1] = *reinterpret_cast<const uint32_t*>(&Bs[col * LDH + k16 + 2 * tig + 8]);
            }
#pragma unroll
            for (int mt = 0; mt < 4; ++mt)
#pragma unroll
                for (int nt = 0; nt < 8; ++nt)
                    MMA_F16(acc[mt][nt], a[mt], bf[nt]);
        }
        buf = (buf + 1) % 3;
    }

    const float scale = 0.0625f;   // 1/sqrt(256)
#pragma unroll
    for (int mt = 0; mt < 4; ++mt) {
        int r0 = q0 + wm + mt * 16 + grp;
        int r1 = r0 + 8;
        float* s0 = g_S + (size_t)b * (HW * HW) + (size_t)r0 * HW + m0;
        float* s1 = g_S + (size_t)b * (HW * HW) + (size_t)r1 * HW + m0;
#pragma unroll
        for (int nt = 0; nt < 8; ++nt) {
            int col = wn + nt * 8 + 2 * tig;
            *reinterpret_cast<float2*>(&s0[col]) =
                make_float2(acc[mt][nt][0] * scale, acc[mt][nt][1] * scale);
            *reinterpret_cast<float2*>(&s1[col]) =
                make_float2(acc[mt][nt][2] * scale, acc[mt][nt][3] * scale);
        }
    }
}

// ---------------------------------------------------------------------------
// Row softmax over m: E = exp(S - rowmax) f16, rsum = 1/rowsum.
// ---------------------------------------------------------------------------
__global__ __launch_bounds__(256)
void softmax_row()
{
    const int warp = threadIdx.x >> 5, lane = threadIdx.x & 31;
    const int gid = blockIdx.x * 8 + warp;
    const float4* s4 = reinterpret_cast<const float4*>(g_S + (size_t)gid * HW);

    float4 v[8];
    float mx = -3.402823e38f;
#pragma unroll
    for (int j = 0; j < 8; ++j) {
        v[j] = s4[j * 32 + lane];
        mx = fmaxf(mx, fmaxf(fmaxf(v[j].x, v[j].y), fmaxf(v[j].z, v[j].w)));
    }
#pragma unroll
    for (int o = 16; o > 0; o >>= 1)
        mx = fmaxf(mx, __shfl_xor_sync(0xFFFFFFFFu, mx, o));

    uint2* e2 = reinterpret_cast<uint2*>(g_E + (size_t)gid * HW);
    float sum = 0.f;
#pragma unroll
    for (int j = 0; j < 8; ++j) {
        float e0 = __expf(v[j].x - mx);
        float e1 = __expf(v[j].y - mx);
        float e2f = __expf(v[j].z - mx);
        float e3 = __expf(v[j].w - mx);
        sum += (e0 + e1) + (e2f + e3);
        __half2 h01 = __floats2half2_rn(e0, e1);
        __half2 h23 = __floats2half2_rn(e2f, e3);
        uint2 u;
        u.x = *reinterpret_cast<uint32_t*>(&h01);
        u.y = *reinterpret_cast<uint32_t*>(&h23);
        e2[j * 32 + lane] = u;
    }
#pragma unroll
    for (int o = 16; o > 0; o >>= 1)
        sum += __shfl_xor_sync(0xFFFFFFFFu, sum, o);
    if (lane == 0) g_rsum[gid] = 1.0f / sum;
}

// ---------------------------------------------------------------------------
// Readout (f16 mma): out[b][c][q] = (sum_m mvh[b][c][m] * E[b][q][m]) * rsum
// ---------------------------------------------------------------------------
__global__ __launch_bounds__(256, 1)
void out_tc(float* __restrict__ out)
{
    extern __shared__ char sm[];
    const int tid  = threadIdx.x;
    const int warp = tid >> 5, lane = tid & 31;
    const int grp  = lane >> 2, tig = lane & 3;
    const int wm   = (warp >> 2) * 64;
    const int wn   = (warp & 3) * 64;

    const int b  = blockIdx.x >> 2;
    const int q0 = (blockIdx.x & 3) * BN;
    const int c0 = blockIdx.y * BM;
    const __half* mvh = g_mvh + (size_t)b * (CV * HW);
    const __half* E   = g_E   + (size_t)b * (HW * HW);

    const uint32_t smem_u = (uint32_t)__cvta_generic_to_shared(sm);

    float acc[4][8][4];
#pragma unroll
    for (int mt = 0; mt < 4; ++mt)
#pragma unroll
        for (int nt = 0; nt < 8; ++nt)
#pragma unroll
            for (int c = 0; c < 4; ++c) acc[mt][nt][c] = 0.f;

    auto issue = [&](int kt, int buf) {
        const uint32_t sA = smem_u + (uint32_t)buf * STAGE_BYTES;
        const uint32_t sB = sA + A_BYTES;
        const __half* abase = mvh + (size_t)c0 * HW + kt * 32;
#pragma unroll
        for (int j = 0; j < 2; ++j) {
            int c = tid * 2 + j;
            int m = c >> 2, q = c & 3;
            cp_async16z(sA + (uint32_t)(m * (LDH * 2) + q * 16),
                        abase + (size_t)m * HW + q * 8, 16);
        }
        const __half* bbase = E + (size_t)(q0 + tid) * HW + kt * 32;
        const uint32_t rb = (uint32_t)tid * (LDH * 2);
#pragma unroll
        for (int j = 0; j < 4; ++j)
            cp_async16z(sB + rb + j * 16, bbase + j * 8, 16);
    };

    issue(0, 0); cp_commit();
    issue(1, 1); cp_commit();

    int buf = 0;
    for (int kt = 0; kt < KITERS_OUT; ++kt) {
        cp_wait1();
        __syncthreads();
        if (kt + 2 < KITERS_OUT) issue(kt + 2, (buf + 2) % 3);
        cp_commit();

        const __half* As = reinterpret_cast<const __half*>(sm + buf * STAGE_BYTES);
        const __half* Bs = reinterpret_cast<const __half*>(sm + buf * STAGE_BYTES + A_BYTES);
#pragma unroll
        for (int s = 0; s < 2; ++s) {
            const int k16 = s * 16;
            uint32_t a[4][4], bf[8][2];
#pragma unroll
            for (int mt = 0; mt < 4; ++mt) {
                int row = wm + mt * 16 + grp;
                a[mt][0] = *reinterpret_cast<const uint32_t*>(&As[row * LDH + k16 + 2 * tig]);
                a[mt][1] = *reinterpret_cast<const uint32_t*>(&As[(row + 8) * LDH + k16 + 2 * tig]);
                a[mt][2] = *reinterpret_cast<const uint32_t*>(&As[row * LDH + k16 + 2 * tig + 8]);
                a[mt][3] = *reinterpret_cast<const uint32_t*>(&As[(row + 8) * LDH + k16 + 2 * tig + 8]);
            }
#pragma unroll
            for (int nt = 0; nt < 8; ++nt) {
                int col = wn + nt * 8 + grp;
                bf[nt][0] = *reinterpret_cast<const uint32_t*>(&Bs[col * LDH + k16 + 2 * tig]);
                bf[nt][1] = *reinterpret_cast<const uint32_t*>(&Bs[col * LDH + k16 + 2 * tig + 8]);
            }
#pragma unroll
            for (int mt = 0; mt < 4; ++mt)
#pragma unroll
                for (int nt = 0; nt < 8; ++nt)
                    MMA_F16(acc[mt][nt], a[mt], bf[nt]);
        }
        buf = (buf + 1) % 3;
    }

    const float* rs = g_rsum + (size_t)b * HW;
#pragma unroll
    for (int mt = 0; mt < 4; ++mt) {
        int r0 = c0 + wm + mt * 16 + grp;
        int r1 = r0 + 8;
        float* d0 = out + (size_t)b * (2 * CV * HW) + (size_t)r0 * HW;
        float* d1 = out + (size_t)b * (2 * CV * HW) + (size_t)r1 * HW;
#pragma unroll
        for (int nt = 0; nt < 8; ++nt) {
            int col = q0 + wn + nt * 8 + 2 * tig;
            float2 r2 = *reinterpret_cast<const float2*>(&rs[col]);
            *reinterpret_cast<float2*>(&d0[col]) =
                make_float2(acc[mt][nt][0] * r2.x, acc[mt][nt][1] * r2.y);
            *reinterpret_cast<float2*>(&d1[col]) =
                make_float2(acc[mt][nt][2] * r2.x, acc[mt][nt][3] * r2.y);
        }
    }
}

// ---------------------------------------------------------------------------
// Launch
// ---------------------------------------------------------------------------
extern "C" void kernel_launch(void* const* d_in, const int* in_sizes, int n_in,
                              void* d_out, int out_size)
{
    const float* src_t = (const float*)d_in[0];
    const float* src_s = (const float*)d_in[1];
    const float* wk_m  = (const float*)d_in[2];
    const float* bk_m  = (const float*)d_in[3];
    const float* wv_m  = (const float*)d_in[4];
    const float* bv_m  = (const float*)d_in[5];
    const float* wk_q  = (const float*)d_in[6];
    const float* bk_q  = (const float*)d_in[7];
    const float* wv_q  = (const float*)d_in[8];
    const float* bv_q  = (const float*)d_in[9];
    float* out = (float*)d_out;

    cudaFuncSetAttribute(wg_gemm,   cudaFuncAttributeMaxDynamicSharedMemorySize, SMEM_TOTAL);
    cudaFuncSetAttribute(scores_tc, cudaFuncAttributeMaxDynamicSharedMemorySize, SMEM_TOTAL);
    cudaFuncSetAttribute(out_tc,    cudaFuncAttributeMaxDynamicSharedMemorySize, SMEM_TOTAL);

    // 0. transpose + f16 sources
    {
        dim3 grid(32, 32, BB);
        dim3 blk(32, 8);
        transpose_src<<<grid, blk>>>(src_t, 0);
        transpose_src<<<grid, blk>>>(src_s, 1);
    }
    // 1. winograd weight transforms
    {
        int n = MTOT * CIN;
        wg_w<<<(n + 255) / 256, 256>>>(wk_m, wv_m, 0);
        wg_w<<<(n + 255) / 256, 256>>>(wk_q, wv_q, 1);
    }
    // 2. winograd conv, branch 0 (temp) then branch 1 (search); V/M reused
    {
        dim3 dgrid(256, BB);
        dim3 ggrid(16, 6, 16);
        dim3 ogrid(16, MTOT);

        wg_d<<<dgrid, 256>>>(0);
        wg_gemm<<<ggrid, 256, SMEM_TOTAL>>>(0);
        wg_out<<<ogrid, 256>>>(bk_m, bv_m, out, 0);

        wg_d<<<dgrid, 256>>>(1);
        wg_gemm<<<ggrid, 256, SMEM_TOTAL>>>(1);
        wg_out<<<ogrid, 256>>>(bk_q, bv_q, out, 1);
    }
    // 3. key transposes -> [b][pix][c]
    {
        dim3 grid(32, 8, BB);
        dim3 blk(32, 8);
        transpose_kh<<<grid, blk>>>(0);
        transpose_kh<<<grid, blk>>>(1);
    }
    // 4. attention scores, S[b][q][m]
    {
        dim3 grid(64, 8);
        scores_tc<<<grid, 256, SMEM_TOTAL>>>();
    }
    // 5. row softmax -> E f16 + rsum
    {
        softmax_row<<<BB * HW / 8, 256>>>();
    }
    // 6. readout -> out channels [0, 512)
    {
        dim3 grid(64, 4);
        out_tc<<<grid, 256, SMEM_TOTAL>>>(out);
    }
}

// round 12
// speedup vs baseline: 7.8970x; 1.0472x over previous
#include <cuda_runtime.h>
#include <cuda_fp16.h>
#include <cstdint>

// ---------------------------------------------------------------------------
// Problem constants
// ---------------------------------------------------------------------------
#define BB     16
#define CIN    1024
#define HW     1024      // 32*32
#define CK     256
#define CV     512
#define MTOT   768       // stacked key(256) + value(512) output channels
#define NTILE  4096      // BB * 256 winograd tiles

// shared f16 mma tiling
#define BM     128
#define BN     256
#define LDH    40        // smem pitch in halfs (80 B) -> conflict-free frags
#define A_BYTES (BM * LDH * 2)          // 10240
#define B_BYTES (BN * LDH * 2)          // 20480
#define STAGE_BYTES (A_BYTES + B_BYTES) // 30720
#define NSTAGE 3
#define SMEM_TOTAL (NSTAGE * STAGE_BYTES)   // 92160

#define KITERS_WG   32    // 1024 / 32
#define KITERS_SC   8     // 256 / 32
#define KITERS_OUT  32    // 1024 / 32

#define U_STRIDE  ((size_t)16 * MTOT * CIN)    // per-branch U halfs
#define V_STRIDE  ((size_t)16 * NTILE * CIN)   // per-branch V halfs
#define M_STRIDE  ((size_t)16 * MTOT * NTILE)  // per-branch M halfs

// ---------------------------------------------------------------------------
// Scratch (device globals; no allocation allowed). All accessed ONLY from
// device code (host passes `which` flags, never symbol addresses).
// ---------------------------------------------------------------------------
__device__ __half g_srcT0[BB * HW * CIN];    // f16 src_temp  [b][pix][ci]
__device__ __half g_srcT1[BB * HW * CIN];    // f16 src_search
__device__ __half g_U [2 * 16 * MTOT * CIN];   // winograd weights [br][t][co][ci]
__device__ __half g_V [2 * 16 * NTILE * CIN];  // winograd input  [br][t][bt][ci]
__device__ __half g_Mh[2 * 16 * MTOT * NTILE]; // gemm out [br][t][co][bt] f16
__device__ __half g_mkh[BB * CK * HW];       // m_key   [b][c][pix] f16
__device__ __half g_qkh[BB * CK * HW];       // q_key   [b][c][pix] f16
__device__ __half g_mkT[BB * HW * CK];       // m_key   [b][m][c]   f16
__device__ __half g_qkT[BB * HW * CK];       // q_key   [b][q][c]   f16
__device__ __half g_mvh[BB * CV * HW];       // m_value [b][c][m]   f16
__device__ float  g_S  [BB * HW * HW];       // scores  [b][q][m]   f32
__device__ __half g_E  [BB * HW * HW];       // exp     [b][q][m]   f16
__device__ float  g_rsum[BB * HW];           // 1 / row sum

// ---------------------------------------------------------------------------
// cp.async helpers
// ---------------------------------------------------------------------------
__device__ __forceinline__ void cp_async16z(uint32_t s, const void* g, int sz) {
    asm volatile("cp.async.cg.shared.global [%0], [%1], 16, %2;"
                 :: "r"(s), "l"(g), "r"(sz));
}
__device__ __forceinline__ void cp_commit() { asm volatile("cp.async.commit_group;"); }
__device__ __forceinline__ void cp_wait1()  { asm volatile("cp.async.wait_group 1;"); }

#define MMA_F16(acc, a, bf)                                                   \
    asm volatile(                                                             \
        "mma.sync.aligned.m16n8k16.row.col.f32.f16.f16.f32 "                  \
        "{%0,%1,%2,%3}, {%4,%5,%6,%7}, {%8,%9}, {%0,%1,%2,%3};"               \
        : "+f"((acc)[0]), "+f"((acc)[1]), "+f"((acc)[2]), "+f"((acc)[3])      \
        : "r"((a)[0]), "r"((a)[1]), "r"((a)[2]), "r"((a)[3]),                 \
          "r"((bf)[0]), "r"((bf)[1]))

// ---------------------------------------------------------------------------
// Pre-pass: transpose + f16 src, BOTH branches: [b][ci][pix] -> [b][pix][ci]
// grid (32, 32, 32): z = b + 16*which
// ---------------------------------------------------------------------------
__global__ void transpose_src(const float* __restrict__ s0,
                              const float* __restrict__ s1)
{
    __shared__ float t[32][33];
    int b = blockIdx.z & 15;
    int which = blockIdx.z >> 4;
    const float* src = which ? s1 : s0;
    int pix0 = blockIdx.x * 32, ci0 = blockIdx.y * 32;
    const float* s = src + ((size_t)b * CIN + ci0) * HW + pix0;
    for (int i = threadIdx.y; i < 32; i += 8)
        t[i][threadIdx.x] = s[(size_t)i * HW + threadIdx.x];   // t[ci][pix]
    __syncthreads();
    __half* d = (which ? g_srcT1 : g_srcT0) + ((size_t)b * HW + pix0) * CIN + ci0;
    for (int i = threadIdx.y; i < 32; i += 8)
        d[(size_t)i * CIN + threadIdx.x] = __float2half_rn(t[threadIdx.x][i]);
}

// ---------------------------------------------------------------------------
// Winograd weight transform, BOTH branches: U = G g G^T per (br, co, ci).
// ---------------------------------------------------------------------------
__global__ void wg_w(const float* __restrict__ wk_m, const float* __restrict__ wv_m,
                     const float* __restrict__ wk_q, const float* __restrict__ wv_q)
{
    int idx = blockIdx.x * blockDim.x + threadIdx.x;
    if (idx >= 2 * MTOT * CIN) return;
    int which = (idx >= MTOT * CIN);
    int r2 = idx - which * (MTOT * CIN);
    int co = r2 / CIN;
    int ci = r2 - co * CIN;
    const float* wk = which ? wk_q : wk_m;
    const float* wv = which ? wv_q : wv_m;
    __half* __restrict__ U = g_U + (size_t)which * U_STRIDE;

    const float* g = (co < CK) ? (wk + ((size_t)co * CIN + ci) * 9)
                               : (wv + ((size_t)(co - CK) * CIN + ci) * 9);
    float gr[3][3];
#pragma unroll
    for (int r = 0; r < 9; ++r) gr[r / 3][r % 3] = g[r];
    float t[4][3];
#pragma unroll
    for (int j = 0; j < 3; ++j) {
        t[0][j] = gr[0][j];
        t[1][j] = 0.5f * (gr[0][j] + gr[1][j] + gr[2][j]);
        t[2][j] = 0.5f * (gr[0][j] - gr[1][j] + gr[2][j]);
        t[3][j] = gr[2][j];
    }
#pragma unroll
    for (int i = 0; i < 4; ++i) {
        float u0 = t[i][0];
        float u1 = 0.5f * (t[i][0] + t[i][1] + t[i][2]);
        float u2 = 0.5f * (t[i][0] - t[i][1] + t[i][2]);
        float u3 = t[i][2];
        U[((size_t)(i * 4 + 0) * MTOT + co) * CIN + ci] = __float2half_rn(u0);
        U[((size_t)(i * 4 + 1) * MTOT + co) * CIN + ci] = __float2half_rn(u1);
        U[((size_t)(i * 4 + 2) * MTOT + co) * CIN + ci] = __float2half_rn(u2);
        U[((size_t)(i * 4 + 3) * MTOT + co) * CIN + ci] = __float2half_rn(u3);
    }
}

// ---------------------------------------------------------------------------
// Winograd input transform, BOTH branches: V = B^T d B per (br, b, tile, ci).
// grid (256 tiles, 32): y = b + 16*which. Zero-pad halo.
// ---------------------------------------------------------------------------
__global__ __launch_bounds__(256)
void wg_d()
{
    const int b     = blockIdx.y & 15;
    const int which = blockIdx.y >> 4;
    const __half* __restrict__ srcT = which ? g_srcT1 : g_srcT0;
    __half* __restrict__ V = g_V + (size_t)which * V_STRIDE;
    const int tile = blockIdx.x;
    const int ty = tile >> 4, tx = tile & 15;
    const int oy = 2 * ty, ox = 2 * tx;
    const int bt = b * 256 + tile;
    const __half* sb = srcT + (size_t)b * (HW * CIN);

#pragma unroll
    for (int pass = 0; pass < 2; ++pass) {
        int ci = (threadIdx.x + pass * 256) * 2;
        float2 d[4][4];
#pragma unroll
        for (int i = 0; i < 4; ++i) {
            int iy = oy - 1 + i;
#pragma unroll
            for (int j = 0; j < 4; ++j) {
                int ix = ox - 1 + j;
                if ((unsigned)iy < 32u && (unsigned)ix < 32u) {
                    __half2 h = *reinterpret_cast<const __half2*>(
                        &sb[(size_t)(iy * 32 + ix) * CIN + ci]);
                    d[i][j] = __half22float2(h);
                } else {
                    d[i][j] = make_float2(0.f, 0.f);
                }
            }
        }
        float2 r[4][4];
#pragma unroll
        for (int j = 0; j < 4; ++j) {
            r[0][j] = make_float2(d[0][j].x - d[2][j].x, d[0][j].y - d[2][j].y);
            r[1][j] = make_float2(d[1][j].x + d[2][j].x, d[1][j].y + d[2][j].y);
            r[2][j] = make_float2(d[2][j].x - d[1][j].x, d[2][j].y - d[1][j].y);
            r[3][j] = make_float2(d[1][j].x - d[3][j].x, d[1][j].y - d[3][j].y);
        }
#pragma unroll
        for (int i = 0; i < 4; ++i) {
            float2 v[4];
            v[0] = make_float2(r[i][0].x - r[i][2].x, r[i][0].y - r[i][2].y);
            v[1] = make_float2(r[i][1].x + r[i][2].x, r[i][1].y + r[i][2].y);
            v[2] = make_float2(r[i][2].x - r[i][1].x, r[i][2].y - r[i][1].y);
            v[3] = make_float2(r[i][1].x - r[i][3].x, r[i][1].y - r[i][3].y);
#pragma unroll
            for (int j = 0; j < 4; ++j) {
                *reinterpret_cast<__half2*>(
                    &V[((size_t)(i * 4 + j) * NTILE + bt) * CIN + ci]) =
                    __floats2half2_rn(v[j].x, v[j].y);
            }
        }
    }
}

// ---------------------------------------------------------------------------
// Winograd GEMM, BOTH branches: M[t][co][n] = sum_ci U[t][co][ci]*V[t][n][ci].
// grid (16 n-tiles, 12, 16 t): which = y/6, co0 = (y%6)*128. K = 1024.
// M stored f16.
// ---------------------------------------------------------------------------
__global__ __launch_bounds__(256, 1)
void wg_gemm()
{
    extern __shared__ char sm[];
    const int which = blockIdx.y / 6;
    const int tid  = threadIdx.x;
    const int warp = tid >> 5, lane = tid & 31;
    const int grp  = lane >> 2, tig = lane & 3;
    const int wm   = (warp >> 2) * 64;
    const int wn   = (warp & 3) * 64;

    const int n0  = blockIdx.x * BN;
    const int co0 = (blockIdx.y % 6) * BM;
    const int t   = blockIdx.z;
    const __half* Ut = g_U + (size_t)which * U_STRIDE + (size_t)t * MTOT * CIN;
    const __half* Vt = g_V + (size_t)which * V_STRIDE + (size_t)t * NTILE * CIN;
    __half* __restrict__ Mh = g_Mh + (size_t)which * M_STRIDE;

    const uint32_t smem_u = (uint32_t)__cvta_generic_to_shared(sm);

    float acc[4][8][4];
#pragma unroll
    for (int mt = 0; mt < 4; ++mt)
#pragma unroll
        for (int nt = 0; nt < 8; ++nt)
#pragma unroll
            for (int c = 0; c < 4; ++c) acc[mt][nt][c] = 0.f;

    auto issue = [&](int kt, int buf) {
        const uint32_t sA = smem_u + (uint32_t)buf * STAGE_BYTES;
        const uint32_t sB = sA + A_BYTES;
        const __half* abase = Ut + (size_t)co0 * CIN + kt * 32;
#pragma unroll
        for (int j = 0; j < 2; ++j) {
            int c = tid * 2 + j;
            int m = c >> 2, q = c & 3;
            cp_async16z(sA + (uint32_t)(m * (LDH * 2) + q * 16),
                        abase + (size_t)m * CIN + q * 8, 16);
        }
        const __half* bbase = Vt + (size_t)(n0 + tid) * CIN + kt * 32;
        const uint32_t rb = (uint32_t)tid * (LDH * 2);
#pragma unroll
        for (int j = 0; j < 4; ++j)
            cp_async16z(sB + rb + j * 16, bbase + j * 8, 16);
    };

    issue(0, 0); cp_commit();
    issue(1, 1); cp_commit();

    int buf = 0;
    for (int kt = 0; kt < KITERS_WG; ++kt) {
        cp_wait1();
        __syncthreads();
        if (kt + 2 < KITERS_WG) issue(kt + 2, (buf + 2) % 3);
        cp_commit();

        const __half* As = reinterpret_cast<const __half*>(sm + buf * STAGE_BYTES);
        const __half* Bs = reinterpret_cast<const __half*>(sm + buf * STAGE_BYTES + A_BYTES);
#pragma unroll
        for (int s = 0; s < 2; ++s) {
            const int k16 = s * 16;
            uint32_t a[4][4], bf[8][2];
#pragma unroll
            for (int mt = 0; mt < 4; ++mt) {
                int row = wm + mt * 16 + grp;
                a[mt][0] = *reinterpret_cast<const uint32_t*>(&As[row * LDH + k16 + 2 * tig]);
                a[mt][1] = *reinterpret_cast<const uint32_t*>(&As[(row + 8) * LDH + k16 + 2 * tig]);
                a[mt][2] = *reinterpret_cast<const uint32_t*>(&As[row * LDH + k16 + 2 * tig + 8]);
                a[mt][3] = *reinterpret_cast<const uint32_t*>(&As[(row + 8) * LDH + k16 + 2 * tig + 8]);
            }
#pragma unroll
            for (int nt = 0; nt < 8; ++nt) {
                int col = wn + nt * 8 + grp;
                bf[nt][0] = *reinterpret_cast<const uint32_t*>(&Bs[col * LDH + k16 + 2 * tig]);
                bf[nt][1] = *reinterpret_cast<const uint32_t*>(&Bs[col * LDH + k16 + 2 * tig + 8]);
            }
#pragma unroll
            for (int mt = 0; mt < 4; ++mt)
#pragma unroll
                for (int nt = 0; nt < 8; ++nt)
                    MMA_F16(acc[mt][nt], a[mt], bf[nt]);
        }
        buf = (buf + 1) % 3;
    }

#pragma unroll
    for (int mt = 0; mt < 4; ++mt) {
        int r0 = co0 + wm + mt * 16 + grp;
        int r1 = r0 + 8;
        __half* d0 = Mh + ((size_t)t * MTOT + r0) * NTILE + n0;
        __half* d1 = Mh + ((size_t)t * MTOT + r1) * NTILE + n0;
#pragma unroll
        for (int nt = 0; nt < 8; ++nt) {
            int col = wn + nt * 8 + 2 * tig;
            *reinterpret_cast<__half2*>(&d0[col]) =
                __floats2half2_rn(acc[mt][nt][0], acc[mt][nt][1]);
            *reinterpret_cast<__half2*>(&d1[col]) =
                __floats2half2_rn(acc[mt][nt][2], acc[mt][nt][3]);
        }
    }
}

// ---------------------------------------------------------------------------
// Winograd output transform, BOTH branches: Y = A^T m A (+bias), scatter.
// grid (32, 768): which = bx>>4, bt = (bx&15)*256+tid, co = by.
// which==0: keys->g_mkh, values->g_mvh (f16).
// which==1: keys->g_qkh (f16), values->d_out[512..] (f32).
// ---------------------------------------------------------------------------
__global__ __launch_bounds__(256)
void wg_out(const float* __restrict__ bk_m, const float* __restrict__ bv_m,
            const float* __restrict__ bk_q, const float* __restrict__ bv_q,
            float* __restrict__ out)
{
    const int which = blockIdx.x >> 4;
    const int bt = (blockIdx.x & 15) * 256 + threadIdx.x;
    const int co = blockIdx.y;
    const int b    = bt >> 8;
    const int tile = bt & 255;
    const int ty = tile >> 4, tx = tile & 15;
    const int pix = (2 * ty) * 32 + 2 * tx;
    const __half* Mh = g_Mh + (size_t)which * M_STRIDE;
    const float* bias_k = which ? bk_q : bk_m;
    const float* bias_v = which ? bv_q : bv_m;

    float m[4][4];
#pragma unroll
    for (int i = 0; i < 4; ++i)
#pragma unroll
        for (int j = 0; j < 4; ++j)
            m[i][j] = __half2float(Mh[((size_t)(i * 4 + j) * MTOT + co) * NTILE + bt]);

    float s0[4], s1[4];
#pragma unroll
    for (int j = 0; j < 4; ++j) {
        s0[j] = m[0][j] + m[1][j] + m[2][j];
        s1[j] = m[1][j] - m[2][j] - m[3][j];
    }
    float y00 = s0[0] + s0[1] + s0[2];
    float y01 = s0[1] - s0[2] - s0[3];
    float y10 = s1[0] + s1[1] + s1[2];
    float y11 = s1[1] - s1[2] - s1[3];

    if (co < CK) {
        float bia = bias_k[co];
        __half* d = (which ? g_qkh : g_mkh) + ((size_t)b * CK + co) * HW;
        *reinterpret_cast<__half2*>(&d[pix])      = __floats2half2_rn(y00 + bia, y01 + bia);
        *reinterpret_cast<__half2*>(&d[pix + 32]) = __floats2half2_rn(y10 + bia, y11 + bia);
    } else {
        int cv = co - CK;
        float bia = bias_v[cv];
        if (which) {
            float* d = out + (size_t)b * (2 * CV * HW) + (size_t)(CV + cv) * HW;
            *reinterpret_cast<float2*>(&d[pix])      = make_float2(y00 + bia, y01 + bia);
            *reinterpret_cast<float2*>(&d[pix + 32]) = make_float2(y10 + bia, y11 + bia);
        } else {
            __half* d = g_mvh + ((size_t)b * CV + cv) * HW;
            *reinterpret_cast<__half2*>(&d[pix])      = __floats2half2_rn(y00 + bia, y01 + bia);
            *reinterpret_cast<__half2*>(&d[pix + 32]) = __floats2half2_rn(y10 + bia, y11 + bia);
        }
    }
}

// ---------------------------------------------------------------------------
// Key transpose f16, BOTH branches: [b][c][pix] -> [b][pix][c]
// grid (32, 8, 32): z = b + 16*which
// ---------------------------------------------------------------------------
__global__ void transpose_kh()
{
    __shared__ __half t[32][34];
    int b = blockIdx.z & 15;
    int which = blockIdx.z >> 4;
    const __half* in = which ? g_qkh : g_mkh;
    __half* outp     = which ? g_qkT : g_mkT;
    int pix0 = blockIdx.x * 32, c0 = blockIdx.y * 32;
    const __half* s = in + ((size_t)b * CK + c0) * HW + pix0;
    for (int i = threadIdx.y; i < 32; i += 8)
        t[i][threadIdx.x] = s[(size_t)i * HW + threadIdx.x];   // t[c][pix]
    __syncthreads();
    __half* d = outp + ((size_t)b * HW + pix0) * CK + c0;
    for (int i = threadIdx.y; i < 32; i += 8)
        d[(size_t)i * CK + threadIdx.x] = t[threadIdx.x][i];
}

// ---------------------------------------------------------------------------
// Scores (f16 mma): S[b][q][m] = (1/16) * sum_c qkT[b][q][c] * mkT[b][m][c]
// ---------------------------------------------------------------------------
__global__ __launch_bounds__(256, 1)
void scores_tc()
{
    extern __shared__ char sm[];
    const int tid  = threadIdx.x;
    const int warp = tid >> 5, lane = tid & 31;
    const int grp  = lane >> 2, tig = lane & 3;
    const int wm   = (warp >> 2) * 64;
    const int wn   = (warp & 3) * 64;

    const int b  = blockIdx.x >> 2;
    const int m0 = (blockIdx.x & 3) * BN;
    const int q0 = blockIdx.y * BM;
    const __half* qkT = g_qkT + (size_t)b * (HW * CK);
    const __half* mkT = g_mkT + (size_t)b * (HW * CK);

    const uint32_t smem_u = (uint32_t)__cvta_generic_to_shared(sm);

    float acc[4][8][4];
#pragma unroll
    for (int mt = 0; mt < 4; ++mt)
#pragma unroll
        for (int nt = 0; nt < 8; ++nt)
#pragma unroll
            for (int c = 0; c < 4; ++c) acc[mt][nt][c] = 0.f;

    auto issue = [&](int kt, int buf) {
        const uint32_t sA = smem_u + (uint32_t)buf * STAGE_BYTES;
        const uint32_t sB = sA + A_BYTES;
        const __half* abase = qkT + (size_t)q0 * CK + kt * 32;
#pragma unroll
        for (int j = 0; j < 2; ++j) {
            int c = tid * 2 + j;
            int m = c >> 2, q = c & 3;
            cp_async16z(sA + (uint32_t)(m * (LDH * 2) + q * 16),
                        abase + (size_t)m * CK + q * 8, 16);
        }
        const __half* bbase = mkT + (size_t)(m0 + tid) * CK + kt * 32;
        const uint32_t rb = (uint32_t)tid * (LDH * 2);
#pragma unroll
        for (int j = 0; j < 4; ++j)
            cp_async16z(sB + rb + j * 16, bbase + j * 8, 16);
    };

    issue(0, 0); cp_commit();
    issue(1, 1); cp_commit();

    int buf = 0;
    for (int kt = 0; kt < KITERS_SC; ++kt) {
        cp_wait1();
        __syncthreads();
        if (kt + 2 < KITERS_SC) issue(kt + 2, (buf + 2) % 3);
        cp_commit();

        const __half* As = reinterpret_cast<const __half*>(sm + buf * STAGE_BYTES);
        const __half* Bs = reinterpret_cast<const __half*>(sm + buf * STAGE_BYTES + A_BYTES);
#pragma unroll
        for (int s = 0; s < 2; ++s) {
            const int k16 = s * 16;
            uint32_t a[4][4], bf[8][2];
#pragma unroll
            for (int mt = 0; mt < 4; ++mt) {
                int row = wm + mt * 16 + grp;
                a[mt][0] = *reinterpret_cast<const uint32_t*>(&As[row * LDH + k16 + 2 * tig]);
                a[mt][1] = *reinterpret_cast<const uint32_t*>(&As[(row + 8) * LDH + k16 + 2 * tig]);
                a[mt][2] = *reinterpret_cast<const uint32_t*>(&As[row * LDH + k16 + 2 * tig + 8]);
                a[mt][3] = *reinterpret_cast<const uint32_t*>(&As[(row + 8) * LDH + k16 + 2 * tig + 8]);
            }
#pragma unroll
            for (int nt = 0; nt < 8; ++nt) {
                int col = wn + nt * 8 + grp;
                bf[nt][0] = *reinterpret_cast<const uint32_t*>(&Bs[col * LDH + k16 + 2 * tig]);
                bf[nt][1] = *reinterpret_cast<const uint32_t*>(&Bs[col * LDH + k16 + 2 * tig + 8]);
            }
#pragma unroll
            for (int mt = 0; mt < 4; ++mt)
#pragma unroll
                for (int nt = 0; nt < 8; ++nt)
                    MMA_F16(acc[mt][nt], a[mt], bf[nt]);
        }
        buf = (buf + 1) % 3;
    }

    const float scale = 0.0625f;   // 1/sqrt(256)
#pragma unroll
    for (int mt = 0; mt < 4; ++mt) {
        int r0 = q0 + wm + mt * 16 + grp;
        int r1 = r0 + 8;
        float* s0 = g_S + (size_t)b * (HW * HW) + (size_t)r0 * HW + m0;
        float* s1 = g_S + (size_t)b * (HW * HW) + (size_t)r1 * HW + m0;
#pragma unroll
        for (int nt = 0; nt < 8; ++nt) {
            int col = wn + nt * 8 + 2 * tig;
            *reinterpret_cast<float2*>(&s0[col]) =
                make_float2(acc[mt][nt][0] * scale, acc[mt][nt][1] * scale);
            *reinterpret_cast<float2*>(&s1[col]) =
                make_float2(acc[mt][nt][2] * scale, acc[mt][nt][3] * scale);
        }
    }
}

// ---------------------------------------------------------------------------
// Row softmax over m: E = exp(S - rowmax) f16, rsum = 1/rowsum.
// ---------------------------------------------------------------------------
__global__ __launch_bounds__(256)
void softmax_row()
{
    const int warp = threadIdx.x >> 5, lane = threadIdx.x & 31;
    const int gid = blockIdx.x * 8 + warp;
    const float4* s4 = reinterpret_cast<const float4*>(g_S + (size_t)gid * HW);

    float4 v[8];
    float mx = -3.402823e38f;
#pragma unroll
    for (int j = 0; j < 8; ++j) {
        v[j] = s4[j * 32 + lane];
        mx = fmaxf(mx, fmaxf(fmaxf(v[j].x, v[j].y), fmaxf(v[j].z, v[j].w)));
    }
#pragma unroll
    for (int o = 16; o > 0; o >>= 1)
        mx = fmaxf(mx, __shfl_xor_sync(0xFFFFFFFFu, mx, o));

    uint2* e2 = reinterpret_cast<uint2*>(g_E + (size_t)gid * HW);
    float sum = 0.f;
#pragma unroll
    for (int j = 0; j < 8; ++j) {
        float e0 = __expf(v[j].x - mx);
        float e1 = __expf(v[j].y - mx);
        float e2f = __expf(v[j].z - mx);
        float e3 = __expf(v[j].w - mx);
        sum += (e0 + e1) + (e2f + e3);
        __half2 h01 = __floats2half2_rn(e0, e1);
        __half2 h23 = __floats2half2_rn(e2f, e3);
        uint2 u;
        u.x = *reinterpret_cast<uint32_t*>(&h01);
        u.y = *reinterpret_cast<uint32_t*>(&h23);
        e2[j * 32 + lane] = u;
    }
#pragma unroll
    for (int o = 16; o > 0; o >>= 1)
        sum += __shfl_xor_sync(0xFFFFFFFFu, sum, o);
    if (lane == 0) g_rsum[gid] = 1.0f / sum;
}

// ---------------------------------------------------------------------------
// Readout (f16 mma): out[b][c][q] = (sum_m mvh[b][c][m] * E[b][q][m]) * rsum
// ---------------------------------------------------------------------------
__global__ __launch_bounds__(256, 1)
void out_tc(float* __restrict__ out)
{
    extern __shared__ char sm[];
    const int tid  = threadIdx.x;
    const int warp = tid >> 5, lane = tid & 31;
    const int grp  = lane >> 2, tig = lane & 3;
    const int wm   = (warp >> 2) * 64;
    const int wn   = (warp & 3) * 64;

    const int b  = blockIdx.x >> 2;
    const int q0 = (blockIdx.x & 3) * BN;
    const int c0 = blockIdx.y * BM;
    const __half* mvh = g_mvh + (size_t)b * (CV * HW);
    const __half* E   = g_E   + (size_t)b * (HW * HW);

    const uint32_t smem_u = (uint32_t)__cvta_generic_to_shared(sm);

    float acc[4][8][4];
#pragma unroll
    for (int mt = 0; mt < 4; ++mt)
#pragma unroll
        for (int nt = 0; nt < 8; ++nt)
#pragma unroll
            for (int c = 0; c < 4; ++c) acc[mt][nt][c] = 0.f;

    auto issue = [&](int kt, int buf) {
        const uint32_t sA = smem_u + (uint32_t)buf * STAGE_BYTES;
        const uint32_t sB = sA + A_BYTES;
        const __half* abase = mvh + (size_t)c0 * HW + kt * 32;
#pragma unroll
        for (int j = 0; j < 2; ++j) {
            int c = tid * 2 + j;
            int m = c >> 2, q = c & 3;
            cp_async16z(sA + (uint32_t)(m * (LDH * 2) + q * 16),
                        abase + (size_t)m * HW + q * 8, 16);
        }
        const __half* bbase = E + (size_t)(q0 + tid) * HW + kt * 32;
        const uint32_t rb = (uint32_t)tid * (LDH * 2);
#pragma unroll
        for (int j = 0; j < 4; ++j)
            cp_async16z(sB + rb + j * 16, bbase + j * 8, 16);
    };

    issue(0, 0); cp_commit();
    issue(1, 1); cp_commit();

    int buf = 0;
    for (int kt = 0; kt < KITERS_OUT; ++kt) {
        cp_wait1();
        __syncthreads();
        if (kt + 2 < KITERS_OUT) issue(kt + 2, (buf + 2) % 3);
        cp_commit();

        const __half* As = reinterpret_cast<const __half*>(sm + buf * STAGE_BYTES);
        const __half* Bs = reinterpret_cast<const __half*>(sm + buf * STAGE_BYTES + A_BYTES);
#pragma unroll
        for (int s = 0; s < 2; ++s) {
            const int k16 = s * 16;
            uint32_t a[4][4], bf[8][2];
#pragma unroll
            for (int mt = 0; mt < 4; ++mt) {
                int row = wm + mt * 16 + grp;
                a[mt][0] = *reinterpret_cast<const uint32_t*>(&As[row * LDH + k16 + 2 * tig]);
                a[mt][1] = *reinterpret_cast<const uint32_t*>(&As[(row + 8) * LDH + k16 + 2 * tig]);
                a[mt][2] = *reinterpret_cast<const uint32_t*>(&As[row * LDH + k16 + 2 * tig + 8]);
                a[mt][3] = *reinterpret_cast<const uint32_t*>(&As[(row + 8) * LDH + k16 + 2 * tig + 8]);
            }
#pragma unroll
            for (int nt = 0; nt < 8; ++nt) {
                int col = wn + nt * 8 + grp;
                bf[nt][0] = *reinterpret_cast<const uint32_t*>(&Bs[col * LDH + k16 + 2 * tig]);
                bf[nt][1] = *reinterpret_cast<const uint32_t*>(&Bs[col * LDH + k16 + 2 * tig + 8]);
            }
#pragma unroll
            for (int mt = 0; mt < 4; ++mt)
#pragma unroll
                for (int nt = 0; nt < 8; ++nt)
                    MMA_F16(acc[mt][nt], a[mt], bf[nt]);
        }
        buf = (buf + 1) % 3;
    }

    const float* rs = g_rsum + (size_t)b * HW;
#pragma unroll
    for (int mt = 0; mt < 4; ++mt) {
        int r0 = c0 + wm + mt * 16 + grp;
        int r1 = r0 + 8;
        float* d0 = out + (size_t)b * (2 * CV * HW) + (size_t)r0 * HW;
        float* d1 = out + (size_t)b * (2 * CV * HW) + (size_t)r1 * HW;
#pragma unroll
        for (int nt = 0; nt < 8; ++nt) {
            int col = q0 + wn + nt * 8 + 2 * tig;
            float2 r2 = *reinterpret_cast<const float2*>(&rs[col]);
            *reinterpret_cast<float2*>(&d0[col]) =
                make_float2(acc[mt][nt][0] * r2.x, acc[mt][nt][1] * r2.y);
            *reinterpret_cast<float2*>(&d1[col]) =
                make_float2(acc[mt][nt][2] * r2.x, acc[mt][nt][3] * r2.y);
        }
    }
}

// ---------------------------------------------------------------------------
// Launch
// ---------------------------------------------------------------------------
extern "C" void kernel_launch(void* const* d_in, const int* in_sizes, int n_in,
                              void* d_out, int out_size)
{
    const float* src_t = (const float*)d_in[0];
    const float* src_s = (const float*)d_in[1];
    const float* wk_m  = (const float*)d_in[2];
    const float* bk_m  = (const float*)d_in[3];
    const float* wv_m  = (const float*)d_in[4];
    const float* bv_m  = (const float*)d_in[5];
    const float* wk_q  = (const float*)d_in[6];
    const float* bk_q  = (const float*)d_in[7];
    const float* wv_q  = (const float*)d_in[8];
    const float* bv_q  = (const float*)d_in[9];
    float* out = (float*)d_out;

    cudaFuncSetAttribute(wg_gemm,   cudaFuncAttributeMaxDynamicSharedMemorySize, SMEM_TOTAL);
    cudaFuncSetAttribute(scores_tc, cudaFuncAttributeMaxDynamicSharedMemorySize, SMEM_TOTAL);
    cudaFuncSetAttribute(out_tc,    cudaFuncAttributeMaxDynamicSharedMemorySize, SMEM_TOTAL);

    // 0. transpose + f16 sources (both branches)
    {
        dim3 grid(32, 32, 32);
        dim3 blk(32, 8);
        transpose_src<<<grid, blk>>>(src_t, src_s);
    }
    // 1. winograd weight transforms (both branches)
    {
        int n = 2 * MTOT * CIN;
        wg_w<<<(n + 255) / 256, 256>>>(wk_m, wv_m, wk_q, wv_q);
    }
    // 2. winograd conv: input transform, GEMM, output transform (both branches)
    {
        dim3 dgrid(256, 32);
        wg_d<<<dgrid, 256>>>();

        dim3 ggrid(16, 12, 16);
        wg_gemm<<<ggrid, 256, SMEM_TOTAL>>>();

        dim3 ogrid(32, MTOT);
        wg_out<<<ogrid, 256>>>(bk_m, bv_m, bk_q, bv_q, out);
    }
    // 3. key transposes -> [b][pix][c] (both branches)
    {
        dim3 grid(32, 8, 32);
        dim3 blk(32, 8);
        transpose_kh<<<grid, blk>>>();
    }
    // 4. attention scores, S[b][q][m]
    {
        dim3 grid(64, 8);
        scores_tc<<<grid, 256, SMEM_TOTAL>>>();
    }
    // 5. row softmax -> E f16 + rsum
    {
        softmax_row<<<BB * HW / 8, 256>>>();
    }
    // 6. readout -> out channels [0, 512)
    {
        dim3 grid(64, 4);
        out_tc<<<grid, 256, SMEM_TOTAL>>>(out);
    }
}

// round 13
// speedup vs baseline: 8.5780x; 1.0862x over previous
#include <cuda_runtime.h>
#include <cuda_fp16.h>
#include <cstdint>

// ---------------------------------------------------------------------------
// Problem constants
// ---------------------------------------------------------------------------
#define BB     16
#define CIN    1024
#define HW     1024      // 32*32
#define CK     256
#define CV     512
#define MTOT   768       // stacked key(256) + value(512) output channels
#define NTILE  4096      // BB * 256 winograd tiles

// shared f16 mma tiling: CTA 128x256, 512 threads (16 warps of 64x32)
#define BM     128
#define BN     256
#define LDH    40        // smem pitch in halfs (80 B) -> conflict-free frags
#define A_BYTES (BM * LDH * 2)          // 10240
#define B_BYTES (BN * LDH * 2)          // 20480
#define STAGE_BYTES (A_BYTES + B_BYTES) // 30720
#define NSTAGE 3
#define SMEM_TOTAL (NSTAGE * STAGE_BYTES)   // 92160

#define KITERS_WG   32    // 1024 / 32
#define KITERS_SC   8     // 256 / 32
#define KITERS_OUT  32    // 1024 / 32

#define U_STRIDE  ((size_t)16 * MTOT * CIN)    // per-branch U halfs
#define V_STRIDE  ((size_t)16 * NTILE * CIN)   // per-branch V halfs
#define M_STRIDE  ((size_t)16 * MTOT * NTILE)  // per-branch M halfs

// ---------------------------------------------------------------------------
// Scratch (device globals; no allocation allowed). All accessed ONLY from
// device code (host passes `which` flags, never symbol addresses).
// ---------------------------------------------------------------------------
__device__ __half g_srcT0[BB * HW * CIN];    // f16 src_temp  [b][pix][ci]
__device__ __half g_srcT1[BB * HW * CIN];    // f16 src_search
__device__ __half g_U [2 * 16 * MTOT * CIN];   // winograd weights [br][t][co][ci]
__device__ __half g_V [2 * 16 * NTILE * CIN];  // winograd input  [br][t][bt][ci]
__device__ __half g_Mh[2 * 16 * MTOT * NTILE]; // gemm out [br][t][co][bt] f16
__device__ __half g_mkh[BB * CK * HW];       // m_key   [b][c][pix] f16
__device__ __half g_qkh[BB * CK * HW];       // q_key   [b][c][pix] f16
__device__ __half g_mkT[BB * HW * CK];       // m_key   [b][m][c]   f16
__device__ __half g_qkT[BB * HW * CK];       // q_key   [b][q][c]   f16
__device__ __half g_mvh[BB * CV * HW];       // m_value [b][c][m]   f16
__device__ float  g_S  [BB * HW * HW];       // scores  [b][q][m]   f32
__device__ __half g_E  [BB * HW * HW];       // exp     [b][q][m]   f16
__device__ float  g_rsum[BB * HW];           // 1 / row sum

// ---------------------------------------------------------------------------
// cp.async helpers
// ---------------------------------------------------------------------------
__device__ __forceinline__ void cp_async16z(uint32_t s, const void* g, int sz) {
    asm volatile("cp.async.cg.shared.global [%0], [%1], 16, %2;"
                 :: "r"(s), "l"(g), "r"(sz));
}
__device__ __forceinline__ void cp_commit() { asm volatile("cp.async.commit_group;"); }
__device__ __forceinline__ void cp_wait1()  { asm volatile("cp.async.wait_group 1;"); }

#define MMA_F16(acc, a, bf)                                                   \
    asm volatile(                                                             \
        "mma.sync.aligned.m16n8k16.row.col.f32.f16.f16.f32 "                  \
        "{%0,%1,%2,%3}, {%4,%5,%6,%7}, {%8,%9}, {%0,%1,%2,%3};"               \
        : "+f"((acc)[0]), "+f"((acc)[1]), "+f"((acc)[2]), "+f"((acc)[3])      \
        : "r"((a)[0]), "r"((a)[1]), "r"((a)[2]), "r"((a)[3]),                 \
          "r"((bf)[0]), "r"((bf)[1]))

// ---------------------------------------------------------------------------
// Pre-pass: transpose + f16 src, BOTH branches: [b][ci][pix] -> [b][pix][ci]
// grid (32, 32, 32): z = b + 16*which
// ---------------------------------------------------------------------------
__global__ void transpose_src(const float* __restrict__ s0,
                              const float* __restrict__ s1)
{
    __shared__ float t[32][33];
    int b = blockIdx.z & 15;
    int which = blockIdx.z >> 4;
    const float* src = which ? s1 : s0;
    int pix0 = blockIdx.x * 32, ci0 = blockIdx.y * 32;
    const float* s = src + ((size_t)b * CIN + ci0) * HW + pix0;
    for (int i = threadIdx.y; i < 32; i += 8)
        t[i][threadIdx.x] = s[(size_t)i * HW + threadIdx.x];   // t[ci][pix]
    __syncthreads();
    __half* d = (which ? g_srcT1 : g_srcT0) + ((size_t)b * HW + pix0) * CIN + ci0;
    for (int i = threadIdx.y; i < 32; i += 8)
        d[(size_t)i * CIN + threadIdx.x] = __float2half_rn(t[threadIdx.x][i]);
}

// ---------------------------------------------------------------------------
// Winograd weight transform, BOTH branches: U = G g G^T per (br, co, ci).
// ---------------------------------------------------------------------------
__global__ void wg_w(const float* __restrict__ wk_m, const float* __restrict__ wv_m,
                     const float* __restrict__ wk_q, const float* __restrict__ wv_q)
{
    int idx = blockIdx.x * blockDim.x + threadIdx.x;
    if (idx >= 2 * MTOT * CIN) return;
    int which = (idx >= MTOT * CIN);
    int r2 = idx - which * (MTOT * CIN);
    int co = r2 / CIN;
    int ci = r2 - co * CIN;
    const float* wk = which ? wk_q : wk_m;
    const float* wv = which ? wv_q : wv_m;
    __half* __restrict__ U = g_U + (size_t)which * U_STRIDE;

    const float* g = (co < CK) ? (wk + ((size_t)co * CIN + ci) * 9)
                               : (wv + ((size_t)(co - CK) * CIN + ci) * 9);
    float gr[3][3];
#pragma unroll
    for (int r = 0; r < 9; ++r) gr[r / 3][r % 3] = g[r];
    float t[4][3];
#pragma unroll
    for (int j = 0; j < 3; ++j) {
        t[0][j] = gr[0][j];
        t[1][j] = 0.5f * (gr[0][j] + gr[1][j] + gr[2][j]);
        t[2][j] = 0.5f * (gr[0][j] - gr[1][j] + gr[2][j]);
        t[3][j] = gr[2][j];
    }
#pragma unroll
    for (int i = 0; i < 4; ++i) {
        float u0 = t[i][0];
        float u1 = 0.5f * (t[i][0] + t[i][1] + t[i][2]);
        float u2 = 0.5f * (t[i][0] - t[i][1] + t[i][2]);
        float u3 = t[i][2];
        U[((size_t)(i * 4 + 0) * MTOT + co) * CIN + ci] = __float2half_rn(u0);
        U[((size_t)(i * 4 + 1) * MTOT + co) * CIN + ci] = __float2half_rn(u1);
        U[((size_t)(i * 4 + 2) * MTOT + co) * CIN + ci] = __float2half_rn(u2);
        U[((size_t)(i * 4 + 3) * MTOT + co) * CIN + ci] = __float2half_rn(u3);
    }
}

// ---------------------------------------------------------------------------
// Winograd input transform, BOTH branches: V = B^T d B per (br, b, tile, ci).
// grid (256 tiles, 32): y = b + 16*which. Zero-pad halo.
// ---------------------------------------------------------------------------
__global__ __launch_bounds__(256)
void wg_d()
{
    const int b     = blockIdx.y & 15;
    const int which = blockIdx.y >> 4;
    const __half* __restrict__ srcT = which ? g_srcT1 : g_srcT0;
    __half* __restrict__ V = g_V + (size_t)which * V_STRIDE;
    const int tile = blockIdx.x;
    const int ty = tile >> 4, tx = tile & 15;
    const int oy = 2 * ty, ox = 2 * tx;
    const int bt = b * 256 + tile;
    const __half* sb = srcT + (size_t)b * (HW * CIN);

#pragma unroll
    for (int pass = 0; pass < 2; ++pass) {
        int ci = (threadIdx.x + pass * 256) * 2;
        float2 d[4][4];
#pragma unroll
        for (int i = 0; i < 4; ++i) {
            int iy = oy - 1 + i;
#pragma unroll
            for (int j = 0; j < 4; ++j) {
                int ix = ox - 1 + j;
                if ((unsigned)iy < 32u && (unsigned)ix < 32u) {
                    __half2 h = *reinterpret_cast<const __half2*>(
                        &sb[(size_t)(iy * 32 + ix) * CIN + ci]);
                    d[i][j] = __half22float2(h);
                } else {
                    d[i][j] = make_float2(0.f, 0.f);
                }
            }
        }
        float2 r[4][4];
#pragma unroll
        for (int j = 0; j < 4; ++j) {
            r[0][j] = make_float2(d[0][j].x - d[2][j].x, d[0][j].y - d[2][j].y);
            r[1][j] = make_float2(d[1][j].x + d[2][j].x, d[1][j].y + d[2][j].y);
            r[2][j] = make_float2(d[2][j].x - d[1][j].x, d[2][j].y - d[1][j].y);
            r[3][j] = make_float2(d[1][j].x - d[3][j].x, d[1][j].y - d[3][j].y);
        }
#pragma unroll
        for (int i = 0; i < 4; ++i) {
            float2 v[4];
            v[0] = make_float2(r[i][0].x - r[i][2].x, r[i][0].y - r[i][2].y);
            v[1] = make_float2(r[i][1].x + r[i][2].x, r[i][1].y + r[i][2].y);
            v[2] = make_float2(r[i][2].x - r[i][1].x, r[i][2].y - r[i][1].y);
            v[3] = make_float2(r[i][1].x - r[i][3].x, r[i][1].y - r[i][3].y);
#pragma unroll
            for (int j = 0; j < 4; ++j) {
                *reinterpret_cast<__half2*>(
                    &V[((size_t)(i * 4 + j) * NTILE + bt) * CIN + ci]) =
                    __floats2half2_rn(v[j].x, v[j].y);
            }
        }
    }
}

// ---------------------------------------------------------------------------
// Winograd GEMM, BOTH branches: M[t][co][n] = sum_ci U[t][co][ci]*V[t][n][ci].
// grid (16 n-tiles, 12, 16 t): which = y/6, co0 = (y%6)*128. K = 1024.
// 512 threads: 16 warps (2x8), warp tile 64x32. M stored f16.
// ---------------------------------------------------------------------------
__global__ __launch_bounds__(512, 1)
void wg_gemm()
{
    extern __shared__ char sm[];
    const int which = blockIdx.y / 6;
    const int tid  = threadIdx.x;
    const int warp = tid >> 5, lane = tid & 31;
    const int grp  = lane >> 2, tig = lane & 3;
    const int wm   = (warp >> 3) * 64;      // 0 / 64
    const int wn   = (warp & 7) * 32;       // 0..224

    const int n0  = blockIdx.x * BN;
    const int co0 = (blockIdx.y % 6) * BM;
    const int t   = blockIdx.z;
    const __half* Ut = g_U + (size_t)which * U_STRIDE + (size_t)t * MTOT * CIN;
    const __half* Vt = g_V + (size_t)which * V_STRIDE + (size_t)t * NTILE * CIN;
    __half* __restrict__ Mh = g_Mh + (size_t)which * M_STRIDE;

    const uint32_t smem_u = (uint32_t)__cvta_generic_to_shared(sm);

    float acc[4][4][4];
#pragma unroll
    for (int mt = 0; mt < 4; ++mt)
#pragma unroll
        for (int nt = 0; nt < 4; ++nt)
#pragma unroll
            for (int c = 0; c < 4; ++c) acc[mt][nt][c] = 0.f;

    // staging maps (512 threads): A 1 chunk/thread, B 2 chunks/thread
    const int am = tid >> 2, aq = tid & 3;           // A: row, 16B-chunk
    const int bn = tid >> 1, bh = tid & 1;           // B: row, half-row
    auto issue = [&](int kt, int buf) {
        const uint32_t sA = smem_u + (uint32_t)buf * STAGE_BYTES;
        const uint32_t sB = sA + A_BYTES;
        cp_async16z(sA + (uint32_t)(am * (LDH * 2) + aq * 16),
                    Ut + (size_t)co0 * CIN + (size_t)am * CIN + kt * 32 + aq * 8, 16);
        const __half* bbase = Vt + (size_t)(n0 + bn) * CIN + kt * 32 + bh * 16;
        const uint32_t rb = (uint32_t)(bn * (LDH * 2) + bh * 32);
#pragma unroll
        for (int j = 0; j < 2; ++j)
            cp_async16z(sB + rb + j * 16, bbase + j * 8, 16);
    };

    issue(0, 0); cp_commit();
    issue(1, 1); cp_commit();

    int buf = 0;
    for (int kt = 0; kt < KITERS_WG; ++kt) {
        cp_wait1();
        __syncthreads();
        if (kt + 2 < KITERS_WG) issue(kt + 2, (buf + 2) % 3);
        cp_commit();

        const __half* As = reinterpret_cast<const __half*>(sm + buf * STAGE_BYTES);
        const __half* Bs = reinterpret_cast<const __half*>(sm + buf * STAGE_BYTES + A_BYTES);
#pragma unroll
        for (int s = 0; s < 2; ++s) {
            const int k16 = s * 16;
            uint32_t a[4][4], bf[4][2];
#pragma unroll
            for (int mt = 0; mt < 4; ++mt) {
                int row = wm + mt * 16 + grp;
                a[mt][0] = *reinterpret_cast<const uint32_t*>(&As[row * LDH + k16 + 2 * tig]);
                a[mt][1] = *reinterpret_cast<const uint32_t*>(&As[(row + 8) * LDH + k16 + 2 * tig]);
                a[mt][2] = *reinterpret_cast<const uint32_t*>(&As[row * LDH + k16 + 2 * tig + 8]);
                a[mt][3] = *reinterpret_cast<const uint32_t*>(&As[(row + 8) * LDH + k16 + 2 * tig + 8]);
            }
#pragma unroll
            for (int nt = 0; nt < 4; ++nt) {
                int col = wn + nt * 8 + grp;
                bf[nt][0] = *reinterpret_cast<const uint32_t*>(&Bs[col * LDH + k16 + 2 * tig]);
                bf[nt][1] = *reinterpret_cast<const uint32_t*>(&Bs[col * LDH + k16 + 2 * tig + 8]);
            }
#pragma unroll
            for (int mt = 0; mt < 4; ++mt)
#pragma unroll
                for (int nt = 0; nt < 4; ++nt)
                    MMA_F16(acc[mt][nt], a[mt], bf[nt]);
        }
        buf = (buf + 1) % 3;
    }

#pragma unroll
    for (int mt = 0; mt < 4; ++mt) {
        int r0 = co0 + wm + mt * 16 + grp;
        int r1 = r0 + 8;
        __half* d0 = Mh + ((size_t)t * MTOT + r0) * NTILE + n0;
        __half* d1 = Mh + ((size_t)t * MTOT + r1) * NTILE + n0;
#pragma unroll
        for (int nt = 0; nt < 4; ++nt) {
            int col = wn + nt * 8 + 2 * tig;
            *reinterpret_cast<__half2*>(&d0[col]) =
                __floats2half2_rn(acc[mt][nt][0], acc[mt][nt][1]);
            *reinterpret_cast<__half2*>(&d1[col]) =
                __floats2half2_rn(acc[mt][nt][2], acc[mt][nt][3]);
        }
    }
}

// ---------------------------------------------------------------------------
// Winograd output transform, BOTH branches: Y = A^T m A (+bias), scatter.
// grid (32, 768): which = bx>>4, bt = (bx&15)*256+tid, co = by.
// ---------------------------------------------------------------------------
__global__ __launch_bounds__(256)
void wg_out(const float* __restrict__ bk_m, const float* __restrict__ bv_m,
            const float* __restrict__ bk_q, const float* __restrict__ bv_q,
            float* __restrict__ out)
{
    const int which = blockIdx.x >> 4;
    const int bt = (blockIdx.x & 15) * 256 + threadIdx.x;
    const int co = blockIdx.y;
    const int b    = bt >> 8;
    const int tile = bt & 255;
    const int ty = tile >> 4, tx = tile & 15;
    const int pix = (2 * ty) * 32 + 2 * tx;
    const __half* Mh = g_Mh + (size_t)which * M_STRIDE;
    const float* bias_k = which ? bk_q : bk_m;
    const float* bias_v = which ? bv_q : bv_m;

    float m[4][4];
#pragma unroll
    for (int i = 0; i < 4; ++i)
#pragma unroll
        for (int j = 0; j < 4; ++j)
            m[i][j] = __half2float(Mh[((size_t)(i * 4 + j) * MTOT + co) * NTILE + bt]);

    float s0[4], s1[4];
#pragma unroll
    for (int j = 0; j < 4; ++j) {
        s0[j] = m[0][j] + m[1][j] + m[2][j];
        s1[j] = m[1][j] - m[2][j] - m[3][j];
    }
    float y00 = s0[0] + s0[1] + s0[2];
    float y01 = s0[1] - s0[2] - s0[3];
    float y10 = s1[0] + s1[1] + s1[2];
    float y11 = s1[1] - s1[2] - s1[3];

    if (co < CK) {
        float bia = bias_k[co];
        __half* d = (which ? g_qkh : g_mkh) + ((size_t)b * CK + co) * HW;
        *reinterpret_cast<__half2*>(&d[pix])      = __floats2half2_rn(y00 + bia, y01 + bia);
        *reinterpret_cast<__half2*>(&d[pix + 32]) = __floats2half2_rn(y10 + bia, y11 + bia);
    } else {
        int cv = co - CK;
        float bia = bias_v[cv];
        if (which) {
            float* d = out + (size_t)b * (2 * CV * HW) + (size_t)(CV + cv) * HW;
            *reinterpret_cast<float2*>(&d[pix])      = make_float2(y00 + bia, y01 + bia);
            *reinterpret_cast<float2*>(&d[pix + 32]) = make_float2(y10 + bia, y11 + bia);
        } else {
            __half* d = g_mvh + ((size_t)b * CV + cv) * HW;
            *reinterpret_cast<__half2*>(&d[pix])      = __floats2half2_rn(y00 + bia, y01 + bia);
            *reinterpret_cast<__half2*>(&d[pix + 32]) = __floats2half2_rn(y10 + bia, y11 + bia);
        }
    }
}

// ---------------------------------------------------------------------------
// Key transpose f16, BOTH branches: [b][c][pix] -> [b][pix][c]
// grid (32, 8, 32): z = b + 16*which
// ---------------------------------------------------------------------------
__global__ void transpose_kh()
{
    __shared__ __half t[32][34];
    int b = blockIdx.z & 15;
    int which = blockIdx.z >> 4;
    const __half* in = which ? g_qkh : g_mkh;
    __half* outp     = which ? g_qkT : g_mkT;
    int pix0 = blockIdx.x * 32, c0 = blockIdx.y * 32;
    const __half* s = in + ((size_t)b * CK + c0) * HW + pix0;
    for (int i = threadIdx.y; i < 32; i += 8)
        t[i][threadIdx.x] = s[(size_t)i * HW + threadIdx.x];   // t[c][pix]
    __syncthreads();
    __half* d = outp + ((size_t)b * HW + pix0) * CK + c0;
    for (int i = threadIdx.y; i < 32; i += 8)
        d[(size_t)i * CK + threadIdx.x] = t[threadIdx.x][i];
}

// ---------------------------------------------------------------------------
// Scores (f16 mma, 512 thr): S[b][q][m] = (1/16)*sum_c qkT[q][c]*mkT[m][c]
// grid (64, 8): x -> (b, m0), y -> q0. K = 256.
// ---------------------------------------------------------------------------
__global__ __launch_bounds__(512, 1)
void scores_tc()
{
    extern __shared__ char sm[];
    const int tid  = threadIdx.x;
    const int warp = tid >> 5, lane = tid & 31;
    const int grp  = lane >> 2, tig = lane & 3;
    const int wm   = (warp >> 3) * 64;
    const int wn   = (warp & 7) * 32;

    const int b  = blockIdx.x >> 2;
    const int m0 = (blockIdx.x & 3) * BN;
    const int q0 = blockIdx.y * BM;
    const __half* qkT = g_qkT + (size_t)b * (HW * CK);
    const __half* mkT = g_mkT + (size_t)b * (HW * CK);

    const uint32_t smem_u = (uint32_t)__cvta_generic_to_shared(sm);

    float acc[4][4][4];
#pragma unroll
    for (int mt = 0; mt < 4; ++mt)
#pragma unroll
        for (int nt = 0; nt < 4; ++nt)
#pragma unroll
            for (int c = 0; c < 4; ++c) acc[mt][nt][c] = 0.f;

    const int am = tid >> 2, aq = tid & 3;
    const int bn = tid >> 1, bh = tid & 1;
    auto issue = [&](int kt, int buf) {
        const uint32_t sA = smem_u + (uint32_t)buf * STAGE_BYTES;
        const uint32_t sB = sA + A_BYTES;
        cp_async16z(sA + (uint32_t)(am * (LDH * 2) + aq * 16),
                    qkT + (size_t)(q0 + am) * CK + kt * 32 + aq * 8, 16);
        const __half* bbase = mkT + (size_t)(m0 + bn) * CK + kt * 32 + bh * 16;
        const uint32_t rb = (uint32_t)(bn * (LDH * 2) + bh * 32);
#pragma unroll
        for (int j = 0; j < 2; ++j)
            cp_async16z(sB + rb + j * 16, bbase + j * 8, 16);
    };

    issue(0, 0); cp_commit();
    issue(1, 1); cp_commit();

    int buf = 0;
    for (int kt = 0; kt < KITERS_SC; ++kt) {
        cp_wait1();
        __syncthreads();
        if (kt + 2 < KITERS_SC) issue(kt + 2, (buf + 2) % 3);
        cp_commit();

        const __half* As = reinterpret_cast<const __half*>(sm + buf * STAGE_BYTES);
        const __half* Bs = reinterpret_cast<const __half*>(sm + buf * STAGE_BYTES + A_BYTES);
#pragma unroll
        for (int s = 0; s < 2; ++s) {
            const int k16 = s * 16;
            uint32_t a[4][4], bf[4][2];
#pragma unroll
            for (int mt = 0; mt < 4; ++mt) {
                int row = wm + mt * 16 + grp;
                a[mt][0] = *reinterpret_cast<const uint32_t*>(&As[row * LDH + k16 + 2 * tig]);
                a[mt][1] = *reinterpret_cast<const uint32_t*>(&As[(row + 8) * LDH + k16 + 2 * tig]);
                a[mt][2] = *reinterpret_cast<const uint32_t*>(&As[row * LDH + k16 + 2 * tig + 8]);
                a[mt][3] = *reinterpret_cast<const uint32_t*>(&As[(row + 8) * LDH + k16 + 2 * tig + 8]);
            }
#pragma unroll
            for (int nt = 0; nt < 4; ++nt) {
                int col = wn + nt * 8 + grp;
                bf[nt][0] = *reinterpret_cast<const uint32_t*>(&Bs[col * LDH + k16 + 2 * tig]);
                bf[nt][1] = *reinterpret_cast<const uint32_t*>(&Bs[col * LDH + k16 + 2 * tig + 8]);
            }
#pragma unroll
            for (int mt = 0; mt < 4; ++mt)
#pragma unroll
                for (int nt = 0; nt < 4; ++nt)
                    MMA_F16(acc[mt][nt], a[mt], bf[nt]);
        }
        buf = (buf + 1) % 3;
    }

    const float scale = 0.0625f;   // 1/sqrt(256)
#pragma unroll
    for (int mt = 0; mt < 4; ++mt) {
        int r0 = q0 + wm + mt * 16 + grp;
        int r1 = r0 + 8;
        float* s0 = g_S + (size_t)b * (HW * HW) + (size_t)r0 * HW + m0;
        float* s1 = g_S + (size_t)b * (HW * HW) + (size_t)r1 * HW + m0;
#pragma unroll
        for (int nt = 0; nt < 4; ++nt) {
            int col = wn + nt * 8 + 2 * tig;
            *reinterpret_cast<float2*>(&s0[col]) =
                make_float2(acc[mt][nt][0] * scale, acc[mt][nt][1] * scale);
            *reinterpret_cast<float2*>(&s1[col]) =
                make_float2(acc[mt][nt][2] * scale, acc[mt][nt][3] * scale);
        }
    }
}

// ---------------------------------------------------------------------------
// Row softmax over m: E = exp(S - rowmax) f16, rsum = 1/rowsum.
// ---------------------------------------------------------------------------
__global__ __launch_bounds__(256)
void softmax_row()
{
    const int warp = threadIdx.x >> 5, lane = threadIdx.x & 31;
    const int gid = blockIdx.x * 8 + warp;
    const float4* s4 = reinterpret_cast<const float4*>(g_S + (size_t)gid * HW);

    float4 v[8];
    float mx = -3.402823e38f;
#pragma unroll
    for (int j = 0; j < 8; ++j) {
        v[j] = s4[j * 32 + lane];
        mx = fmaxf(mx, fmaxf(fmaxf(v[j].x, v[j].y), fmaxf(v[j].z, v[j].w)));
    }
#pragma unroll
    for (int o = 16; o > 0; o >>= 1)
        mx = fmaxf(mx, __shfl_xor_sync(0xFFFFFFFFu, mx, o));

    uint2* e2 = reinterpret_cast<uint2*>(g_E + (size_t)gid * HW);
    float sum = 0.f;
#pragma unroll
    for (int j = 0; j < 8; ++j) {
        float e0 = __expf(v[j].x - mx);
        float e1 = __expf(v[j].y - mx);
        float e2f = __expf(v[j].z - mx);
        float e3 = __expf(v[j].w - mx);
        sum += (e0 + e1) + (e2f + e3);
        __half2 h01 = __floats2half2_rn(e0, e1);
        __half2 h23 = __floats2half2_rn(e2f, e3);
        uint2 u;
        u.x = *reinterpret_cast<uint32_t*>(&h01);
        u.y = *reinterpret_cast<uint32_t*>(&h23);
        e2[j * 32 + lane] = u;
    }
#pragma unroll
    for (int o = 16; o > 0; o >>= 1)
        sum += __shfl_xor_sync(0xFFFFFFFFu, sum, o);
    if (lane == 0) g_rsum[gid] = 1.0f / sum;
}

// ---------------------------------------------------------------------------
// Readout (f16 mma, 512 thr): out[b][c][q] = (sum_m mvh[c][m]*E[q][m])*rsum
// grid (64, 4): x -> (b, q0), y -> c0. K = 1024.
// ---------------------------------------------------------------------------
__global__ __launch_bounds__(512, 1)
void out_tc(float* __restrict__ out)
{
    extern __shared__ char sm[];
    const int tid  = threadIdx.x;
    const int warp = tid >> 5, lane = tid & 31;
    const int grp  = lane >> 2, tig = lane & 3;
    const int wm   = (warp >> 3) * 64;
    const int wn   = (warp & 7) * 32;

    const int b  = blockIdx.x >> 2;
    const int q0 = (blockIdx.x & 3) * BN;
    const int c0 = blockIdx.y * BM;
    const __half* mvh = g_mvh + (size_t)b * (CV * HW);
    const __half* E   = g_E   + (size_t)b * (HW * HW);

    const uint32_t smem_u = (uint32_t)__cvta_generic_to_shared(sm);

    float acc[4][4][4];
#pragma unroll
    for (int mt = 0; mt < 4; ++mt)
#pragma unroll
        for (int nt = 0; nt < 4; ++nt)
#pragma unroll
            for (int c = 0; c < 4; ++c) acc[mt][nt][c] = 0.f;

    const int am = tid >> 2, aq = tid & 3;
    const int bn = tid >> 1, bh = tid & 1;
    auto issue = [&](int kt, int buf) {
        const uint32_t sA = smem_u + (uint32_t)buf * STAGE_BYTES;
        const uint32_t sB = sA + A_BYTES;
        cp_async16z(sA + (uint32_t)(am * (LDH * 2) + aq * 16),
                    mvh + (size_t)(c0 + am) * HW + kt * 32 + aq * 8, 16);
        const __half* bbase = E + (size_t)(q0 + bn) * HW + kt * 32 + bh * 16;
        const uint32_t rb = (uint32_t)(bn * (LDH * 2) + bh * 32);
#pragma unroll
        for (int j = 0; j < 2; ++j)
            cp_async16z(sB + rb + j * 16, bbase + j * 8, 16);
    };

    issue(0, 0); cp_commit();
    issue(1, 1); cp_commit();

    int buf = 0;
    for (int kt = 0; kt < KITERS_OUT; ++kt) {
        cp_wait1();
        __syncthreads();
        if (kt + 2 < KITERS_OUT) issue(kt + 2, (buf + 2) % 3);
        cp_commit();

        const __half* As = reinterpret_cast<const __half*>(sm + buf * STAGE_BYTES);
        const __half* Bs = reinterpret_cast<const __half*>(sm + buf * STAGE_BYTES + A_BYTES);
#pragma unroll
        for (int s = 0; s < 2; ++s) {
            const int k16 = s * 16;
            uint32_t a[4][4], bf[4][2];
#pragma unroll
            for (int mt = 0; mt < 4; ++mt) {
                int row = wm + mt * 16 + grp;
                a[mt][0] = *reinterpret_cast<const uint32_t*>(&As[row * LDH + k16 + 2 * tig]);
                a[mt][1] = *reinterpret_cast<const uint32_t*>(&As[(row + 8) * LDH + k16 + 2 * tig]);
                a[mt][2] = *reinterpret_cast<const uint32_t*>(&As[row * LDH + k16 + 2 * tig + 8]);
                a[mt][3] = *reinterpret_cast<const uint32_t*>(&As[(row + 8) * LDH + k16 + 2 * tig + 8]);
            }
#pragma unroll
            for (int nt = 0; nt < 4; ++nt) {
                int col = wn + nt * 8 + grp;
                bf[nt][0] = *reinterpret_cast<const uint32_t*>(&Bs[col * LDH + k16 + 2 * tig]);
                bf[nt][1] = *reinterpret_cast<const uint32_t*>(&Bs[col * LDH + k16 + 2 * tig + 8]);
            }
#pragma unroll
            for (int mt = 0; mt < 4; ++mt)
#pragma unroll
                for (int nt = 0; nt < 4; ++nt)
                    MMA_F16(acc[mt][nt], a[mt], bf[nt]);
        }
        buf = (buf + 1) % 3;
    }

    const float* rs = g_rsum + (size_t)b * HW;
#pragma unroll
    for (int mt = 0; mt < 4; ++mt) {
        int r0 = c0 + wm + mt * 16 + grp;
        int r1 = r0 + 8;
        float* d0 = out + (size_t)b * (2 * CV * HW) + (size_t)r0 * HW;
        float* d1 = out + (size_t)b * (2 * CV * HW) + (size_t)r1 * HW;
#pragma unroll
        for (int nt = 0; nt < 4; ++nt) {
            int col = q0 + wn + nt * 8 + 2 * tig;
            float2 r2 = *reinterpret_cast<const float2*>(&rs[col]);
            *reinterpret_cast<float2*>(&d0[col]) =
                make_float2(acc[mt][nt][0] * r2.x, acc[mt][nt][1] * r2.y);
            *reinterpret_cast<float2*>(&d1[col]) =
                make_float2(acc[mt][nt][2] * r2.x, acc[mt][nt][3] * r2.y);
        }
    }
}

// ---------------------------------------------------------------------------
// Launch
// ---------------------------------------------------------------------------
extern "C" void kernel_launch(void* const* d_in, const int* in_sizes, int n_in,
                              void* d_out, int out_size)
{
    const float* src_t = (const float*)d_in[0];
    const float* src_s = (const float*)d_in[1];
    const float* wk_m  = (const float*)d_in[2];
    const float* bk_m  = (const float*)d_in[3];
    const float* wv_m  = (const float*)d_in[4];
    const float* bv_m  = (const float*)d_in[5];
    const float* wk_q  = (const float*)d_in[6];
    const float* bk_q  = (const float*)d_in[7];
    const float* wv_q  = (const float*)d_in[8];
    const float* bv_q  = (const float*)d_in[9];
    float* out = (float*)d_out;

    cudaFuncSetAttribute(wg_gemm,   cudaFuncAttributeMaxDynamicSharedMemorySize, SMEM_TOTAL);
    cudaFuncSetAttribute(scores_tc, cudaFuncAttributeMaxDynamicSharedMemorySize, SMEM_TOTAL);
    cudaFuncSetAttribute(out_tc,    cudaFuncAttributeMaxDynamicSharedMemorySize, SMEM_TOTAL);

    // 0. transpose + f16 sources (both branches)
    {
        dim3 grid(32, 32, 32);
        dim3 blk(32, 8);
        transpose_src<<<grid, blk>>>(src_t, src_s);
    }
    // 1. winograd weight transforms (both branches)
    {
        int n = 2 * MTOT * CIN;
        wg_w<<<(n + 255) / 256, 256>>>(wk_m, wv_m, wk_q, wv_q);
    }
    // 2. winograd conv: input transform, GEMM, output transform (both branches)
    {
        dim3 dgrid(256, 32);
        wg_d<<<dgrid, 256>>>();

        dim3 ggrid(16, 12, 16);
        wg_gemm<<<ggrid, 512, SMEM_TOTAL>>>();

        dim3 ogrid(32, MTOT);
        wg_out<<<ogrid, 256>>>(bk_m, bv_m, bk_q, bv_q, out);
    }
    // 3. key transposes -> [b][pix][c] (both branches)
    {
        dim3 grid(32, 8, 32);
        dim3 blk(32, 8);
        transpose_kh<<<grid, blk>>>();
    }
    // 4. attention scores, S[b][q][m]
    {
        dim3 grid(64, 8);
        scores_tc<<<grid, 512, SMEM_TOTAL>>>();
    }
    // 5. row softmax -> E f16 + rsum
    {
        softmax_row<<<BB * HW / 8, 256>>>();
    }
    // 6. readout -> out channels [0, 512)
    {
        dim3 grid(64, 4);
        out_tc<<<grid, 512, SMEM_TOTAL>>>(out);
    }
}

// round 14
// speedup vs baseline: 10.1099x; 1.1786x over previous
#include <cuda_runtime.h>
#include <cuda_fp16.h>
#include <cstdint>

// ---------------------------------------------------------------------------
// Problem constants
// ---------------------------------------------------------------------------
#define BB     16
#define CIN    1024
#define HW     1024      // 32*32
#define CK     256
#define CV     512
#define MTOT   768       // stacked key(256) + value(512) output channels
#define NTILE  4096      // BB * 256 winograd tiles

// shared f16 mma tiling: CTA 128x256, 512 threads (16 warps of 64x32)
#define BM     128
#define BN     256
#define LDH    40        // pitch in halfs (80 B) -> conflict-free frags
#define A_BYTES (BM * LDH * 2)          // 10240
#define B_BYTES (BN * LDH * 2)          // 20480
#define STAGE_BYTES (A_BYTES + B_BYTES) // 30720
#define NSTAGE 3
#define SMEM_GEMM (128 + NSTAGE * STAGE_BYTES)   // mbars + stages = 92288
#define SMEM_TOTAL (NSTAGE * STAGE_BYTES)        // cp.async kernels (92160)

#define KITERS_WG   32    // 1024 / 32
#define KITERS_SC   8     // 256 / 32
#define KITERS_OUT  32    // 1024 / 32

// blocked U/V strides (pitch-40 rows, smem-image layout)
#define U_STRIDE  ((size_t)16 * 32 * MTOT  * LDH)   // per-branch U halfs
#define V_STRIDE  ((size_t)16 * 32 * NTILE * LDH)   // per-branch V halfs
#define M_STRIDE  ((size_t)16 * MTOT * NTILE)       // per-branch M halfs

// ---------------------------------------------------------------------------
// Scratch (device globals; no allocation allowed). All accessed ONLY from
// device code (host passes `which` flags, never symbol addresses).
// ---------------------------------------------------------------------------
__device__ __half g_srcT0[BB * HW * CIN];    // f16 src_temp  [b][pix][ci]
__device__ __half g_srcT1[BB * HW * CIN];    // f16 src_search
__device__ __half g_U [2 * 16 * 32 * MTOT  * LDH]; // [br][t][kt][co][40]
__device__ __half g_V [2 * 16 * 32 * NTILE * LDH]; // [br][t][kt][bt][40]
__device__ __half g_Mh[2 * 16 * MTOT * NTILE];     // [br][t][co][bt] f16
__device__ __half g_mkh[BB * CK * HW];       // m_key   [b][c][pix] f16
__device__ __half g_qkh[BB * CK * HW];       // q_key   [b][c][pix] f16
__device__ __half g_mkT[BB * HW * CK];       // m_key   [b][m][c]   f16
__device__ __half g_qkT[BB * HW * CK];       // q_key   [b][q][c]   f16
__device__ __half g_mvh[BB * CV * HW];       // m_value [b][c][m]   f16
__device__ float  g_S  [BB * HW * HW];       // scores  [b][q][m]   f32
__device__ __half g_E  [BB * HW * HW];       // exp     [b][q][m]   f16
__device__ float  g_rsum[BB * HW];           // 1 / row sum

// ---------------------------------------------------------------------------
// async-copy helpers
// ---------------------------------------------------------------------------
__device__ __forceinline__ void cp_async16z(uint32_t s, const void* g, int sz) {
    asm volatile("cp.async.cg.shared.global [%0], [%1], 16, %2;"
                 :: "r"(s), "l"(g), "r"(sz));
}
__device__ __forceinline__ void cp_commit() { asm volatile("cp.async.commit_group;"); }
__device__ __forceinline__ void cp_wait1()  { asm volatile("cp.async.wait_group 1;"); }

__device__ __forceinline__ void mbar_init(uint32_t a, uint32_t cnt) {
    asm volatile("mbarrier.init.shared.b64 [%0], %1;" :: "r"(a), "r"(cnt) : "memory");
}
__device__ __forceinline__ void mbar_expect_tx(uint32_t a, uint32_t bytes) {
    asm volatile("mbarrier.arrive.expect_tx.shared.b64 _, [%0], %1;"
                 :: "r"(a), "r"(bytes) : "memory");
}
__device__ __forceinline__ void bulk_g2s(uint32_t dst, const void* src,
                                         uint32_t bytes, uint32_t mbar) {
    asm volatile("cp.async.bulk.shared::cluster.global.mbarrier::complete_tx::bytes "
                 "[%0], [%1], %2, [%3];"
                 :: "r"(dst), "l"(src), "r"(bytes), "r"(mbar) : "memory");
}
__device__ __forceinline__ void mbar_wait(uint32_t a, uint32_t parity) {
    uint32_t done;
    asm volatile("{\n\t.reg .pred p;\n\t"
        "mbarrier.try_wait.parity.acquire.cta.shared::cta.b64 p, [%1], %2;\n\t"
        "selp.b32 %0, 1, 0, p;\n\t}" : "=r"(done) : "r"(a), "r"(parity) : "memory");
    if (!done) {
        asm volatile("{\n\t.reg .pred P1;\n\t"
            "WL_%=:\n\t"
            "mbarrier.try_wait.parity.acquire.cta.shared::cta.b64 P1, [%0], %1, 0x989680;\n\t"
            "@P1 bra.uni WD_%=;\n\t"
            "bra.uni WL_%=;\n\t"
            "WD_%=:\n\t}" :: "r"(a), "r"(parity) : "memory");
    }
}

#define MMA_F16(acc, a, bf)                                                   \
    asm volatile(                                                             \
        "mma.sync.aligned.m16n8k16.row.col.f32.f16.f16.f32 "                  \
        "{%0,%1,%2,%3}, {%4,%5,%6,%7}, {%8,%9}, {%0,%1,%2,%3};"               \
        : "+f"((acc)[0]), "+f"((acc)[1]), "+f"((acc)[2]), "+f"((acc)[3])      \
        : "r"((a)[0]), "r"((a)[1]), "r"((a)[2]), "r"((a)[3]),                 \
          "r"((bf)[0]), "r"((bf)[1]))

// ---------------------------------------------------------------------------
// Pre-pass: transpose + f16 src, BOTH branches: [b][ci][pix] -> [b][pix][ci]
// ---------------------------------------------------------------------------
__global__ void transpose_src(const float* __restrict__ s0,
                              const float* __restrict__ s1)
{
    __shared__ float t[32][33];
    int b = blockIdx.z & 15;
    int which = blockIdx.z >> 4;
    const float* src = which ? s1 : s0;
    int pix0 = blockIdx.x * 32, ci0 = blockIdx.y * 32;
    const float* s = src + ((size_t)b * CIN + ci0) * HW + pix0;
    for (int i = threadIdx.y; i < 32; i += 8)
        t[i][threadIdx.x] = s[(size_t)i * HW + threadIdx.x];   // t[ci][pix]
    __syncthreads();
    __half* d = (which ? g_srcT1 : g_srcT0) + ((size_t)b * HW + pix0) * CIN + ci0;
    for (int i = threadIdx.y; i < 32; i += 8)
        d[(size_t)i * CIN + threadIdx.x] = __float2half_rn(t[threadIdx.x][i]);
}

// ---------------------------------------------------------------------------
// Winograd weight transform, BOTH branches: U = G g G^T per (br, co, ci).
// Output BLOCKED: U[br][t][kt][co][40], kt = ci>>5, kk = ci&31.
// ---------------------------------------------------------------------------
__global__ void wg_w(const float* __restrict__ wk_m, const float* __restrict__ wv_m,
                     const float* __restrict__ wk_q, const float* __restrict__ wv_q)
{
    int idx = blockIdx.x * blockDim.x + threadIdx.x;
    if (idx >= 2 * MTOT * CIN) return;
    int which = (idx >= MTOT * CIN);
    int r2 = idx - which * (MTOT * CIN);
    int co = r2 / CIN;
    int ci = r2 - co * CIN;
    const float* wk = which ? wk_q : wk_m;
    const float* wv = which ? wv_q : wv_m;
    __half* __restrict__ U = g_U + (size_t)which * U_STRIDE;
    const int kt = ci >> 5, kk = ci & 31;

    const float* g = (co < CK) ? (wk + ((size_t)co * CIN + ci) * 9)
                               : (wv + ((size_t)(co - CK) * CIN + ci) * 9);
    float gr[3][3];
#pragma unroll
    for (int r = 0; r < 9; ++r) gr[r / 3][r % 3] = g[r];
    float t[4][3];
#pragma unroll
    for (int j = 0; j < 3; ++j) {
        t[0][j] = gr[0][j];
        t[1][j] = 0.5f * (gr[0][j] + gr[1][j] + gr[2][j]);
        t[2][j] = 0.5f * (gr[0][j] - gr[1][j] + gr[2][j]);
        t[3][j] = gr[2][j];
    }
#pragma unroll
    for (int i = 0; i < 4; ++i) {
        float u0 = t[i][0];
        float u1 = 0.5f * (t[i][0] + t[i][1] + t[i][2]);
        float u2 = 0.5f * (t[i][0] - t[i][1] + t[i][2]);
        float u3 = t[i][2];
        const float uv[4] = {u0, u1, u2, u3};
#pragma unroll
        for (int j = 0; j < 4; ++j)
            U[(((size_t)(i * 4 + j) * 32 + kt) * MTOT + co) * LDH + kk] =
                __float2half_rn(uv[j]);
    }
}

// ---------------------------------------------------------------------------
// Winograd input transform, BOTH branches: V = B^T d B per (br, b, tile, ci).
// Output BLOCKED: V[br][t][kt][bt][40]. grid (256 tiles, 32). Zero-pad halo.
// ---------------------------------------------------------------------------
__global__ __launch_bounds__(256)
void wg_d()
{
    const int b     = blockIdx.y & 15;
    const int which = blockIdx.y >> 4;
    const __half* __restrict__ srcT = which ? g_srcT1 : g_srcT0;
    __half* __restrict__ V = g_V + (size_t)which * V_STRIDE;
    const int tile = blockIdx.x;
    const int ty = tile >> 4, tx = tile & 15;
    const int oy = 2 * ty, ox = 2 * tx;
    const int bt = b * 256 + tile;
    const __half* sb = srcT + (size_t)b * (HW * CIN);

#pragma unroll
    for (int pass = 0; pass < 2; ++pass) {
        int ci = (threadIdx.x + pass * 256) * 2;
        const int kt = ci >> 5, kk = ci & 31;
        float2 d[4][4];
#pragma unroll
        for (int i = 0; i < 4; ++i) {
            int iy = oy - 1 + i;
#pragma unroll
            for (int j = 0; j < 4; ++j) {
                int ix = ox - 1 + j;
                if ((unsigned)iy < 32u && (unsigned)ix < 32u) {
                    __half2 h = *reinterpret_cast<const __half2*>(
                        &sb[(size_t)(iy * 32 + ix) * CIN + ci]);
                    d[i][j] = __half22float2(h);
                } else {
                    d[i][j] = make_float2(0.f, 0.f);
                }
            }
        }
        float2 r[4][4];
#pragma unroll
        for (int j = 0; j < 4; ++j) {
            r[0][j] = make_float2(d[0][j].x - d[2][j].x, d[0][j].y - d[2][j].y);
            r[1][j] = make_float2(d[1][j].x + d[2][j].x, d[1][j].y + d[2][j].y);
            r[2][j] = make_float2(d[2][j].x - d[1][j].x, d[2][j].y - d[1][j].y);
            r[3][j] = make_float2(d[1][j].x - d[3][j].x, d[1][j].y - d[3][j].y);
        }
#pragma unroll
        for (int i = 0; i < 4; ++i) {
            float2 v[4];
            v[0] = make_float2(r[i][0].x - r[i][2].x, r[i][0].y - r[i][2].y);
            v[1] = make_float2(r[i][1].x + r[i][2].x, r[i][1].y + r[i][2].y);
            v[2] = make_float2(r[i][2].x - r[i][1].x, r[i][2].y - r[i][1].y);
            v[3] = make_float2(r[i][1].x - r[i][3].x, r[i][1].y - r[i][3].y);
#pragma unroll
            for (int j = 0; j < 4; ++j) {
                *reinterpret_cast<__half2*>(
                    &V[(((size_t)(i * 4 + j) * 32 + kt) * NTILE + bt) * LDH + kk]) =
                    __floats2half2_rn(v[j].x, v[j].y);
            }
        }
    }
}

// ---------------------------------------------------------------------------
// Winograd GEMM, BOTH branches: M[t][co][n] = sum_ci U*V, f16 mma.
// Bulk-copy (UBLKCP) + mbarrier 3-stage pipeline: 2 copies/stage instead of
// 1536 LDGSTS. grid (16 n-tiles, 12, 16 t). 512 thr, warp tile 64x32.
// ---------------------------------------------------------------------------
__global__ __launch_bounds__(512, 1)
void wg_gemm()
{
    extern __shared__ char sm[];
    const int which = blockIdx.y / 6;
    const int tid  = threadIdx.x;
    const int warp = tid >> 5, lane = tid & 31;
    const int grp  = lane >> 2, tig = lane & 3;
    const int wm   = (warp >> 3) * 64;      // 0 / 64
    const int wn   = (warp & 7) * 32;       // 0..224

    const int n0  = blockIdx.x * BN;
    const int co0 = (blockIdx.y % 6) * BM;
    const int t   = blockIdx.z;
    const __half* Ub = g_U + (size_t)which * U_STRIDE + (size_t)t * 32 * MTOT * LDH;
    const __half* Vb = g_V + (size_t)which * V_STRIDE + (size_t)t * 32 * NTILE * LDH;
    __half* __restrict__ Mh = g_Mh + (size_t)which * M_STRIDE;

    const uint32_t smem_u = (uint32_t)__cvta_generic_to_shared(sm);
    const uint32_t mb0    = smem_u;            // 3 mbarriers at +0,+8,+16
    const uint32_t stg0   = smem_u + 128;

    if (tid == 0) {
        mbar_init(mb0 + 0, 1);
        mbar_init(mb0 + 8, 1);
        mbar_init(mb0 + 16, 1);
    }
    __syncthreads();

    auto issue = [&](int kt, int buf) {
        const uint32_t mbar = mb0 + buf * 8;
        const uint32_t sA = stg0 + (uint32_t)buf * STAGE_BYTES;
        mbar_expect_tx(mbar, STAGE_BYTES);
        bulk_g2s(sA, Ub + ((size_t)kt * MTOT + co0) * LDH, A_BYTES, mbar);
        bulk_g2s(sA + A_BYTES, Vb + ((size_t)kt * NTILE + n0) * LDH, B_BYTES, mbar);
    };
    if (tid == 0) { issue(0, 0); issue(1, 1); issue(2, 2); }

    float acc[4][4][4];
#pragma unroll
    for (int mt = 0; mt < 4; ++mt)
#pragma unroll
        for (int nt = 0; nt < 4; ++nt)
#pragma unroll
            for (int c = 0; c < 4; ++c) acc[mt][nt][c] = 0.f;

    for (int kt = 0; kt < KITERS_WG; ++kt) {
        const int buf = kt % 3;
        mbar_wait(mb0 + buf * 8, (kt / 3) & 1);

        const __half* As = reinterpret_cast<const __half*>(sm + 128 + buf * STAGE_BYTES);
        const __half* Bs = As + BM * LDH;
#pragma unroll
        for (int s = 0; s < 2; ++s) {
            const int k16 = s * 16;
            uint32_t a[4][4], bf[4][2];
#pragma unroll
            for (int mt = 0; mt < 4; ++mt) {
                int row = wm + mt * 16 + grp;
                a[mt][0] = *reinterpret_cast<const uint32_t*>(&As[row * LDH + k16 + 2 * tig]);
                a[mt][1] = *reinterpret_cast<const uint32_t*>(&As[(row + 8) * LDH + k16 + 2 * tig]);
                a[mt][2] = *reinterpret_cast<const uint32_t*>(&As[row * LDH + k16 + 2 * tig + 8]);
                a[mt][3] = *reinterpret_cast<const uint32_t*>(&As[(row + 8) * LDH + k16 + 2 * tig + 8]);
            }
#pragma unroll
            for (int nt = 0; nt < 4; ++nt) {
                int col = wn + nt * 8 + grp;
                bf[nt][0] = *reinterpret_cast<const uint32_t*>(&Bs[col * LDH + k16 + 2 * tig]);
                bf[nt][1] = *reinterpret_cast<const uint32_t*>(&Bs[col * LDH + k16 + 2 * tig + 8]);
            }
#pragma unroll
            for (int mt = 0; mt < 4; ++mt)
#pragma unroll
                for (int nt = 0; nt < 4; ++nt)
                    MMA_F16(acc[mt][nt], a[mt], bf[nt]);
        }

        __syncthreads();                       // all warps done with buf
        if (kt + 3 < KITERS_WG && tid == 0) issue(kt + 3, buf);
    }

#pragma unroll
    for (int mt = 0; mt < 4; ++mt) {
        int r0 = co0 + wm + mt * 16 + grp;
        int r1 = r0 + 8;
        __half* d0 = Mh + ((size_t)t * MTOT + r0) * NTILE + n0;
        __half* d1 = Mh + ((size_t)t * MTOT + r1) * NTILE + n0;
#pragma unroll
        for (int nt = 0; nt < 4; ++nt) {
            int col = wn + nt * 8 + 2 * tig;
            *reinterpret_cast<__half2*>(&d0[col]) =
                __floats2half2_rn(acc[mt][nt][0], acc[mt][nt][1]);
            *reinterpret_cast<__half2*>(&d1[col]) =
                __floats2half2_rn(acc[mt][nt][2], acc[mt][nt][3]);
        }
    }
}

// ---------------------------------------------------------------------------
// Winograd output transform, BOTH branches: Y = A^T m A (+bias), scatter.
// ---------------------------------------------------------------------------
__global__ __launch_bounds__(256)
void wg_out(const float* __restrict__ bk_m, const float* __restrict__ bv_m,
            const float* __restrict__ bk_q, const float* __restrict__ bv_q,
            float* __restrict__ out)
{
    const int which = blockIdx.x >> 4;
    const int bt = (blockIdx.x & 15) * 256 + threadIdx.x;
    const int co = blockIdx.y;
    const int b    = bt >> 8;
    const int tile = bt & 255;
    const int ty = tile >> 4, tx = tile & 15;
    const int pix = (2 * ty) * 32 + 2 * tx;
    const __half* Mh = g_Mh + (size_t)which * M_STRIDE;
    const float* bias_k = which ? bk_q : bk_m;
    const float* bias_v = which ? bv_q : bv_m;

    float m[4][4];
#pragma unroll
    for (int i = 0; i < 4; ++i)
#pragma unroll
        for (int j = 0; j < 4; ++j)
            m[i][j] = __half2float(Mh[((size_t)(i * 4 + j) * MTOT + co) * NTILE + bt]);

    float s0[4], s1[4];
#pragma unroll
    for (int j = 0; j < 4; ++j) {
        s0[j] = m[0][j] + m[1][j] + m[2][j];
        s1[j] = m[1][j] - m[2][j] - m[3][j];
    }
    float y00 = s0[0] + s0[1] + s0[2];
    float y01 = s0[1] - s0[2] - s0[3];
    float y10 = s1[0] + s1[1] + s1[2];
    float y11 = s1[1] - s1[2] - s1[3];

    if (co < CK) {
        float bia = bias_k[co];
        __half* d = (which ? g_qkh : g_mkh) + ((size_t)b * CK + co) * HW;
        *reinterpret_cast<__half2*>(&d[pix])      = __floats2half2_rn(y00 + bia, y01 + bia);
        *reinterpret_cast<__half2*>(&d[pix + 32]) = __floats2half2_rn(y10 + bia, y11 + bia);
    } else {
        int cv = co - CK;
        float bia = bias_v[cv];
        if (which) {
            float* d = out + (size_t)b * (2 * CV * HW) + (size_t)(CV + cv) * HW;
            *reinterpret_cast<float2*>(&d[pix])      = make_float2(y00 + bia, y01 + bia);
            *reinterpret_cast<float2*>(&d[pix + 32]) = make_float2(y10 + bia, y11 + bia);
        } else {
            __half* d = g_mvh + ((size_t)b * CV + cv) * HW;
            *reinterpret_cast<__half2*>(&d[pix])      = __floats2half2_rn(y00 + bia, y01 + bia);
            *reinterpret_cast<__half2*>(&d[pix + 32]) = __floats2half2_rn(y10 + bia, y11 + bia);
        }
    }
}

// ---------------------------------------------------------------------------
// Key transpose f16, BOTH branches: [b][c][pix] -> [b][pix][c]
// ---------------------------------------------------------------------------
__global__ void transpose_kh()
{
    __shared__ __half t[32][34];
    int b = blockIdx.z & 15;
    int which = blockIdx.z >> 4;
    const __half* in = which ? g_qkh : g_mkh;
    __half* outp     = which ? g_qkT : g_mkT;
    int pix0 = blockIdx.x * 32, c0 = blockIdx.y * 32;
    const __half* s = in + ((size_t)b * CK + c0) * HW + pix0;
    for (int i = threadIdx.y; i < 32; i += 8)
        t[i][threadIdx.x] = s[(size_t)i * HW + threadIdx.x];   // t[c][pix]
    __syncthreads();
    __half* d = outp + ((size_t)b * HW + pix0) * CK + c0;
    for (int i = threadIdx.y; i < 32; i += 8)
        d[(size_t)i * CK + threadIdx.x] = t[threadIdx.x][i];
}

// ---------------------------------------------------------------------------
// Scores (f16 mma, 512 thr): S[b][q][m] = (1/16)*sum_c qkT[q][c]*mkT[m][c]
// ---------------------------------------------------------------------------
__global__ __launch_bounds__(512, 1)
void scores_tc()
{
    extern __shared__ char sm[];
    const int tid  = threadIdx.x;
    const int warp = tid >> 5, lane = tid & 31;
    const int grp  = lane >> 2, tig = lane & 3;
    const int wm   = (warp >> 3) * 64;
    const int wn   = (warp & 7) * 32;

    const int b  = blockIdx.x >> 2;
    const int m0 = (blockIdx.x & 3) * BN;
    const int q0 = blockIdx.y * BM;
    const __half* qkT = g_qkT + (size_t)b * (HW * CK);
    const __half* mkT = g_mkT + (size_t)b * (HW * CK);

    const uint32_t smem_u = (uint32_t)__cvta_generic_to_shared(sm);

    float acc[4][4][4];
#pragma unroll
    for (int mt = 0; mt < 4; ++mt)
#pragma unroll
        for (int nt = 0; nt < 4; ++nt)
#pragma unroll
            for (int c = 0; c < 4; ++c) acc[mt][nt][c] = 0.f;

    const int am = tid >> 2, aq = tid & 3;
    const int bn = tid >> 1, bh = tid & 1;
    auto issue = [&](int kt, int buf) {
        const uint32_t sA = smem_u + (uint32_t)buf * STAGE_BYTES;
        const uint32_t sB = sA + A_BYTES;
        cp_async16z(sA + (uint32_t)(am * (LDH * 2) + aq * 16),
                    qkT + (size_t)(q0 + am) * CK + kt * 32 + aq * 8, 16);
        const __half* bbase = mkT + (size_t)(m0 + bn) * CK + kt * 32 + bh * 16;
        const uint32_t rb = (uint32_t)(bn * (LDH * 2) + bh * 32);
#pragma unroll
        for (int j = 0; j < 2; ++j)
            cp_async16z(sB + rb + j * 16, bbase + j * 8, 16);
    };

    issue(0, 0); cp_commit();
    issue(1, 1); cp_commit();

    int buf = 0;
    for (int kt = 0; kt < KITERS_SC; ++kt) {
        cp_wait1();
        __syncthreads();
        if (kt + 2 < KITERS_SC) issue(kt + 2, (buf + 2) % 3);
        cp_commit();

        const __half* As = reinterpret_cast<const __half*>(sm + buf * STAGE_BYTES);
        const __half* Bs = reinterpret_cast<const __half*>(sm + buf * STAGE_BYTES + A_BYTES);
#pragma unroll
        for (int s = 0; s < 2; ++s) {
            const int k16 = s * 16;
            uint32_t a[4][4], bf[4][2];
#pragma unroll
            for (int mt = 0; mt < 4; ++mt) {
                int row = wm + mt * 16 + grp;
                a[mt][0] = *reinterpret_cast<const uint32_t*>(&As[row * LDH + k16 + 2 * tig]);
                a[mt][1] = *reinterpret_cast<const uint32_t*>(&As[(row + 8) * LDH + k16 + 2 * tig]);
                a[mt][2] = *reinterpret_cast<const uint32_t*>(&As[row * LDH + k16 + 2 * tig + 8]);
                a[mt][3] = *reinterpret_cast<const uint32_t*>(&As[(row + 8) * LDH + k16 + 2 * tig + 8]);
            }
#pragma unroll
            for (int nt = 0; nt < 4; ++nt) {
                int col = wn + nt * 8 + grp;
                bf[nt][0] = *reinterpret_cast<const uint32_t*>(&Bs[col * LDH + k16 + 2 * tig]);
                bf[nt][1] = *reinterpret_cast<const uint32_t*>(&Bs[col * LDH + k16 + 2 * tig + 8]);
            }
#pragma unroll
            for (int mt = 0; mt < 4; ++mt)
#pragma unroll
                for (int nt = 0; nt < 4; ++nt)
                    MMA_F16(acc[mt][nt], a[mt], bf[nt]);
        }
        buf = (buf + 1) % 3;
    }

    const float scale = 0.0625f;   // 1/sqrt(256)
#pragma unroll
    for (int mt = 0; mt < 4; ++mt) {
        int r0 = q0 + wm + mt * 16 + grp;
        int r1 = r0 + 8;
        float* s0 = g_S + (size_t)b * (HW * HW) + (size_t)r0 * HW + m0;
        float* s1 = g_S + (size_t)b * (HW * HW) + (size_t)r1 * HW + m0;
#pragma unroll
        for (int nt = 0; nt < 4; ++nt) {
            int col = wn + nt * 8 + 2 * tig;
            *reinterpret_cast<float2*>(&s0[col]) =
                make_float2(acc[mt][nt][0] * scale, acc[mt][nt][1] * scale);
            *reinterpret_cast<float2*>(&s1[col]) =
                make_float2(acc[mt][nt][2] * scale, acc[mt][nt][3] * scale);
        }
    }
}

// ---------------------------------------------------------------------------
// Row softmax over m: E = exp(S - rowmax) f16, rsum = 1/rowsum.
// ---------------------------------------------------------------------------
__global__ __launch_bounds__(256)
void softmax_row()
{
    const int warp = threadIdx.x >> 5, lane = threadIdx.x & 31;
    const int gid = blockIdx.x * 8 + warp;
    const float4* s4 = reinterpret_cast<const float4*>(g_S + (size_t)gid * HW);

    float4 v[8];
    float mx = -3.402823e38f;
#pragma unroll
    for (int j = 0; j < 8; ++j) {
        v[j] = s4[j * 32 + lane];
        mx = fmaxf(mx, fmaxf(fmaxf(v[j].x, v[j].y), fmaxf(v[j].z, v[j].w)));
    }
#pragma unroll
    for (int o = 16; o > 0; o >>= 1)
        mx = fmaxf(mx, __shfl_xor_sync(0xFFFFFFFFu, mx, o));

    uint2* e2 = reinterpret_cast<uint2*>(g_E + (size_t)gid * HW);
    float sum = 0.f;
#pragma unroll
    for (int j = 0; j < 8; ++j) {
        float e0 = __expf(v[j].x - mx);
        float e1 = __expf(v[j].y - mx);
        float e2f = __expf(v[j].z - mx);
        float e3 = __expf(v[j].w - mx);
        sum += (e0 + e1) + (e2f + e3);
        __half2 h01 = __floats2half2_rn(e0, e1);
        __half2 h23 = __floats2half2_rn(e2f, e3);
        uint2 u;
        u.x = *reinterpret_cast<uint32_t*>(&h01);
        u.y = *reinterpret_cast<uint32_t*>(&h23);
        e2[j * 32 + lane] = u;
    }
#pragma unroll
    for (int o = 16; o > 0; o >>= 1)
        sum += __shfl_xor_sync(0xFFFFFFFFu, sum, o);
    if (lane == 0) g_rsum[gid] = 1.0f / sum;
}

// ---------------------------------------------------------------------------
// Readout (f16 mma, 512 thr): out[b][c][q] = (sum_m mvh[c][m]*E[q][m])*rsum
// ---------------------------------------------------------------------------
__global__ __launch_bounds__(512, 1)
void out_tc(float* __restrict__ out)
{
    extern __shared__ char sm[];
    const int tid  = threadIdx.x;
    const int warp = tid >> 5, lane = tid & 31;
    const int grp  = lane >> 2, tig = lane & 3;
    const int wm   = (warp >> 3) * 64;
    const int wn   = (warp & 7) * 32;

    const int b  = blockIdx.x >> 2;
    const int q0 = (blockIdx.x & 3) * BN;
    const int c0 = blockIdx.y * BM;
    const __half* mvh = g_mvh + (size_t)b * (CV * HW);
    const __half* E   = g_E   + (size_t)b * (HW * HW);

    const uint32_t smem_u = (uint32_t)__cvta_generic_to_shared(sm);

    float acc[4][4][4];
#pragma unroll
    for (int mt = 0; mt < 4; ++mt)
#pragma unroll
        for (int nt = 0; nt < 4; ++nt)
#pragma unroll
            for (int c = 0; c < 4; ++c) acc[mt][nt][c] = 0.f;

    const int am = tid >> 2, aq = tid & 3;
    const int bn = tid >> 1, bh = tid & 1;
    auto issue = [&](int kt, int buf) {
        const uint32_t sA = smem_u + (uint32_t)buf * STAGE_BYTES;
        const uint32_t sB = sA + A_BYTES;
        cp_async16z(sA + (uint32_t)(am * (LDH * 2) + aq * 16),
                    mvh + (size_t)(c0 + am) * HW + kt * 32 + aq * 8, 16);
        const __half* bbase = E + (size_t)(q0 + bn) * HW + kt * 32 + bh * 16;
        const uint32_t rb = (uint32_t)(bn * (LDH * 2) + bh * 32);
#pragma unroll
        for (int j = 0; j < 2; ++j)
            cp_async16z(sB + rb + j * 16, bbase + j * 8, 16);
    };

    issue(0, 0); cp_commit();
    issue(1, 1); cp_commit();

    int buf = 0;
    for (int kt = 0; kt < KITERS_OUT; ++kt) {
        cp_wait1();
        __syncthreads();
        if (kt + 2 < KITERS_OUT) issue(kt + 2, (buf + 2) % 3);
        cp_commit();

        const __half* As = reinterpret_cast<const __half*>(sm + buf * STAGE_BYTES);
        const __half* Bs = reinterpret_cast<const __half*>(sm + buf * STAGE_BYTES + A_BYTES);
#pragma unroll
        for (int s = 0; s < 2; ++s) {
            const int k16 = s * 16;
            uint32_t a[4][4], bf[4][2];
#pragma unroll
            for (int mt = 0; mt < 4; ++mt) {
                int row = wm + mt * 16 + grp;
                a[mt][0] = *reinterpret_cast<const uint32_t*>(&As[row * LDH + k16 + 2 * tig]);
                a[mt][1] = *reinterpret_cast<const uint32_t*>(&As[(row + 8) * LDH + k16 + 2 * tig]);
                a[mt][2] = *reinterpret_cast<const uint32_t*>(&As[row * LDH + k16 + 2 * tig + 8]);
                a[mt][3] = *reinterpret_cast<const uint32_t*>(&As[(row + 8) * LDH + k16 + 2 * tig + 8]);
            }
#pragma unroll
            for (int nt = 0; nt < 4; ++nt) {
                int col = wn + nt * 8 + grp;
                bf[nt][0] = *reinterpret_cast<const uint32_t*>(&Bs[col * LDH + k16 + 2 * tig]);
                bf[nt][1] = *reinterpret_cast<const uint32_t*>(&Bs[col * LDH + k16 + 2 * tig + 8]);
            }
#pragma unroll
            for (int mt = 0; mt < 4; ++mt)
#pragma unroll
                for (int nt = 0; nt < 4; ++nt)
                    MMA_F16(acc[mt][nt], a[mt], bf[nt]);
        }
        buf = (buf + 1) % 3;
    }

    const float* rs = g_rsum + (size_t)b * HW;
#pragma unroll
    for (int mt = 0; mt < 4; ++mt) {
        int r0 = c0 + wm + mt * 16 + grp;
        int r1 = r0 + 8;
        float* d0 = out + (size_t)b * (2 * CV * HW) + (size_t)r0 * HW;
        float* d1 = out + (size_t)b * (2 * CV * HW) + (size_t)r1 * HW;
#pragma unroll
        for (int nt = 0; nt < 4; ++nt) {
            int col = q0 + wn + nt * 8 + 2 * tig;
            float2 r2 = *reinterpret_cast<const float2*>(&rs[col]);
            *reinterpret_cast<float2*>(&d0[col]) =
                make_float2(acc[mt][nt][0] * r2.x, acc[mt][nt][1] * r2.y);
            *reinterpret_cast<float2*>(&d1[col]) =
                make_float2(acc[mt][nt][2] * r2.x, acc[mt][nt][3] * r2.y);
        }
    }
}

// ---------------------------------------------------------------------------
// Launch
// ---------------------------------------------------------------------------
extern "C" void kernel_launch(void* const* d_in, const int* in_sizes, int n_in,
                              void* d_out, int out_size)
{
    const float* src_t = (const float*)d_in[0];
    const float* src_s = (const float*)d_in[1];
    const float* wk_m  = (const float*)d_in[2];
    const float* bk_m  = (const float*)d_in[3];
    const float* wv_m  = (const float*)d_in[4];
    const float* bv_m  = (const float*)d_in[5];
    const float* wk_q  = (const float*)d_in[6];
    const float* bk_q  = (const float*)d_in[7];
    const float* wv_q  = (const float*)d_in[8];
    const float* bv_q  = (const float*)d_in[9];
    float* out = (float*)d_out;

    cudaFuncSetAttribute(wg_gemm,   cudaFuncAttributeMaxDynamicSharedMemorySize, SMEM_GEMM);
    cudaFuncSetAttribute(scores_tc, cudaFuncAttributeMaxDynamicSharedMemorySize, SMEM_TOTAL);
    cudaFuncSetAttribute(out_tc,    cudaFuncAttributeMaxDynamicSharedMemorySize, SMEM_TOTAL);

    // 0. transpose + f16 sources (both branches)
    {
        dim3 grid(32, 32, 32);
        dim3 blk(32, 8);
        transpose_src<<<grid, blk>>>(src_t, src_s);
    }
    // 1. winograd weight transforms (both branches, blocked layout)
    {
        int n = 2 * MTOT * CIN;
        wg_w<<<(n + 255) / 256, 256>>>(wk_m, wv_m, wk_q, wv_q);
    }
    // 2. winograd conv: input transform, GEMM (bulk-copy pipeline), output
    {
        dim3 dgrid(256, 32);
        wg_d<<<dgrid, 256>>>();

        dim3 ggrid(16, 12, 16);
        wg_gemm<<<ggrid, 512, SMEM_GEMM>>>();

        dim3 ogrid(32, MTOT);
        wg_out<<<ogrid, 256>>>(bk_m, bv_m, bk_q, bv_q, out);
    }
    // 3. key transposes -> [b][pix][c] (both branches)
    {
        dim3 grid(32, 8, 32);
        dim3 blk(32, 8);
        transpose_kh<<<grid, blk>>>();
    }
    // 4. attention scores, S[b][q][m]
    {
        dim3 grid(64, 8);
        scores_tc<<<grid, 512, SMEM_TOTAL>>>();
    }
    // 5. row softmax -> E f16 + rsum
    {
        softmax_row<<<BB * HW / 8, 256>>>();
    }
    // 6. readout -> out channels [0, 512)
    {
        dim3 grid(64, 4);
        out_tc<<<grid, 512, SMEM_TOTAL>>>(out);
    }
}

// round 15
// speedup vs baseline: 10.5004x; 1.0386x over previous
#include <cuda_runtime.h>
#include <cuda_fp16.h>
#include <cstdint>

// ---------------------------------------------------------------------------
// Problem constants
// ---------------------------------------------------------------------------
#define BB     16
#define CIN    1024
#define HW     1024      // 32*32
#define CK     256
#define CV     512
#define MTOT   768       // stacked key(256) + value(512) output channels
#define NTILE  4096      // BB * 256 winograd tiles

// shared f16 mma tiling: CTA 128x256, 512 threads (16 warps of 64x32)
#define BM     128
#define BN     256
#define LDH    40        // pitch in halfs (80 B) -> conflict-free frags/LDSM
#define A_BYTES (BM * LDH * 2)          // 10240
#define B_BYTES (BN * LDH * 2)          // 20480
#define STAGE_BYTES (A_BYTES + B_BYTES) // 30720
#define NSTAGE 3
#define SMEM_GEMM (128 + NSTAGE * STAGE_BYTES)   // mbars + stages = 92288
#define SMEM_TOTAL (NSTAGE * STAGE_BYTES)        // cp.async kernels (92160)

#define KITERS_WG   32    // 1024 / 32
#define KITERS_SC   8     // 256 / 32
#define KITERS_OUT  32    // 1024 / 32

// blocked U/V strides (pitch-40 rows, smem-image layout)
#define U_STRIDE  ((size_t)16 * 32 * MTOT  * LDH)   // per-branch U halfs
#define V_STRIDE  ((size_t)16 * 32 * NTILE * LDH)   // per-branch V halfs
#define M_STRIDE  ((size_t)16 * MTOT * NTILE)       // per-branch M halfs

// ---------------------------------------------------------------------------
// Scratch (device globals; no allocation allowed). All accessed ONLY from
// device code (host passes `which` flags, never symbol addresses).
// ---------------------------------------------------------------------------
__device__ __half g_srcT0[BB * HW * CIN];    // f16 src_temp  [b][pix][ci]
__device__ __half g_srcT1[BB * HW * CIN];    // f16 src_search
__device__ __half g_U [2 * 16 * 32 * MTOT  * LDH]; // [br][t][kt][co][40]
__device__ __half g_V [2 * 16 * 32 * NTILE * LDH]; // [br][t][kt][bt][40]
__device__ __half g_Mh[2 * 16 * MTOT * NTILE];     // [br][t][co][bt] f16
__device__ __half g_mkh[BB * CK * HW];       // m_key   [b][c][pix] f16
__device__ __half g_qkh[BB * CK * HW];       // q_key   [b][c][pix] f16
__device__ __half g_mkT[BB * HW * CK];       // m_key   [b][m][c]   f16
__device__ __half g_qkT[BB * HW * CK];       // q_key   [b][q][c]   f16
__device__ __half g_mvh[BB * CV * HW];       // m_value [b][c][m]   f16
__device__ float  g_S  [BB * HW * HW];       // scores  [b][q][m]   f32
__device__ __half g_E  [BB * HW * HW];       // exp     [b][q][m]   f16
__device__ float  g_rsum[BB * HW];           // 1 / row sum

// ---------------------------------------------------------------------------
// async-copy / ldmatrix helpers
// ---------------------------------------------------------------------------
__device__ __forceinline__ void cp_async16z(uint32_t s, const void* g, int sz) {
    asm volatile("cp.async.cg.shared.global [%0], [%1], 16, %2;"
                 :: "r"(s), "l"(g), "r"(sz));
}
__device__ __forceinline__ void cp_commit() { asm volatile("cp.async.commit_group;"); }
__device__ __forceinline__ void cp_wait1()  { asm volatile("cp.async.wait_group 1;"); }

__device__ __forceinline__ void mbar_init(uint32_t a, uint32_t cnt) {
    asm volatile("mbarrier.init.shared.b64 [%0], %1;" :: "r"(a), "r"(cnt) : "memory");
}
__device__ __forceinline__ void mbar_expect_tx(uint32_t a, uint32_t bytes) {
    asm volatile("mbarrier.arrive.expect_tx.shared.b64 _, [%0], %1;"
                 :: "r"(a), "r"(bytes) : "memory");
}
__device__ __forceinline__ void bulk_g2s(uint32_t dst, const void* src,
                                         uint32_t bytes, uint32_t mbar) {
    asm volatile("cp.async.bulk.shared::cluster.global.mbarrier::complete_tx::bytes "
                 "[%0], [%1], %2, [%3];"
                 :: "r"(dst), "l"(src), "r"(bytes), "r"(mbar) : "memory");
}
__device__ __forceinline__ void mbar_wait(uint32_t a, uint32_t parity) {
    uint32_t done;
    asm volatile("{\n\t.reg .pred p;\n\t"
        "mbarrier.try_wait.parity.acquire.cta.shared::cta.b64 p, [%1], %2;\n\t"
        "selp.b32 %0, 1, 0, p;\n\t}" : "=r"(done) : "r"(a), "r"(parity) : "memory");
    if (!done) {
        asm volatile("{\n\t.reg .pred P1;\n\t"
            "WL_%=:\n\t"
            "mbarrier.try_wait.parity.acquire.cta.shared::cta.b64 P1, [%0], %1, 0x989680;\n\t"
            "@P1 bra.uni WD_%=;\n\t"
            "bra.uni WL_%=;\n\t"
            "WD_%=:\n\t}" :: "r"(a), "r"(parity) : "memory");
    }
}
__device__ __forceinline__ void ldsm_x4(uint32_t& r0, uint32_t& r1,
                                        uint32_t& r2, uint32_t& r3, uint32_t addr) {
    asm volatile("ldmatrix.sync.aligned.m8n8.x4.shared.b16 {%0,%1,%2,%3}, [%4];"
                 : "=r"(r0), "=r"(r1), "=r"(r2), "=r"(r3) : "r"(addr));
}

#define MMA_F16(acc, a, bf)                                                   \
    asm volatile(                                                             \
        "mma.sync.aligned.m16n8k16.row.col.f32.f16.f16.f32 "                  \
        "{%0,%1,%2,%3}, {%4,%5,%6,%7}, {%8,%9}, {%0,%1,%2,%3};"               \
        : "+f"((acc)[0]), "+f"((acc)[1]), "+f"((acc)[2]), "+f"((acc)[3])      \
        : "r"((a)[0]), "r"((a)[1]), "r"((a)[2]), "r"((a)[3]),                 \
          "r"((bf)[0]), "r"((bf)[1]))

// ldmatrix-based fragment load + mma for one 64x32 warp tile, one 32-K tile.
// sAu/sBu: smem uint32 addresses of A/B stage. Lane constants:
//   sub = lane&7, seg = lane>>3
//   A: row_in = (seg&1)*8+sub, k_off = (seg>>1)*8
//   B: nt_sel = seg>>1, k_off = (seg&1)*8
#define MMA_TILE_LDSM(acc, sAu, sBu, wm, wn, sub, seg)                        \
    do {                                                                      \
        const int _arow = ((seg) & 1) * 8 + (sub);                            \
        const int _akof = ((seg) >> 1) * 8;                                   \
        const int _bnt  = (seg) >> 1;                                         \
        const int _bkof = ((seg) & 1) * 8;                                    \
        _Pragma("unroll")                                                     \
        for (int s = 0; s < 2; ++s) {                                         \
            const int k16 = s * 16;                                           \
            uint32_t a[4][4], bf[4][2];                                       \
            _Pragma("unroll")                                                 \
            for (int mt = 0; mt < 4; ++mt)                                    \
                ldsm_x4(a[mt][0], a[mt][1], a[mt][2], a[mt][3],               \
                    (sAu) + (uint32_t)((((wm) + mt * 16 + _arow) * LDH        \
                                        + k16 + _akof) * 2));                 \
            _Pragma("unroll")                                                 \
            for (int p = 0; p < 2; ++p)                                       \
                ldsm_x4(bf[p*2][0], bf[p*2][1], bf[p*2+1][0], bf[p*2+1][1],   \
                    (sBu) + (uint32_t)((((wn) + (p * 2 + _bnt) * 8 + (sub))   \
                                        * LDH + k16 + _bkof) * 2));           \
            _Pragma("unroll")                                                 \
            for (int mt = 0; mt < 4; ++mt)                                    \
                _Pragma("unroll")                                             \
                for (int nt = 0; nt < 4; ++nt)                                \
                    MMA_F16(acc[mt][nt], a[mt], bf[nt]);                      \
        }                                                                     \
    } while (0)

// ---------------------------------------------------------------------------
// Pre-pass: transpose + f16 src, BOTH branches: [b][ci][pix] -> [b][pix][ci]
// ---------------------------------------------------------------------------
__global__ void transpose_src(const float* __restrict__ s0,
                              const float* __restrict__ s1)
{
    __shared__ float t[32][33];
    int b = blockIdx.z & 15;
    int which = blockIdx.z >> 4;
    const float* src = which ? s1 : s0;
    int pix0 = blockIdx.x * 32, ci0 = blockIdx.y * 32;
    const float* s = src + ((size_t)b * CIN + ci0) * HW + pix0;
    for (int i = threadIdx.y; i < 32; i += 8)
        t[i][threadIdx.x] = s[(size_t)i * HW + threadIdx.x];   // t[ci][pix]
    __syncthreads();
    __half* d = (which ? g_srcT1 : g_srcT0) + ((size_t)b * HW + pix0) * CIN + ci0;
    for (int i = threadIdx.y; i < 32; i += 8)
        d[(size_t)i * CIN + threadIdx.x] = __float2half_rn(t[threadIdx.x][i]);
}

// ---------------------------------------------------------------------------
// Winograd weight transform, BOTH branches: U = G g G^T per (br, co, ci).
// Output BLOCKED: U[br][t][kt][co][40], kt = ci>>5, kk = ci&31.
// ---------------------------------------------------------------------------
__global__ void wg_w(const float* __restrict__ wk_m, const float* __restrict__ wv_m,
                     const float* __restrict__ wk_q, const float* __restrict__ wv_q)
{
    int idx = blockIdx.x * blockDim.x + threadIdx.x;
    if (idx >= 2 * MTOT * CIN) return;
    int which = (idx >= MTOT * CIN);
    int r2 = idx - which * (MTOT * CIN);
    int co = r2 / CIN;
    int ci = r2 - co * CIN;
    const float* wk = which ? wk_q : wk_m;
    const float* wv = which ? wv_q : wv_m;
    __half* __restrict__ U = g_U + (size_t)which * U_STRIDE;
    const int kt = ci >> 5, kk = ci & 31;

    const float* g = (co < CK) ? (wk + ((size_t)co * CIN + ci) * 9)
                               : (wv + ((size_t)(co - CK) * CIN + ci) * 9);
    float gr[3][3];
#pragma unroll
    for (int r = 0; r < 9; ++r) gr[r / 3][r % 3] = g[r];
    float t[4][3];
#pragma unroll
    for (int j = 0; j < 3; ++j) {
        t[0][j] = gr[0][j];
        t[1][j] = 0.5f * (gr[0][j] + gr[1][j] + gr[2][j]);
        t[2][j] = 0.5f * (gr[0][j] - gr[1][j] + gr[2][j]);
        t[3][j] = gr[2][j];
    }
#pragma unroll
    for (int i = 0; i < 4; ++i) {
        float u0 = t[i][0];
        float u1 = 0.5f * (t[i][0] + t[i][1] + t[i][2]);
        float u2 = 0.5f * (t[i][0] - t[i][1] + t[i][2]);
        float u3 = t[i][2];
        const float uv[4] = {u0, u1, u2, u3};
#pragma unroll
        for (int j = 0; j < 4; ++j)
            U[(((size_t)(i * 4 + j) * 32 + kt) * MTOT + co) * LDH + kk] =
                __float2half_rn(uv[j]);
    }
}

// ---------------------------------------------------------------------------
// Winograd input transform, BOTH branches: V = B^T d B per (br, b, tile, ci).
// Output BLOCKED: V[br][t][kt][bt][40]. grid (256 tiles, 32). Zero-pad halo.
// ---------------------------------------------------------------------------
__global__ __launch_bounds__(256)
void wg_d()
{
    const int b     = blockIdx.y & 15;
    const int which = blockIdx.y >> 4;
    const __half* __restrict__ srcT = which ? g_srcT1 : g_srcT0;
    __half* __restrict__ V = g_V + (size_t)which * V_STRIDE;
    const int tile = blockIdx.x;
    const int ty = tile >> 4, tx = tile & 15;
    const int oy = 2 * ty, ox = 2 * tx;
    const int bt = b * 256 + tile;
    const __half* sb = srcT + (size_t)b * (HW * CIN);

#pragma unroll
    for (int pass = 0; pass < 2; ++pass) {
        int ci = (threadIdx.x + pass * 256) * 2;
        const int kt = ci >> 5, kk = ci & 31;
        float2 d[4][4];
#pragma unroll
        for (int i = 0; i < 4; ++i) {
            int iy = oy - 1 + i;
#pragma unroll
            for (int j = 0; j < 4; ++j) {
                int ix = ox - 1 + j;
                if ((unsigned)iy < 32u && (unsigned)ix < 32u) {
                    __half2 h = *reinterpret_cast<const __half2*>(
                        &sb[(size_t)(iy * 32 + ix) * CIN + ci]);
                    d[i][j] = __half22float2(h);
                } else {
                    d[i][j] = make_float2(0.f, 0.f);
                }
            }
        }
        float2 r[4][4];
#pragma unroll
        for (int j = 0; j < 4; ++j) {
            r[0][j] = make_float2(d[0][j].x - d[2][j].x, d[0][j].y - d[2][j].y);
            r[1][j] = make_float2(d[1][j].x + d[2][j].x, d[1][j].y + d[2][j].y);
            r[2][j] = make_float2(d[2][j].x - d[1][j].x, d[2][j].y - d[1][j].y);
            r[3][j] = make_float2(d[1][j].x - d[3][j].x, d[1][j].y - d[3][j].y);
        }
#pragma unroll
        for (int i = 0; i < 4; ++i) {
            float2 v[4];
            v[0] = make_float2(r[i][0].x - r[i][2].x, r[i][0].y - r[i][2].y);
            v[1] = make_float2(r[i][1].x + r[i][2].x, r[i][1].y + r[i][2].y);
            v[2] = make_float2(r[i][2].x - r[i][1].x, r[i][2].y - r[i][1].y);
            v[3] = make_float2(r[i][1].x - r[i][3].x, r[i][1].y - r[i][3].y);
#pragma unroll
            for (int j = 0; j < 4; ++j) {
                *reinterpret_cast<__half2*>(
                    &V[(((size_t)(i * 4 + j) * 32 + kt) * NTILE + bt) * LDH + kk]) =
                    __floats2half2_rn(v[j].x, v[j].y);
            }
        }
    }
}

// ---------------------------------------------------------------------------
// Winograd GEMM, BOTH branches: M[t][co][n] = sum_ci U*V, f16 mma.
// Bulk-copy + mbarrier 3-stage pipeline; ldmatrix fragment loads.
// grid (16 n-tiles, 12, 16 t). 512 thr, warp tile 64x32.
// ---------------------------------------------------------------------------
__global__ __launch_bounds__(512, 1)
void wg_gemm()
{
    extern __shared__ char sm[];
    const int which = blockIdx.y / 6;
    const int tid  = threadIdx.x;
    const int warp = tid >> 5, lane = tid & 31;
    const int grp  = lane >> 2, tig = lane & 3;
    const int sub  = lane & 7, seg = lane >> 3;
    const int wm   = (warp >> 3) * 64;      // 0 / 64
    const int wn   = (warp & 7) * 32;       // 0..224

    const int n0  = blockIdx.x * BN;
    const int co0 = (blockIdx.y % 6) * BM;
    const int t   = blockIdx.z;
    const __half* Ub = g_U + (size_t)which * U_STRIDE + (size_t)t * 32 * MTOT * LDH;
    const __half* Vb = g_V + (size_t)which * V_STRIDE + (size_t)t * 32 * NTILE * LDH;
    __half* __restrict__ Mh = g_Mh + (size_t)which * M_STRIDE;

    const uint32_t smem_u = (uint32_t)__cvta_generic_to_shared(sm);
    const uint32_t mb0    = smem_u;            // 3 mbarriers at +0,+8,+16
    const uint32_t stg0   = smem_u + 128;

    if (tid == 0) {
        mbar_init(mb0 + 0, 1);
        mbar_init(mb0 + 8, 1);
        mbar_init(mb0 + 16, 1);
    }
    __syncthreads();

    auto issue = [&](int kt, int buf) {
        const uint32_t mbar = mb0 + buf * 8;
        const uint32_t sA = stg0 + (uint32_t)buf * STAGE_BYTES;
        mbar_expect_tx(mbar, STAGE_BYTES);
        bulk_g2s(sA, Ub + ((size_t)kt * MTOT + co0) * LDH, A_BYTES, mbar);
        bulk_g2s(sA + A_BYTES, Vb + ((size_t)kt * NTILE + n0) * LDH, B_BYTES, mbar);
    };
    if (tid == 0) { issue(0, 0); issue(1, 1); issue(2, 2); }

    float acc[4][4][4];
#pragma unroll
    for (int mt = 0; mt < 4; ++mt)
#pragma unroll
        for (int nt = 0; nt < 4; ++nt)
#pragma unroll
            for (int c = 0; c < 4; ++c) acc[mt][nt][c] = 0.f;

    for (int kt = 0; kt < KITERS_WG; ++kt) {
        const int buf = kt % 3;
        mbar_wait(mb0 + buf * 8, (kt / 3) & 1);

        const uint32_t sAu = stg0 + (uint32_t)buf * STAGE_BYTES;
        const uint32_t sBu = sAu + A_BYTES;
        MMA_TILE_LDSM(acc, sAu, sBu, wm, wn, sub, seg);

        __syncthreads();                       // all warps done with buf
        if (kt + 3 < KITERS_WG && tid == 0) issue(kt + 3, buf);
    }

#pragma unroll
    for (int mt = 0; mt < 4; ++mt) {
        int r0 = co0 + wm + mt * 16 + grp;
        int r1 = r0 + 8;
        __half* d0 = Mh + ((size_t)t * MTOT + r0) * NTILE + n0;
        __half* d1 = Mh + ((size_t)t * MTOT + r1) * NTILE + n0;
#pragma unroll
        for (int nt = 0; nt < 4; ++nt) {
            int col = wn + nt * 8 + 2 * tig;
            *reinterpret_cast<__half2*>(&d0[col]) =
                __floats2half2_rn(acc[mt][nt][0], acc[mt][nt][1]);
            *reinterpret_cast<__half2*>(&d1[col]) =
                __floats2half2_rn(acc[mt][nt][2], acc[mt][nt][3]);
        }
    }
}

// ---------------------------------------------------------------------------
// Winograd output transform, BOTH branches: Y = A^T m A (+bias), scatter.
// ---------------------------------------------------------------------------
__global__ __launch_bounds__(256)
void wg_out(const float* __restrict__ bk_m, const float* __restrict__ bv_m,
            const float* __restrict__ bk_q, const float* __restrict__ bv_q,
            float* __restrict__ out)
{
    const int which = blockIdx.x >> 4;
    const int bt = (blockIdx.x & 15) * 256 + threadIdx.x;
    const int co = blockIdx.y;
    const int b    = bt >> 8;
    const int tile = bt & 255;
    const int ty = tile >> 4, tx = tile & 15;
    const int pix = (2 * ty) * 32 + 2 * tx;
    const __half* Mh = g_Mh + (size_t)which * M_STRIDE;
    const float* bias_k = which ? bk_q : bk_m;
    const float* bias_v = which ? bv_q : bv_m;

    float m[4][4];
#pragma unroll
    for (int i = 0; i < 4; ++i)
#pragma unroll
        for (int j = 0; j < 4; ++j)
            m[i][j] = __half2float(Mh[((size_t)(i * 4 + j) * MTOT + co) * NTILE + bt]);

    float s0[4], s1[4];
#pragma unroll
    for (int j = 0; j < 4; ++j) {
        s0[j] = m[0][j] + m[1][j] + m[2][j];
        s1[j] = m[1][j] - m[2][j] - m[3][j];
    }
    float y00 = s0[0] + s0[1] + s0[2];
    float y01 = s0[1] - s0[2] - s0[3];
    float y10 = s1[0] + s1[1] + s1[2];
    float y11 = s1[1] - s1[2] - s1[3];

    if (co < CK) {
        float bia = bias_k[co];
        __half* d = (which ? g_qkh : g_mkh) + ((size_t)b * CK + co) * HW;
        *reinterpret_cast<__half2*>(&d[pix])      = __floats2half2_rn(y00 + bia, y01 + bia);
        *reinterpret_cast<__half2*>(&d[pix + 32]) = __floats2half2_rn(y10 + bia, y11 + bia);
    } else {
        int cv = co - CK;
        float bia = bias_v[cv];
        if (which) {
            float* d = out + (size_t)b * (2 * CV * HW) + (size_t)(CV + cv) * HW;
            *reinterpret_cast<float2*>(&d[pix])      = make_float2(y00 + bia, y01 + bia);
            *reinterpret_cast<float2*>(&d[pix + 32]) = make_float2(y10 + bia, y11 + bia);
        } else {
            __half* d = g_mvh + ((size_t)b * CV + cv) * HW;
            *reinterpret_cast<__half2*>(&d[pix])      = __floats2half2_rn(y00 + bia, y01 + bia);
            *reinterpret_cast<__half2*>(&d[pix + 32]) = __floats2half2_rn(y10 + bia, y11 + bia);
        }
    }
}

// ---------------------------------------------------------------------------
// Key transpose f16, BOTH branches: [b][c][pix] -> [b][pix][c]
// ---------------------------------------------------------------------------
__global__ void transpose_kh()
{
    __shared__ __half t[32][34];
    int b = blockIdx.z & 15;
    int which = blockIdx.z >> 4;
    const __half* in = which ? g_qkh : g_mkh;
    __half* outp     = which ? g_qkT : g_mkT;
    int pix0 = blockIdx.x * 32, c0 = blockIdx.y * 32;
    const __half* s = in + ((size_t)b * CK + c0) * HW + pix0;
    for (int i = threadIdx.y; i < 32; i += 8)
        t[i][threadIdx.x] = s[(size_t)i * HW + threadIdx.x];   // t[c][pix]
    __syncthreads();
    __half* d = outp + ((size_t)b * HW + pix0) * CK + c0;
    for (int i = threadIdx.y; i < 32; i += 8)
        d[(size_t)i * CK + threadIdx.x] = t[threadIdx.x][i];
}

// ---------------------------------------------------------------------------
// Scores (f16 mma, 512 thr, ldmatrix): S[b][q][m] = (1/16)*sum qkT*mkT
// ---------------------------------------------------------------------------
__global__ __launch_bounds__(512, 1)
void scores_tc()
{
    extern __shared__ char sm[];
    const int tid  = threadIdx.x;
    const int warp = tid >> 5, lane = tid & 31;
    const int grp  = lane >> 2, tig = lane & 3;
    const int sub  = lane & 7, seg = lane >> 3;
    const int wm   = (warp >> 3) * 64;
    const int wn   = (warp & 7) * 32;

    const int b  = blockIdx.x >> 2;
    const int m0 = (blockIdx.x & 3) * BN;
    const int q0 = blockIdx.y * BM;
    const __half* qkT = g_qkT + (size_t)b * (HW * CK);
    const __half* mkT = g_mkT + (size_t)b * (HW * CK);

    const uint32_t smem_u = (uint32_t)__cvta_generic_to_shared(sm);

    float acc[4][4][4];
#pragma unroll
    for (int mt = 0; mt < 4; ++mt)
#pragma unroll
        for (int nt = 0; nt < 4; ++nt)
#pragma unroll
            for (int c = 0; c < 4; ++c) acc[mt][nt][c] = 0.f;

    const int am = tid >> 2, aq = tid & 3;
    const int bn = tid >> 1, bh = tid & 1;
    auto issue = [&](int kt, int buf) {
        const uint32_t sA = smem_u + (uint32_t)buf * STAGE_BYTES;
        const uint32_t sB = sA + A_BYTES;
        cp_async16z(sA + (uint32_t)(am * (LDH * 2) + aq * 16),
                    qkT + (size_t)(q0 + am) * CK + kt * 32 + aq * 8, 16);
        const __half* bbase = mkT + (size_t)(m0 + bn) * CK + kt * 32 + bh * 16;
        const uint32_t rb = (uint32_t)(bn * (LDH * 2) + bh * 32);
#pragma unroll
        for (int j = 0; j < 2; ++j)
            cp_async16z(sB + rb + j * 16, bbase + j * 8, 16);
    };

    issue(0, 0); cp_commit();
    issue(1, 1); cp_commit();

    int buf = 0;
    for (int kt = 0; kt < KITERS_SC; ++kt) {
        cp_wait1();
        __syncthreads();
        if (kt + 2 < KITERS_SC) issue(kt + 2, (buf + 2) % 3);
        cp_commit();

        const uint32_t sAu = smem_u + (uint32_t)buf * STAGE_BYTES;
        const uint32_t sBu = sAu + A_BYTES;
        MMA_TILE_LDSM(acc, sAu, sBu, wm, wn, sub, seg);
        __syncthreads();
        buf = (buf + 1) % 3;
    }

    const float scale = 0.0625f;   // 1/sqrt(256)
#pragma unroll
    for (int mt = 0; mt < 4; ++mt) {
        int r0 = q0 + wm + mt * 16 + grp;
        int r1 = r0 + 8;
        float* s0 = g_S + (size_t)b * (HW * HW) + (size_t)r0 * HW + m0;
        float* s1 = g_S + (size_t)b * (HW * HW) + (size_t)r1 * HW + m0;
#pragma unroll
        for (int nt = 0; nt < 4; ++nt) {
            int col = wn + nt * 8 + 2 * tig;
            *reinterpret_cast<float2*>(&s0[col]) =
                make_float2(acc[mt][nt][0] * scale, acc[mt][nt][1] * scale);
            *reinterpret_cast<float2*>(&s1[col]) =
                make_float2(acc[mt][nt][2] * scale, acc[mt][nt][3] * scale);
        }
    }
}

// ---------------------------------------------------------------------------
// Row softmax over m: E = exp(S - rowmax) f16, rsum = 1/rowsum.
// ---------------------------------------------------------------------------
__global__ __launch_bounds__(256)
void softmax_row()
{
    const int warp = threadIdx.x >> 5, lane = threadIdx.x & 31;
    const int gid = blockIdx.x * 8 + warp;
    const float4* s4 = reinterpret_cast<const float4*>(g_S + (size_t)gid * HW);

    float4 v[8];
    float mx = -3.402823e38f;
#pragma unroll
    for (int j = 0; j < 8; ++j) {
        v[j] = s4[j * 32 + lane];
        mx = fmaxf(mx, fmaxf(fmaxf(v[j].x, v[j].y), fmaxf(v[j].z, v[j].w)));
    }
#pragma unroll
    for (int o = 16; o > 0; o >>= 1)
        mx = fmaxf(mx, __shfl_xor_sync(0xFFFFFFFFu, mx, o));

    uint2* e2 = reinterpret_cast<uint2*>(g_E + (size_t)gid * HW);
    float sum = 0.f;
#pragma unroll
    for (int j = 0; j < 8; ++j) {
        float e0 = __expf(v[j].x - mx);
        float e1 = __expf(v[j].y - mx);
        float e2f = __expf(v[j].z - mx);
        float e3 = __expf(v[j].w - mx);
        sum += (e0 + e1) + (e2f + e3);
        __half2 h01 = __floats2half2_rn(e0, e1);
        __half2 h23 = __floats2half2_rn(e2f, e3);
        uint2 u;
        u.x = *reinterpret_cast<uint32_t*>(&h01);
        u.y = *reinterpret_cast<uint32_t*>(&h23);
        e2[j * 32 + lane] = u;
    }
#pragma unroll
    for (int o = 16; o > 0; o >>= 1)
        sum += __shfl_xor_sync(0xFFFFFFFFu, sum, o);
    if (lane == 0) g_rsum[gid] = 1.0f / sum;
}

// ---------------------------------------------------------------------------
// Readout (f16 mma, 512 thr, ldmatrix): out = (sum_m mvh*E)*rsum
// ---------------------------------------------------------------------------
__global__ __launch_bounds__(512, 1)
void out_tc(float* __restrict__ out)
{
    extern __shared__ char sm[];
    const int tid  = threadIdx.x;
    const int warp = tid >> 5, lane = tid & 31;
    const int grp  = lane >> 2, tig = lane & 3;
    const int sub  = lane & 7, seg = lane >> 3;
    const int wm   = (warp >> 3) * 64;
    const int wn   = (warp & 7) * 32;

    const int b  = blockIdx.x >> 2;
    const int q0 = (blockIdx.x & 3) * BN;
    const int c0 = blockIdx.y * BM;
    const __half* mvh = g_mvh + (size_t)b * (CV * HW);
    const __half* E   = g_E   + (size_t)b * (HW * HW);

    const uint32_t smem_u = (uint32_t)__cvta_generic_to_shared(sm);

    float acc[4][4][4];
#pragma unroll
    for (int mt = 0; mt < 4; ++mt)
#pragma unroll
        for (int nt = 0; nt < 4; ++nt)
#pragma unroll
            for (int c = 0; c < 4; ++c) acc[mt][nt][c] = 0.f;

    const int am = tid >> 2, aq = tid & 3;
    const int bn = tid >> 1, bh = tid & 1;
    auto issue = [&](int kt, int buf) {
        const uint32_t sA = smem_u + (uint32_t)buf * STAGE_BYTES;
        const uint32_t sB = sA + A_BYTES;
        cp_async16z(sA + (uint32_t)(am * (LDH * 2) + aq * 16),
                    mvh + (size_t)(c0 + am) * HW + kt * 32 + aq * 8, 16);
        const __half* bbase = E + (size_t)(q0 + bn) * HW + kt * 32 + bh * 16;
        const uint32_t rb = (uint32_t)(bn * (LDH * 2) + bh * 32);
#pragma unroll
        for (int j = 0; j < 2; ++j)
            cp_async16z(sB + rb + j * 16, bbase + j * 8, 16);
    };

    issue(0, 0); cp_commit();
    issue(1, 1); cp_commit();

    int buf = 0;
    for (int kt = 0; kt < KITERS_OUT; ++kt) {
        cp_wait1();
        __syncthreads();
        if (kt + 2 < KITERS_OUT) issue(kt + 2, (buf + 2) % 3);
        cp_commit();

        const uint32_t sAu = smem_u + (uint32_t)buf * STAGE_BYTES;
        const uint32_t sBu = sAu + A_BYTES;
        MMA_TILE_LDSM(acc, sAu, sBu, wm, wn, sub, seg);
        __syncthreads();
        buf = (buf + 1) % 3;
    }

    const float* rs = g_rsum + (size_t)b * HW;
#pragma unroll
    for (int mt = 0; mt < 4; ++mt) {
        int r0 = c0 + wm + mt * 16 + grp;
        int r1 = r0 + 8;
        float* d0 = out + (size_t)b * (2 * CV * HW) + (size_t)r0 * HW;
        float* d1 = out + (size_t)b * (2 * CV * HW) + (size_t)r1 * HW;
#pragma unroll
        for (int nt = 0; nt < 4; ++nt) {
            int col = q0 + wn + nt * 8 + 2 * tig;
            float2 r2 = *reinterpret_cast<const float2*>(&rs[col]);
            *reinterpret_cast<float2*>(&d0[col]) =
                make_float2(acc[mt][nt][0] * r2.x, acc[mt][nt][1] * r2.y);
            *reinterpret_cast<float2*>(&d1[col]) =
                make_float2(acc[mt][nt][2] * r2.x, acc[mt][nt][3] * r2.y);
        }
    }
}

// ---------------------------------------------------------------------------
// Launch
// ---------------------------------------------------------------------------
extern "C" void kernel_launch(void* const* d_in, const int* in_sizes, int n_in,
                              void* d_out, int out_size)
{
    const float* src_t = (const float*)d_in[0];
    const float* src_s = (const float*)d_in[1];
    const float* wk_m  = (const float*)d_in[2];
    const float* bk_m  = (const float*)d_in[3];
    const float* wv_m  = (const float*)d_in[4];
    const float* bv_m  = (const float*)d_in[5];
    const float* wk_q  = (const float*)d_in[6];
    const float* bk_q  = (const float*)d_in[7];
    const float* wv_q  = (const float*)d_in[8];
    const float* bv_q  = (const float*)d_in[9];
    float* out = (float*)d_out;

    cudaFuncSetAttribute(wg_gemm,   cudaFuncAttributeMaxDynamicSharedMemorySize, SMEM_GEMM);
    cudaFuncSetAttribute(scores_tc, cudaFuncAttributeMaxDynamicSharedMemorySize, SMEM_TOTAL);
    cudaFuncSetAttribute(out_tc,    cudaFuncAttributeMaxDynamicSharedMemorySize, SMEM_TOTAL);

    // 0. transpose + f16 sources (both branches)
    {
        dim3 grid(32, 32, 32);
        dim3 blk(32, 8);
        transpose_src<<<grid, blk>>>(src_t, src_s);
    }
    // 1. winograd weight transforms (both branches, blocked layout)
    {
        int n = 2 * MTOT * CIN;
        wg_w<<<(n + 255) / 256, 256>>>(wk_m, wv_m, wk_q, wv_q);
    }
    // 2. winograd conv: input transform, GEMM (bulk + ldmatrix), output
    {
        dim3 dgrid(256, 32);
        wg_d<<<dgrid, 256>>>();

        dim3 ggrid(16, 12, 16);
        wg_gemm<<<ggrid, 512, SMEM_GEMM>>>();

        dim3 ogrid(32, MTOT);
        wg_out<<<ogrid, 256>>>(bk_m, bv_m, bk_q, bv_q, out);
    }
    // 3. key transposes -> [b][pix][c] (both branches)
    {
        dim3 grid(32, 8, 32);
        dim3 blk(32, 8);
        transpose_kh<<<grid, blk>>>();
    }
    // 4. attention scores, S[b][q][m]
    {
        dim3 grid(64, 8);
        scores_tc<<<grid, 512, SMEM_TOTAL>>>();
    }
    // 5. row softmax -> E f16 + rsum
    {
        softmax_row<<<BB * HW / 8, 256>>>();
    }
    // 6. readout -> out channels [0, 512)
    {
        dim3 grid(64, 4);
        out_tc<<<grid, 512, SMEM_TOTAL>>>(out);
    }
}